// round 2
// baseline (speedup 1.0000x reference)
#include <cuda_runtime.h>
#include <math.h>

#define NE    42
#define BATCH 4
#define EMBD  256
#define IN_D  768
#define NREL  97
#define NPIX  (NE*NE)          // 1764
#define NROWS (BATCH*NE)       // 168
#define NPAIR (BATCH*NPIX)     // 7056

// ---------------- scratch (static device memory; no allocation) ----------------
__device__ float g_e   [NROWS*EMBD];          // entity embeddings [168,256]
__device__ float g_norm[NROWS];
__device__ float g_W3  [NE*EMBD*EMBD];        // sim3 weight permuted: [c=j*256+m][n]
__device__ float g_T   [NROWS*NE*EMBD];       // sim3 intermediate [bi][j*256+m]
__device__ float g_fm  [BATCH*3*NE*NE];       // conv input [b][c][H][W]
__device__ float g_w1t [27*EMBD];             // conv1 w transposed [k][oc]
__device__ float g_w2t [EMBD*9*EMBD];         // conv2 w transposed [ic*9+k][oc]
__device__ float g_h1  [BATCH*EMBD*NE*NE];    // conv1 out [b][c][H][W]
__device__ float g_h2  [BATCH*EMBD*NE*NE];    // conv2 out [b][c][H][W]
__device__ float g_attn[NPAIR*EMBD];          // [pq][c]
__device__ float g_S   [NROWS*EMBD];
__device__ float g_O   [NROWS*EMBD];
__device__ float g_zs  [NPAIR*EMBD];
__device__ float g_zo  [NPAIR*EMBD];

// ---------------- prep: weight permutes (inputs change every call) ----------------
__global__ void k_prep(const float* __restrict__ c1w,
                       const float* __restrict__ c2w,
                       const float* __restrict__ wsim3)
{
    int i = blockIdx.x * 256 + threadIdx.x;
    if (i < 27*EMBD) {                       // w1t[k*256+oc] = c1w[oc*27+k]
        int oc = i & 255, k = i >> 8;
        g_w1t[i] = c1w[oc*27 + k];
    }
    if (i < EMBD*9*EMBD) {                   // w2t[r*256+oc] = c2w[oc*2304+r]
        int oc = i & 255, r = i >> 8;
        g_w2t[i] = c2w[oc*2304 + r];
    }
    if (i < NE*EMBD*EMBD) {                  // W3[(j*256+m)*256+n] = wsim3[j,n,m]
        int n = i & 255;
        int c = i >> 8;
        int j = c >> 8, m = c & 255;
        g_W3[i] = wsim3[j*65536 + n*256 + m];
    }
}

// ---------------- shared tiled SGEMM-NT:  C[M,N] = A[M,K] * W[N,K]^T (+bias) ------
// amode 0: A row-major [M,K]
// amode 1: A is g_h2 viewed as rows=pixels, cols=channels:
//          A[row,k] = base[(row/1764)*EMBD*1764 + k*1764 + row%1764]
__device__ __forceinline__ void gemm_nt_dev(
    const float* __restrict__ A, const float* __restrict__ W,
    float* __restrict__ C, const float* __restrict__ bias,
    int M, int N, int K, int amode)
{
    __shared__ float As[16][68];
    __shared__ float Bs[16][68];
    const int tid = threadIdx.x;
    const int tx = tid & 15, ty = tid >> 4;
    const int m0 = blockIdx.y * 64, n0 = blockIdx.x * 64;
    float acc[4][4];
#pragma unroll
    for (int i = 0; i < 4; i++)
#pragma unroll
        for (int j = 0; j < 4; j++) acc[i][j] = 0.f;

    for (int k0 = 0; k0 < K; k0 += 16) {
        if (amode == 0) {
            for (int e = tid; e < 1024; e += 256) {
                int kk = e & 15, m = e >> 4;
                int gm = m0 + m;
                As[kk][m] = (gm < M) ? A[gm * K + k0 + kk] : 0.f;
            }
        } else {
            for (int e = tid; e < 1024; e += 256) {
                int kk = e >> 6, m = e & 63;
                int gm = m0 + m;
                float v = 0.f;
                if (gm < M) {
                    int bb  = gm / NPIX;
                    int pix = gm - bb * NPIX;
                    v = A[bb * (EMBD*NPIX) + (k0 + kk) * NPIX + pix];
                }
                As[kk][m] = v;
            }
        }
        for (int e = tid; e < 1024; e += 256) {
            int kk = e & 15, n = e >> 4;
            int gn = n0 + n;
            Bs[kk][n] = (gn < N) ? W[gn * K + k0 + kk] : 0.f;
        }
        __syncthreads();
#pragma unroll
        for (int kk = 0; kk < 16; kk++) {
            float a0 = As[kk][ty*4+0], a1 = As[kk][ty*4+1];
            float a2 = As[kk][ty*4+2], a3 = As[kk][ty*4+3];
            float b0 = Bs[kk][tx*4+0], b1 = Bs[kk][tx*4+1];
            float b2 = Bs[kk][tx*4+2], b3 = Bs[kk][tx*4+3];
            acc[0][0] += a0*b0; acc[0][1] += a0*b1; acc[0][2] += a0*b2; acc[0][3] += a0*b3;
            acc[1][0] += a1*b0; acc[1][1] += a1*b1; acc[1][2] += a1*b2; acc[1][3] += a1*b3;
            acc[2][0] += a2*b0; acc[2][1] += a2*b1; acc[2][2] += a2*b2; acc[2][3] += a2*b3;
            acc[3][0] += a3*b0; acc[3][1] += a3*b1; acc[3][2] += a3*b2; acc[3][3] += a3*b3;
        }
        __syncthreads();
    }
#pragma unroll
    for (int i = 0; i < 4; i++) {
        int gm = m0 + ty*4 + i;
        if (gm >= M) continue;
#pragma unroll
        for (int j = 0; j < 4; j++) {
            int gn = n0 + tx*4 + j;
            if (gn < N)
                C[gm * N + gn] = acc[i][j] + (bias ? bias[gn] : 0.f);
        }
    }
}

__global__ void __launch_bounds__(256) k_gemm_E(const float* __restrict__ ent,
                                                const float* __restrict__ wred)
{ gemm_nt_dev(ent, wred, g_e, nullptr, NROWS, EMBD, IN_D, 0); }

__global__ void __launch_bounds__(256) k_gemm_T()
{ gemm_nt_dev(g_e, g_W3, g_T, nullptr, NROWS, NE*EMBD, EMBD, 0); }

__global__ void __launch_bounds__(256) k_gemm_attn(const float* __restrict__ wlin,
                                                   const float* __restrict__ blin)
{ gemm_nt_dev(g_h2, wlin, g_attn, blin, NPAIR, EMBD, EMBD, 1); }

// fused S and O projections: z-dim selects which
__global__ void __launch_bounds__(256) k_gemm_SO(const float* __restrict__ ws,
                                                 const float* __restrict__ wo)
{
    if (blockIdx.z == 0)
        gemm_nt_dev(g_e, ws, g_S, nullptr, NROWS, EMBD, EMBD, 0);
    else
        gemm_nt_dev(g_e, wo, g_O, nullptr, NROWS, EMBD, EMBD, 0);
}

// ---------------- norms ----------------
__global__ void k_norms()
{
    int bi = blockIdx.x;
    int tid = threadIdx.x;
    float v = g_e[bi*EMBD + tid];
    float s = v * v;
    __shared__ float red[8];
    for (int off = 16; off; off >>= 1) s += __shfl_down_sync(0xffffffffu, s, off);
    if ((tid & 31) == 0) red[tid >> 5] = s;
    __syncthreads();
    if (tid == 0) {
        float t = 0.f;
#pragma unroll
        for (int i = 0; i < 8; i++) t += red[i];
        g_norm[bi] = sqrtf(t);
    }
}

// ---------------- sim1/sim2 -> fm channels 0,1 ----------------
// fm[b,c,H,W] = sim_c[b, i=W, j=H]; sim1/sim2 symmetric in (i,j)
__global__ void k_sims()
{
    int b = blockIdx.x, H = blockIdx.y;
    int tid = threadIdx.x, lane = tid & 31, wid = tid >> 5;
    __shared__ float eH[EMBD];
    eH[tid] = g_e[(b*NE + H)*EMBD + tid];
    __syncthreads();
    float nH = fmaxf(g_norm[b*NE + H], 1e-6f);
    for (int Wc = wid; Wc < NE; Wc += 8) {
        const float* eW = &g_e[(b*NE + Wc)*EMBD];
        float s = 0.f;
        for (int k = lane; k < EMBD; k += 32) s += eH[k] * eW[k];
        for (int off = 16; off; off >>= 1) s += __shfl_down_sync(0xffffffffu, s, off);
        if (lane == 0) {
            float nW = fmaxf(g_norm[b*NE + Wc], 1e-6f);
            g_fm[((b*3 + 0)*NE + H)*NE + Wc] = s;
            g_fm[((b*3 + 1)*NE + H)*NE + Wc] = s / (nH * nW);
        }
    }
}

// ---------------- sim3 epilogue: fm[b,2,H=j,W=r] = e_r^T Wsim3[j] e_r ----------
__global__ void k_sim3b()
{
    int bi = blockIdx.x;
    int tid = threadIdx.x, lane = tid & 31, wid = tid >> 5;
    __shared__ float ev[EMBD];
    ev[tid] = g_e[bi*EMBD + tid];
    __syncthreads();
    int b = bi / NE, r = bi - b*NE;
    for (int j = wid; j < NE; j += 8) {
        const float* Trow = &g_T[bi*(NE*EMBD) + j*EMBD];
        float s = 0.f;
        for (int k = lane; k < EMBD; k += 32) s += Trow[k] * ev[k];
        for (int off = 16; off; off >>= 1) s += __shfl_down_sync(0xffffffffu, s, off);
        if (lane == 0) g_fm[((b*3 + 2)*NE + j)*NE + r] = s;
    }
}

// ---------------- conv1: 3->256, 3x3 SAME, bias + relu ----------------
__global__ void __launch_bounds__(256) k_conv1(const float* __restrict__ b1)
{
    int b = blockIdx.x, H = blockIdx.y;
    int oc = threadIdx.x;
    __shared__ float sm[3][3][44];
    for (int idx = threadIdx.x; idx < 396; idx += 256) {
        int ch = idx / 132, rem = idx - ch*132;
        int r = rem / 44, w = rem - r*44;
        int y = H + r - 1, x = w - 1;
        float v = 0.f;
        if (y >= 0 && y < NE && x >= 0 && x < NE)
            v = g_fm[((b*3 + ch)*NE + y)*NE + x];
        sm[ch][r][w] = v;
    }
    __syncthreads();
    float wreg[27];
#pragma unroll
    for (int k = 0; k < 27; k++) wreg[k] = g_w1t[k*EMBD + oc];
    float acc[NE];
    float bias = b1[oc];
#pragma unroll
    for (int W = 0; W < NE; W++) acc[W] = bias;
#pragma unroll
    for (int ch = 0; ch < 3; ch++)
#pragma unroll
    for (int ky = 0; ky < 3; ky++) {
        const float* row = sm[ch][ky];
        float w0 = wreg[(ch*3+ky)*3+0];
        float w1 = wreg[(ch*3+ky)*3+1];
        float w2 = wreg[(ch*3+ky)*3+2];
        float r0 = row[0], r1 = row[1];
#pragma unroll
        for (int W = 0; W < NE; W++) {
            float r2 = row[W + 2];
            acc[W] += w0*r0 + w1*r1 + w2*r2;
            r0 = r1; r1 = r2;
        }
    }
    int base = ((b*EMBD + oc)*NE + H)*NE;
#pragma unroll
    for (int W = 0; W < NE; W++) g_h1[base + W] = fmaxf(acc[W], 0.f);
}

// ---------------- conv2: 256->256, 3x3 SAME, bias ----------------
__global__ void __launch_bounds__(128) k_conv2(const float* __restrict__ b2)
{
    int b = blockIdx.x, H = blockIdx.y;
    int oc = blockIdx.z * 128 + threadIdx.x;
    __shared__ float sm[32][3][44];
    float acc[NE];
    float bias = b2[oc];
#pragma unroll
    for (int W = 0; W < NE; W++) acc[W] = bias;
    for (int ict = 0; ict < 8; ict++) {
        for (int idx = threadIdx.x; idx < 4224; idx += 128) {
            int ic = idx / 132, rem = idx - ic*132;
            int r = rem / 44, w = rem - r*44;
            int y = H + r - 1, x = w - 1;
            float v = 0.f;
            if (y >= 0 && y < NE && x >= 0 && x < NE)
                v = g_h1[((b*EMBD + ict*32 + ic)*NE + y)*NE + x];
            sm[ic][r][w] = v;
        }
        __syncthreads();
        for (int ic = 0; ic < 32; ic++) {
            float w9[9];
#pragma unroll
            for (int k = 0; k < 9; k++)
                w9[k] = g_w2t[((ict*32 + ic)*9 + k)*EMBD + oc];
#pragma unroll
            for (int ky = 0; ky < 3; ky++) {
                const float* row = sm[ic][ky];
                float r0 = row[0], r1 = row[1];
#pragma unroll
                for (int W = 0; W < NE; W++) {
                    float r2 = row[W + 2];
                    acc[W] += w9[ky*3+0]*r0 + w9[ky*3+1]*r1 + w9[ky*3+2]*r2;
                    r0 = r1; r1 = r2;
                }
            }
        }
        __syncthreads();
    }
    int base = ((b*EMBD + oc)*NE + H)*NE;
#pragma unroll
    for (int W = 0; W < NE; W++) g_h2[base + W] = acc[W];
}

// ---------------- zs / zo: tanh(S/O broadcast + attn) ----------------
__global__ void k_zszo()
{
    int pq = blockIdx.x;
    int c  = threadIdx.x;
    int b   = pq / NPIX;
    int rem = pq - b*NPIX;
    int a1  = rem / NE;
    int a2  = rem - a1*NE;
    float a = g_attn[pq*EMBD + c];
    g_zs[pq*EMBD + c] = tanhf(g_S[(b*NE + a1)*EMBD + c] + a);
    g_zo[pq*EMBD + c] = tanhf(g_O[(b*NE + a2)*EMBD + c] + a);
}

// ---------------- final bilinear: out[pq,o] = zs^T W_bil[o] zo + b ----------------
// grid (168 pair-tiles of 42, 97 o). zs tile in SMEM (broadcast LDS.128),
// W rows streamed coalesced (L2-resident), 42 accumulators/thread.
__global__ void __launch_bounds__(256) k_final(const float* __restrict__ Wb,
                                               const float* __restrict__ bb,
                                               float* __restrict__ out)
{
    __shared__ float szs[NE*EMBD];     // 42 pairs x 256 = 43 KB
    __shared__ float wpart[NE][8];
    const int tid = threadIdx.x;
    const int lane = tid & 31, wid = tid >> 5;
    const int pq0 = blockIdx.x * NE;
    const int o = blockIdx.y;

    for (int i = tid; i < NE*EMBD; i += 256)
        szs[i] = g_zs[pq0*EMBD + i];
    __syncthreads();

    const float* __restrict__ W = Wb + o * (EMBD*EMBD);
    float y[NE];
#pragma unroll
    for (int p = 0; p < NE; p++) y[p] = 0.f;

    const float4* szs4 = reinterpret_cast<const float4*>(szs);
    for (int n4 = 0; n4 < EMBD/4; n4++) {
        float w0 = __ldg(&W[(4*n4 + 0)*EMBD + tid]);
        float w1 = __ldg(&W[(4*n4 + 1)*EMBD + tid]);
        float w2 = __ldg(&W[(4*n4 + 2)*EMBD + tid]);
        float w3 = __ldg(&W[(4*n4 + 3)*EMBD + tid]);
#pragma unroll
        for (int p = 0; p < NE; p++) {
            float4 z = szs4[p*(EMBD/4) + n4];
            y[p] += z.x*w0 + z.y*w1 + z.z*w2 + z.w*w3;
        }
    }

    // deterministic reduction: warp shuffle -> per-warp partials -> 8-way sum
#pragma unroll 1
    for (int p = 0; p < NE; p++) {
        float v = y[p] * __ldg(&g_zo[(pq0 + p)*EMBD + tid]);
        for (int off = 16; off; off >>= 1) v += __shfl_down_sync(0xffffffffu, v, off);
        if (lane == 0) wpart[p][wid] = v;
    }
    __syncthreads();
    if (tid < NE) {
        float s = 0.f;
#pragma unroll
        for (int w = 0; w < 8; w++) s += wpart[tid][w];
        out[(pq0 + tid)*NREL + o] = s + __ldg(&bb[o]);
    }
}

// ---------------- launcher ----------------
extern "C" void kernel_launch(void* const* d_in, const int* in_sizes, int n_in,
                              void* d_out, int out_size)
{
    const float* entity  = (const float*)d_in[0];
    const float* w_red   = (const float*)d_in[1];
    const float* w_sim3  = (const float*)d_in[2];
    const float* c1w     = (const float*)d_in[3];
    const float* c1b     = (const float*)d_in[4];
    const float* c2w     = (const float*)d_in[5];
    const float* c2b     = (const float*)d_in[6];
    const float* w_lin   = (const float*)d_in[7];
    const float* b_lin   = (const float*)d_in[8];
    const float* w_s     = (const float*)d_in[9];
    const float* w_o     = (const float*)d_in[10];
    const float* w_bil   = (const float*)d_in[11];
    const float* b_bil   = (const float*)d_in[12];
    float* out = (float*)d_out;

    // weight permutes (largest: W3 = 2,752,512 elems)
    k_prep<<<(NE*EMBD*EMBD + 255)/256, 256>>>(c1w, c2w, w_sim3);

    // e = entity @ W_reduce^T
    k_gemm_E<<<dim3((EMBD+63)/64, (NROWS+63)/64), 256>>>(entity, w_red);
    k_norms<<<NROWS, 256>>>();

    // sim3 GEMM: T = E @ W3^T   [168 x 10752 x 256]
    k_gemm_T<<<dim3((NE*EMBD)/64, (NROWS+63)/64), 256>>>();

    k_sims<<<dim3(BATCH, NE), 256>>>();
    k_sim3b<<<NROWS, 256>>>();

    k_conv1<<<dim3(BATCH, NE), 256>>>(c1b);
    k_conv2<<<dim3(BATCH, NE, 2), 128>>>(c2b);

    // attn = h2 (pixel-major view) @ W_lin^T + b_lin   [7056 x 256 x 256]
    k_gemm_attn<<<dim3(EMBD/64, (NPAIR+63)/64), 256>>>(w_lin, b_lin);

    // S and O projections in one launch
    k_gemm_SO<<<dim3(EMBD/64, (NROWS+63)/64, 2), 256>>>(w_s, w_o);

    k_zszo<<<NPAIR, 256>>>();

    // dominant kernel: 44.8 GMACs
    k_final<<<dim3(NPAIR/NE, NREL), 256>>>(w_bil, b_bil, out);
}

// round 5
// speedup vs baseline: 1.6715x; 1.6715x over previous
#include <cuda_runtime.h>
#include <cuda_bf16.h>
#include <cstdint>
#include <math.h>

#define NE    42
#define BATCH 4
#define EMBD  256
#define IN_D  768
#define NREL  97
#define NPIX  (NE*NE)          // 1764
#define NROWS (BATCH*NE)       // 168
#define NPAIR (BATCH*NPIX)     // 7056
#define FB_TILE 128
#define NPAIR_PAD (56*FB_TILE) // 7168

// ---------------- scratch (static device memory; no allocation) ----------------
__device__ float g_e   [NROWS*EMBD];
__device__ float g_norm[NROWS];
__device__ float g_W3  [NE*EMBD*EMBD];
__device__ float g_T   [NROWS*NE*EMBD];
__device__ float g_fm  [BATCH*3*NE*NE];
__device__ float g_w1t [27*EMBD];
__device__ float g_w2t [EMBD*9*EMBD];
__device__ float g_h1  [BATCH*EMBD*NE*NE];
__device__ float g_h2  [BATCH*EMBD*NE*NE];
__device__ float g_attn[NPAIR*EMBD];
__device__ float g_S   [NROWS*EMBD];
__device__ float g_O   [NROWS*EMBD];
__device__ __nv_bfloat16 g_zs_hi[NPAIR_PAD*EMBD];
__device__ __nv_bfloat16 g_zs_lo[NPAIR_PAD*EMBD];
__device__ float         g_zo   [NPAIR_PAD*EMBD];
__device__ __nv_bfloat16 g_Wt_hi[NREL*EMBD*EMBD];   // [o][m][n] = W_bil[o][n][m]
__device__ __nv_bfloat16 g_Wt_lo[NREL*EMBD*EMBD];

// ---------------- prep: conv + sim3 weight permutes ----------------
__global__ void k_prep(const float* __restrict__ c1w,
                       const float* __restrict__ c2w,
                       const float* __restrict__ wsim3)
{
    int i = blockIdx.x * 256 + threadIdx.x;
    if (i < 27*EMBD) {
        int oc = i & 255, k = i >> 8;
        g_w1t[i] = c1w[oc*27 + k];
    }
    if (i < EMBD*9*EMBD) {
        int oc = i & 255, r = i >> 8;
        g_w2t[i] = c2w[oc*2304 + r];
    }
    if (i < NE*EMBD*EMBD) {
        int n = i & 255;
        int c = i >> 8;
        int j = c >> 8, m = c & 255;
        g_W3[i] = wsim3[j*65536 + n*256 + m];
    }
}

// ---------------- prep: W_bil transpose + bf16 hi/lo split ----------------
__global__ void __launch_bounds__(256) k_wsplit(const float* __restrict__ wbil)
{
    __shared__ float tile[32][33];
    int o = blockIdx.y;
    int t = blockIdx.x;
    int m0 = (t & 7) * 32, n0 = (t >> 3) * 32;
    int tx = threadIdx.x & 31, ty = threadIdx.x >> 5;
    for (int rr = ty; rr < 32; rr += 8)
        tile[rr][tx] = wbil[(size_t)o*65536 + (n0+rr)*256 + (m0+tx)];
    __syncthreads();
    for (int rr = ty; rr < 32; rr += 8) {
        float v = tile[tx][rr];                 // = w[o][n0+tx][m0+rr]
        __nv_bfloat16 hi = __float2bfloat16(v);
        __nv_bfloat16 lo = __float2bfloat16(v - __bfloat162float(hi));
        size_t di = (size_t)o*65536 + (size_t)(m0+rr)*256 + (n0+tx);
        g_Wt_hi[di] = hi;
        g_Wt_lo[di] = lo;
    }
}

// ---------------- shared tiled SGEMM-NT:  C[M,N] = A[M,K] * W[N,K]^T (+bias) ------
__device__ __forceinline__ void gemm_nt_dev(
    const float* __restrict__ A, const float* __restrict__ W,
    float* __restrict__ C, const float* __restrict__ bias,
    int M, int N, int K, int amode)
{
    __shared__ float As[16][68];
    __shared__ float Bs[16][68];
    const int tid = threadIdx.x;
    const int tx = tid & 15, ty = tid >> 4;
    const int m0 = blockIdx.y * 64, n0 = blockIdx.x * 64;
    float acc[4][4];
#pragma unroll
    for (int i = 0; i < 4; i++)
#pragma unroll
        for (int j = 0; j < 4; j++) acc[i][j] = 0.f;

    for (int k0 = 0; k0 < K; k0 += 16) {
        if (amode == 0) {
            for (int e = tid; e < 1024; e += 256) {
                int kk = e & 15, m = e >> 4;
                int gm = m0 + m;
                As[kk][m] = (gm < M) ? A[gm * K + k0 + kk] : 0.f;
            }
        } else {
            for (int e = tid; e < 1024; e += 256) {
                int kk = e >> 6, m = e & 63;
                int gm = m0 + m;
                float v = 0.f;
                if (gm < M) {
                    int bb  = gm / NPIX;
                    int pix = gm - bb * NPIX;
                    v = A[bb * (EMBD*NPIX) + (k0 + kk) * NPIX + pix];
                }
                As[kk][m] = v;
            }
        }
        for (int e = tid; e < 1024; e += 256) {
            int kk = e & 15, n = e >> 4;
            int gn = n0 + n;
            Bs[kk][n] = (gn < N) ? W[gn * K + k0 + kk] : 0.f;
        }
        __syncthreads();
#pragma unroll
        for (int kk = 0; kk < 16; kk++) {
            float a0 = As[kk][ty*4+0], a1 = As[kk][ty*4+1];
            float a2 = As[kk][ty*4+2], a3 = As[kk][ty*4+3];
            float b0 = Bs[kk][tx*4+0], b1 = Bs[kk][tx*4+1];
            float b2 = Bs[kk][tx*4+2], b3 = Bs[kk][tx*4+3];
            acc[0][0] += a0*b0; acc[0][1] += a0*b1; acc[0][2] += a0*b2; acc[0][3] += a0*b3;
            acc[1][0] += a1*b0; acc[1][1] += a1*b1; acc[1][2] += a1*b2; acc[1][3] += a1*b3;
            acc[2][0] += a2*b0; acc[2][1] += a2*b1; acc[2][2] += a2*b2; acc[2][3] += a2*b3;
            acc[3][0] += a3*b0; acc[3][1] += a3*b1; acc[3][2] += a3*b2; acc[3][3] += a3*b3;
        }
        __syncthreads();
    }
#pragma unroll
    for (int i = 0; i < 4; i++) {
        int gm = m0 + ty*4 + i;
        if (gm >= M) continue;
#pragma unroll
        for (int j = 0; j < 4; j++) {
            int gn = n0 + tx*4 + j;
            if (gn < N)
                C[gm * N + gn] = acc[i][j] + (bias ? bias[gn] : 0.f);
        }
    }
}

__global__ void __launch_bounds__(256) k_gemm_E(const float* __restrict__ ent,
                                                const float* __restrict__ wred)
{ gemm_nt_dev(ent, wred, g_e, nullptr, NROWS, EMBD, IN_D, 0); }

__global__ void __launch_bounds__(256) k_gemm_T()
{ gemm_nt_dev(g_e, g_W3, g_T, nullptr, NROWS, NE*EMBD, EMBD, 0); }

__global__ void __launch_bounds__(256) k_gemm_attn(const float* __restrict__ wlin,
                                                   const float* __restrict__ blin)
{ gemm_nt_dev(g_h2, wlin, g_attn, blin, NPAIR, EMBD, EMBD, 1); }

__global__ void __launch_bounds__(256) k_gemm_SO(const float* __restrict__ ws,
                                                 const float* __restrict__ wo)
{
    if (blockIdx.z == 0)
        gemm_nt_dev(g_e, ws, g_S, nullptr, NROWS, EMBD, EMBD, 0);
    else
        gemm_nt_dev(g_e, wo, g_O, nullptr, NROWS, EMBD, EMBD, 0);
}

// ---------------- norms ----------------
__global__ void k_norms()
{
    int bi = blockIdx.x;
    int tid = threadIdx.x;
    float v = g_e[bi*EMBD + tid];
    float s = v * v;
    __shared__ float red[8];
    for (int off = 16; off; off >>= 1) s += __shfl_down_sync(0xffffffffu, s, off);
    if ((tid & 31) == 0) red[tid >> 5] = s;
    __syncthreads();
    if (tid == 0) {
        float t = 0.f;
#pragma unroll
        for (int i = 0; i < 8; i++) t += red[i];
        g_norm[bi] = sqrtf(t);
    }
}

// ---------------- sim1/sim2 ----------------
__global__ void k_sims()
{
    int b = blockIdx.x, H = blockIdx.y;
    int tid = threadIdx.x, lane = tid & 31, wid = tid >> 5;
    __shared__ float eH[EMBD];
    eH[tid] = g_e[(b*NE + H)*EMBD + tid];
    __syncthreads();
    float nH = fmaxf(g_norm[b*NE + H], 1e-6f);
    for (int Wc = wid; Wc < NE; Wc += 8) {
        const float* eW = &g_e[(b*NE + Wc)*EMBD];
        float s = 0.f;
        for (int k = lane; k < EMBD; k += 32) s += eH[k] * eW[k];
        for (int off = 16; off; off >>= 1) s += __shfl_down_sync(0xffffffffu, s, off);
        if (lane == 0) {
            float nW = fmaxf(g_norm[b*NE + Wc], 1e-6f);
            g_fm[((b*3 + 0)*NE + H)*NE + Wc] = s;
            g_fm[((b*3 + 1)*NE + H)*NE + Wc] = s / (nH * nW);
        }
    }
}

// ---------------- sim3 epilogue ----------------
__global__ void k_sim3b()
{
    int bi = blockIdx.x;
    int tid = threadIdx.x, lane = tid & 31, wid = tid >> 5;
    __shared__ float ev[EMBD];
    ev[tid] = g_e[bi*EMBD + tid];
    __syncthreads();
    int b = bi / NE, r = bi - b*NE;
    for (int j = wid; j < NE; j += 8) {
        const float* Trow = &g_T[bi*(NE*EMBD) + j*EMBD];
        float s = 0.f;
        for (int k = lane; k < EMBD; k += 32) s += Trow[k] * ev[k];
        for (int off = 16; off; off >>= 1) s += __shfl_down_sync(0xffffffffu, s, off);
        if (lane == 0) g_fm[((b*3 + 2)*NE + j)*NE + r] = s;
    }
}

// ---------------- conv1 ----------------
__global__ void __launch_bounds__(256) k_conv1(const float* __restrict__ b1)
{
    int b = blockIdx.x, H = blockIdx.y;
    int oc = threadIdx.x;
    __shared__ float sm[3][3][44];
    for (int idx = threadIdx.x; idx < 396; idx += 256) {
        int ch = idx / 132, rem = idx - ch*132;
        int r = rem / 44, w = rem - r*44;
        int y = H + r - 1, x = w - 1;
        float v = 0.f;
        if (y >= 0 && y < NE && x >= 0 && x < NE)
            v = g_fm[((b*3 + ch)*NE + y)*NE + x];
        sm[ch][r][w] = v;
    }
    __syncthreads();
    float wreg[27];
#pragma unroll
    for (int k = 0; k < 27; k++) wreg[k] = g_w1t[k*EMBD + oc];
    float acc[NE];
    float bias = b1[oc];
#pragma unroll
    for (int W = 0; W < NE; W++) acc[W] = bias;
#pragma unroll
    for (int ch = 0; ch < 3; ch++)
#pragma unroll
    for (int ky = 0; ky < 3; ky++) {
        const float* row = sm[ch][ky];
        float w0 = wreg[(ch*3+ky)*3+0];
        float w1 = wreg[(ch*3+ky)*3+1];
        float w2 = wreg[(ch*3+ky)*3+2];
        float r0 = row[0], r1 = row[1];
#pragma unroll
        for (int W = 0; W < NE; W++) {
            float r2 = row[W + 2];
            acc[W] += w0*r0 + w1*r1 + w2*r2;
            r0 = r1; r1 = r2;
        }
    }
    int base = ((b*EMBD + oc)*NE + H)*NE;
#pragma unroll
    for (int W = 0; W < NE; W++) g_h1[base + W] = fmaxf(acc[W], 0.f);
}

// ---------------- conv2 ----------------
__global__ void __launch_bounds__(128) k_conv2(const float* __restrict__ b2)
{
    int b = blockIdx.x, H = blockIdx.y;
    int oc = blockIdx.z * 128 + threadIdx.x;
    __shared__ float sm[32][3][44];
    float acc[NE];
    float bias = b2[oc];
#pragma unroll
    for (int W = 0; W < NE; W++) acc[W] = bias;
    for (int ict = 0; ict < 8; ict++) {
        for (int idx = threadIdx.x; idx < 4224; idx += 128) {
            int ic = idx / 132, rem = idx - ic*132;
            int r = rem / 44, w = rem - r*44;
            int y = H + r - 1, x = w - 1;
            float v = 0.f;
            if (y >= 0 && y < NE && x >= 0 && x < NE)
                v = g_h1[((b*EMBD + ict*32 + ic)*NE + y)*NE + x];
            sm[ic][r][w] = v;
        }
        __syncthreads();
        for (int ic = 0; ic < 32; ic++) {
            float w9[9];
#pragma unroll
            for (int k = 0; k < 9; k++)
                w9[k] = g_w2t[((ict*32 + ic)*9 + k)*EMBD + oc];
#pragma unroll
            for (int ky = 0; ky < 3; ky++) {
                const float* row = sm[ic][ky];
                float r0 = row[0], r1 = row[1];
#pragma unroll
                for (int W = 0; W < NE; W++) {
                    float r2 = row[W + 2];
                    acc[W] += w9[ky*3+0]*r0 + w9[ky*3+1]*r1 + w9[ky*3+2]*r2;
                    r0 = r1; r1 = r2;
                }
            }
        }
        __syncthreads();
    }
    int base = ((b*EMBD + oc)*NE + H)*NE;
#pragma unroll
    for (int W = 0; W < NE; W++) g_h2[base + W] = acc[W];
}

// ---------------- zs/zo: tanh + bf16 hi/lo split (padded to 7168 rows) ----------
__global__ void k_zszo()
{
    int pq = blockIdx.x;
    int c  = threadIdx.x;
    float zs = 0.f, zo = 0.f;
    if (pq < NPAIR) {
        int b   = pq / NPIX;
        int rem = pq - b*NPIX;
        int a1  = rem / NE;
        int a2  = rem - a1*NE;
        float a = g_attn[pq*EMBD + c];
        zs = tanhf(g_S[(b*NE + a1)*EMBD + c] + a);
        zo = tanhf(g_O[(b*NE + a2)*EMBD + c] + a);
    }
    __nv_bfloat16 hi = __float2bfloat16(zs);
    __nv_bfloat16 lo = __float2bfloat16(zs - __bfloat162float(hi));
    g_zs_hi[pq*EMBD + c] = hi;
    g_zs_lo[pq*EMBD + c] = lo;
    g_zo  [pq*EMBD + c] = zo;
}

// ======================= final bilinear via mma.sync bf16 ======================
// Per CTA (o, 128-pair tile): D[p,m] = sum_n zs[p,n]*Wt[o][m][n] (3-pass hi/lo),
// epilogue out[pq,o] = sum_m D[p,m]*zo[p,m] + b[o].
#define FB_ZS_HI   0
#define FB_ZS_LO   67584              // 128 rows * 528 B (264 bf16, pad 8)
#define FB_WS_HI   135168             // 32 rows * 528 B
#define FB_WS_LO   152064
#define FB_ZO      168960             // 32 m * 133 floats * 4
#define FB_SUMS    185984             // 128 p * 2 * 4
#define FB_SMEM    187008
#define FB_RSTR    528                // row stride bytes (264 bf16)

__device__ __forceinline__ void ldm_x4(uint32_t* r, uint32_t addr) {
    asm volatile("ldmatrix.sync.aligned.m8n8.x4.shared.b16 {%0,%1,%2,%3}, [%4];"
                 : "=r"(r[0]), "=r"(r[1]), "=r"(r[2]), "=r"(r[3]) : "r"(addr));
}
__device__ __forceinline__ void mma_bf16(float* c, const uint32_t* a, const uint32_t* b) {
    asm volatile("mma.sync.aligned.m16n8k16.row.col.f32.bf16.bf16.f32 "
                 "{%0,%1,%2,%3}, {%4,%5,%6,%7}, {%8,%9}, {%0,%1,%2,%3};"
                 : "+f"(c[0]), "+f"(c[1]), "+f"(c[2]), "+f"(c[3])
                 : "r"(a[0]), "r"(a[1]), "r"(a[2]), "r"(a[3]), "r"(b[0]), "r"(b[1]));
}
__device__ __forceinline__ uint32_t smem_u32(const void* p) {
    uint32_t a;
    asm("{ .reg .u64 t; cvta.to.shared.u64 t, %1; cvt.u32.u64 %0, t; }" : "=r"(a) : "l"(p));
    return a;
}

__global__ void __launch_bounds__(256) k_final_mma(const float* __restrict__ bb,
                                                   float* __restrict__ out)
{
    extern __shared__ char smem[];
    const uint32_t sb = smem_u32(smem);
    const int tid  = threadIdx.x;
    const int lane = tid & 31;
    const int w    = tid >> 5;           // 8 warps
    const int pgrp = w >> 1;             // 0..3  (32 p each)
    const int wm   = w & 1;              // 0..1  (16 m each)
    const int pq0  = blockIdx.x * FB_TILE;
    const int o    = blockIdx.y;

    const uint32_t* __restrict__ zsh32 = (const uint32_t*)g_zs_hi;
    const uint32_t* __restrict__ zsl32 = (const uint32_t*)g_zs_lo;
    const uint32_t* __restrict__ wth32 = (const uint32_t*)g_Wt_hi;
    const uint32_t* __restrict__ wtl32 = (const uint32_t*)g_Wt_lo;

    // ---- load zs tile (128 x 256 bf16, hi & lo) once ----
    for (int i = tid; i < 128*128; i += 256) {
        int row = i >> 7, cu = i & 127;
        uint32_t off = row * FB_RSTR + cu * 4;
        uint32_t src = (uint32_t)((pq0 + row)*128 + cu);
        *(uint32_t*)(smem + FB_ZS_HI + off) = __ldg(&zsh32[src]);
        *(uint32_t*)(smem + FB_ZS_LO + off) = __ldg(&zsl32[src]);
    }

    // A ldmatrix address pieces (per lane): row-within-16 and k-half
    const int a_sub = (((lane >> 3) & 1) << 3) + (lane & 7);   // 0..15
    const int a_kh  = ((lane >> 4) & 1) << 3;                  // 0 or 8
    // B ldmatrix: m-within-16 and k-half
    const int b_sub = (((lane >> 4) & 1) << 3) + (lane & 7);   // 0..15
    const int b_kh  = ((lane >> 3) & 1) << 3;                  // 0 or 8

    float psum[2][2] = {{0.f, 0.f}, {0.f, 0.f}};  // [pf][rowhalf]
    float* zo_s = (float*)(smem + FB_ZO);

    for (int mc = 0; mc < 8; mc++) {
        __syncthreads();
        // ---- load W chunk (32 m x 256 n, hi & lo) + zo chunk ----
        for (int i = tid; i < 32*128; i += 256) {
            int r = i >> 7, cu = i & 127;
            uint32_t off = r * FB_RSTR + cu * 4;
            uint32_t src = (uint32_t)(o*32768 + (mc*32 + r)*128 + cu);
            *(uint32_t*)(smem + FB_WS_HI + off) = __ldg(&wth32[src]);
            *(uint32_t*)(smem + FB_WS_LO + off) = __ldg(&wtl32[src]);
        }
        for (int i = tid; i < 128*32; i += 256) {
            int p = i >> 5, m = i & 31;
            zo_s[m*133 + p] = __ldg(&g_zo[(size_t)(pq0 + p)*EMBD + mc*32 + m]);
        }
        __syncthreads();

        float acc[2][2][4];
#pragma unroll
        for (int pf = 0; pf < 2; pf++)
#pragma unroll
            for (int mf = 0; mf < 2; mf++)
#pragma unroll
                for (int q = 0; q < 4; q++) acc[pf][mf][q] = 0.f;

#pragma unroll 4
        for (int k0 = 0; k0 < 256; k0 += 16) {
            uint32_t ah[2][4], al[2][4], bh[4], bl[4];
#pragma unroll
            for (int pf = 0; pf < 2; pf++) {
                uint32_t arow = (uint32_t)(pgrp*32 + pf*16 + a_sub);
                uint32_t aoff = arow * FB_RSTR + (uint32_t)(k0 + a_kh) * 2;
                ldm_x4(ah[pf], sb + FB_ZS_HI + aoff);
                ldm_x4(al[pf], sb + FB_ZS_LO + aoff);
            }
            {
                uint32_t brow = (uint32_t)(wm*16 + b_sub);
                uint32_t boff = brow * FB_RSTR + (uint32_t)(k0 + b_kh) * 2;
                ldm_x4(bh, sb + FB_WS_HI + boff);
                ldm_x4(bl, sb + FB_WS_LO + boff);
            }
#pragma unroll
            for (int pf = 0; pf < 2; pf++)
#pragma unroll
                for (int mf = 0; mf < 2; mf++) {
                    mma_bf16(acc[pf][mf], ah[pf], bh + mf*2);
                    mma_bf16(acc[pf][mf], ah[pf], bl + mf*2);
                    mma_bf16(acc[pf][mf], al[pf], bh + mf*2);
                }
        }

        // ---- epilogue for this m-chunk: dot with zo ----
        const int mbase = wm*16 + (lane & 3)*2;   // + mf*8 + col
        const int prow  = (lane >> 2);
#pragma unroll
        for (int pf = 0; pf < 2; pf++) {
            int pl0 = pgrp*32 + pf*16 + prow;
#pragma unroll
            for (int mf = 0; mf < 2; mf++) {
                int ml = mbase + mf*8;
                float z0 = zo_s[ml*133 + pl0];
                float z1 = zo_s[(ml+1)*133 + pl0];
                float z2 = zo_s[ml*133 + pl0 + 8];
                float z3 = zo_s[(ml+1)*133 + pl0 + 8];
                psum[pf][0] += acc[pf][mf][0]*z0 + acc[pf][mf][1]*z1;
                psum[pf][1] += acc[pf][mf][2]*z2 + acc[pf][mf][3]*z3;
            }
        }
    }

    // ---- reduce across the 4 lanes of each quad (different m) ----
    float* sums = (float*)(smem + FB_SUMS);
#pragma unroll
    for (int pf = 0; pf < 2; pf++)
#pragma unroll
        for (int rh = 0; rh < 2; rh++) {
            float v = psum[pf][rh];
            v += __shfl_xor_sync(0xffffffffu, v, 1);
            v += __shfl_xor_sync(0xffffffffu, v, 2);
            if ((lane & 3) == 0) {
                int p = pgrp*32 + pf*16 + rh*8 + (lane >> 2);
                sums[p*2 + wm] = v;
            }
        }
    __syncthreads();

    if (tid < 128) {
        int pq = pq0 + tid;
        if (pq < NPAIR) {
            float tot = sums[tid*2] + sums[tid*2 + 1] + __ldg(&bb[o]);
            out[(size_t)pq*NREL + o] = tot;
        }
    }
}

// ---------------- launcher ----------------
extern "C" void kernel_launch(void* const* d_in, const int* in_sizes, int n_in,
                              void* d_out, int out_size)
{
    const float* entity  = (const float*)d_in[0];
    const float* w_red   = (const float*)d_in[1];
    const float* w_sim3  = (const float*)d_in[2];
    const float* c1w     = (const float*)d_in[3];
    const float* c1b     = (const float*)d_in[4];
    const float* c2w     = (const float*)d_in[5];
    const float* c2b     = (const float*)d_in[6];
    const float* w_lin   = (const float*)d_in[7];
    const float* b_lin   = (const float*)d_in[8];
    const float* w_s     = (const float*)d_in[9];
    const float* w_o     = (const float*)d_in[10];
    const float* w_bil   = (const float*)d_in[11];
    const float* b_bil   = (const float*)d_in[12];
    float* out = (float*)d_out;

    // idempotent, deterministic — same call every invocation (no static guards)
    cudaFuncSetAttribute(k_final_mma, cudaFuncAttributeMaxDynamicSharedMemorySize,
                         FB_SMEM);

    k_prep<<<(NE*EMBD*EMBD + 255)/256, 256>>>(c1w, c2w, w_sim3);
    k_wsplit<<<dim3(64, NREL), 256>>>(w_bil);

    k_gemm_E<<<dim3((EMBD+63)/64, (NROWS+63)/64), 256>>>(entity, w_red);
    k_norms<<<NROWS, 256>>>();

    k_gemm_T<<<dim3((NE*EMBD)/64, (NROWS+63)/64), 256>>>();

    k_sims<<<dim3(BATCH, NE), 256>>>();
    k_sim3b<<<NROWS, 256>>>();

    k_conv1<<<dim3(BATCH, NE), 256>>>(c1b);
    k_conv2<<<dim3(BATCH, NE, 2), 128>>>(c2b);

    k_gemm_attn<<<dim3(EMBD/64, (NPAIR+63)/64), 256>>>(w_lin, b_lin);
    k_gemm_SO<<<dim3(EMBD/64, (NROWS+63)/64, 2), 256>>>(w_s, w_o);

    k_zszo<<<NPAIR_PAD, 256>>>();

    k_final_mma<<<dim3(NPAIR_PAD/FB_TILE, NREL), 256, FB_SMEM>>>(b_bil, out);
}

// round 6
// speedup vs baseline: 2.0304x; 1.2148x over previous
#include <cuda_runtime.h>
#include <cuda_bf16.h>
#include <cstdint>
#include <math.h>

#define NE    42
#define BATCH 4
#define EMBD  256
#define IN_D  768
#define NREL  97
#define NPIX  (NE*NE)          // 1764
#define NROWS (BATCH*NE)       // 168
#define NPAIR (BATCH*NPIX)     // 7056
#define FB_TILE 128
#define NPAIR_PAD (56*FB_TILE) // 7168

// ---------------- scratch (static device memory; no allocation) ----------------
__device__ float g_e   [NROWS*EMBD];
__device__ float g_norm[NROWS];
__device__ float g_W3  [NE*EMBD*EMBD];
__device__ float g_T   [NROWS*NE*EMBD];
__device__ float g_fm  [BATCH*3*NE*NE];
__device__ float g_w1t [27*EMBD];
__device__ float g_w2t [EMBD*9*EMBD];
__device__ float g_h1  [BATCH*EMBD*NE*NE];
__device__ float g_h2  [BATCH*EMBD*NE*NE];
__device__ float g_attn[NPAIR*EMBD];
__device__ float g_S   [NROWS*EMBD];
__device__ float g_O   [NROWS*EMBD];
__device__ __nv_bfloat16 g_zs_hi[NPAIR_PAD*EMBD];
__device__ __nv_bfloat16 g_zs_lo[NPAIR_PAD*EMBD];
__device__ float         g_zo   [NPAIR_PAD*EMBD];
__device__ __nv_bfloat16 g_Wt_hi[NREL*EMBD*EMBD];   // [o][m][n] = W_bil[o][n][m]
__device__ __nv_bfloat16 g_Wt_lo[NREL*EMBD*EMBD];

// ---------------- prep: conv + sim3 weight permutes ----------------
__global__ void k_prep(const float* __restrict__ c1w,
                       const float* __restrict__ c2w,
                       const float* __restrict__ wsim3)
{
    int i = blockIdx.x * 256 + threadIdx.x;
    if (i < 27*EMBD) {
        int oc = i & 255, k = i >> 8;
        g_w1t[i] = c1w[oc*27 + k];
    }
    if (i < EMBD*9*EMBD) {
        int oc = i & 255, r = i >> 8;
        g_w2t[i] = c2w[oc*2304 + r];
    }
    if (i < NE*EMBD*EMBD) {
        int n = i & 255;
        int c = i >> 8;
        int j = c >> 8, m = c & 255;
        g_W3[i] = wsim3[j*65536 + n*256 + m];
    }
}

// ---------------- prep: W_bil transpose + bf16 hi/lo split ----------------
__global__ void __launch_bounds__(256) k_wsplit(const float* __restrict__ wbil)
{
    __shared__ float tile[32][33];
    int o = blockIdx.y;
    int t = blockIdx.x;
    int m0 = (t & 7) * 32, n0 = (t >> 3) * 32;
    int tx = threadIdx.x & 31, ty = threadIdx.x >> 5;
    for (int rr = ty; rr < 32; rr += 8)
        tile[rr][tx] = wbil[(size_t)o*65536 + (n0+rr)*256 + (m0+tx)];
    __syncthreads();
    for (int rr = ty; rr < 32; rr += 8) {
        float v = tile[tx][rr];                 // = w[o][n0+tx][m0+rr]
        __nv_bfloat16 hi = __float2bfloat16(v);
        __nv_bfloat16 lo = __float2bfloat16(v - __bfloat162float(hi));
        size_t di = (size_t)o*65536 + (size_t)(m0+rr)*256 + (n0+tx);
        g_Wt_hi[di] = hi;
        g_Wt_lo[di] = lo;
    }
}

// ---------------- shared tiled SGEMM-NT:  C[M,N] = A[M,K] * W[N,K]^T (+bias) ------
__device__ __forceinline__ void gemm_nt_dev(
    const float* __restrict__ A, const float* __restrict__ W,
    float* __restrict__ C, const float* __restrict__ bias,
    int M, int N, int K, int amode)
{
    __shared__ float As[16][68];
    __shared__ float Bs[16][68];
    const int tid = threadIdx.x;
    const int tx = tid & 15, ty = tid >> 4;
    const int m0 = blockIdx.y * 64, n0 = blockIdx.x * 64;
    float acc[4][4];
#pragma unroll
    for (int i = 0; i < 4; i++)
#pragma unroll
        for (int j = 0; j < 4; j++) acc[i][j] = 0.f;

    for (int k0 = 0; k0 < K; k0 += 16) {
        if (amode == 0) {
            for (int e = tid; e < 1024; e += 256) {
                int kk = e & 15, m = e >> 4;
                int gm = m0 + m;
                As[kk][m] = (gm < M) ? A[gm * K + k0 + kk] : 0.f;
            }
        } else {
            for (int e = tid; e < 1024; e += 256) {
                int kk = e >> 6, m = e & 63;
                int gm = m0 + m;
                float v = 0.f;
                if (gm < M) {
                    int bb  = gm / NPIX;
                    int pix = gm - bb * NPIX;
                    v = A[bb * (EMBD*NPIX) + (k0 + kk) * NPIX + pix];
                }
                As[kk][m] = v;
            }
        }
        for (int e = tid; e < 1024; e += 256) {
            int kk = e & 15, n = e >> 4;
            int gn = n0 + n;
            Bs[kk][n] = (gn < N) ? W[gn * K + k0 + kk] : 0.f;
        }
        __syncthreads();
#pragma unroll
        for (int kk = 0; kk < 16; kk++) {
            float a0 = As[kk][ty*4+0], a1 = As[kk][ty*4+1];
            float a2 = As[kk][ty*4+2], a3 = As[kk][ty*4+3];
            float b0 = Bs[kk][tx*4+0], b1 = Bs[kk][tx*4+1];
            float b2 = Bs[kk][tx*4+2], b3 = Bs[kk][tx*4+3];
            acc[0][0] += a0*b0; acc[0][1] += a0*b1; acc[0][2] += a0*b2; acc[0][3] += a0*b3;
            acc[1][0] += a1*b0; acc[1][1] += a1*b1; acc[1][2] += a1*b2; acc[1][3] += a1*b3;
            acc[2][0] += a2*b0; acc[2][1] += a2*b1; acc[2][2] += a2*b2; acc[2][3] += a2*b3;
            acc[3][0] += a3*b0; acc[3][1] += a3*b1; acc[3][2] += a3*b2; acc[3][3] += a3*b3;
        }
        __syncthreads();
    }
#pragma unroll
    for (int i = 0; i < 4; i++) {
        int gm = m0 + ty*4 + i;
        if (gm >= M) continue;
#pragma unroll
        for (int j = 0; j < 4; j++) {
            int gn = n0 + tx*4 + j;
            if (gn < N)
                C[gm * N + gn] = acc[i][j] + (bias ? bias[gn] : 0.f);
        }
    }
}

__global__ void __launch_bounds__(256) k_gemm_E(const float* __restrict__ ent,
                                                const float* __restrict__ wred)
{ gemm_nt_dev(ent, wred, g_e, nullptr, NROWS, EMBD, IN_D, 0); }

__global__ void __launch_bounds__(256) k_gemm_T()
{ gemm_nt_dev(g_e, g_W3, g_T, nullptr, NROWS, NE*EMBD, EMBD, 0); }

__global__ void __launch_bounds__(256) k_gemm_attn(const float* __restrict__ wlin,
                                                   const float* __restrict__ blin)
{ gemm_nt_dev(g_h2, wlin, g_attn, blin, NPAIR, EMBD, EMBD, 1); }

__global__ void __launch_bounds__(256) k_gemm_SO(const float* __restrict__ ws,
                                                 const float* __restrict__ wo)
{
    if (blockIdx.z == 0)
        gemm_nt_dev(g_e, ws, g_S, nullptr, NROWS, EMBD, EMBD, 0);
    else
        gemm_nt_dev(g_e, wo, g_O, nullptr, NROWS, EMBD, EMBD, 0);
}

// ---------------- norms ----------------
__global__ void k_norms()
{
    int bi = blockIdx.x;
    int tid = threadIdx.x;
    float v = g_e[bi*EMBD + tid];
    float s = v * v;
    __shared__ float red[8];
    for (int off = 16; off; off >>= 1) s += __shfl_down_sync(0xffffffffu, s, off);
    if ((tid & 31) == 0) red[tid >> 5] = s;
    __syncthreads();
    if (tid == 0) {
        float t = 0.f;
#pragma unroll
        for (int i = 0; i < 8; i++) t += red[i];
        g_norm[bi] = sqrtf(t);
    }
}

// ---------------- sim1/sim2 ----------------
__global__ void k_sims()
{
    int b = blockIdx.x, H = blockIdx.y;
    int tid = threadIdx.x, lane = tid & 31, wid = tid >> 5;
    __shared__ float eH[EMBD];
    eH[tid] = g_e[(b*NE + H)*EMBD + tid];
    __syncthreads();
    float nH = fmaxf(g_norm[b*NE + H], 1e-6f);
    for (int Wc = wid; Wc < NE; Wc += 8) {
        const float* eW = &g_e[(b*NE + Wc)*EMBD];
        float s = 0.f;
        for (int k = lane; k < EMBD; k += 32) s += eH[k] * eW[k];
        for (int off = 16; off; off >>= 1) s += __shfl_down_sync(0xffffffffu, s, off);
        if (lane == 0) {
            float nW = fmaxf(g_norm[b*NE + Wc], 1e-6f);
            g_fm[((b*3 + 0)*NE + H)*NE + Wc] = s;
            g_fm[((b*3 + 1)*NE + H)*NE + Wc] = s / (nH * nW);
        }
    }
}

// ---------------- sim3 epilogue ----------------
__global__ void k_sim3b()
{
    int bi = blockIdx.x;
    int tid = threadIdx.x, lane = tid & 31, wid = tid >> 5;
    __shared__ float ev[EMBD];
    ev[tid] = g_e[bi*EMBD + tid];
    __syncthreads();
    int b = bi / NE, r = bi - b*NE;
    for (int j = wid; j < NE; j += 8) {
        const float* Trow = &g_T[bi*(NE*EMBD) + j*EMBD];
        float s = 0.f;
        for (int k = lane; k < EMBD; k += 32) s += Trow[k] * ev[k];
        for (int off = 16; off; off >>= 1) s += __shfl_down_sync(0xffffffffu, s, off);
        if (lane == 0) g_fm[((b*3 + 2)*NE + j)*NE + r] = s;
    }
}

// ---------------- conv1 ----------------
__global__ void __launch_bounds__(256) k_conv1(const float* __restrict__ b1)
{
    int b = blockIdx.x, H = blockIdx.y;
    int oc = threadIdx.x;
    __shared__ float sm[3][3][44];
    for (int idx = threadIdx.x; idx < 396; idx += 256) {
        int ch = idx / 132, rem = idx - ch*132;
        int r = rem / 44, w = rem - r*44;
        int y = H + r - 1, x = w - 1;
        float v = 0.f;
        if (y >= 0 && y < NE && x >= 0 && x < NE)
            v = g_fm[((b*3 + ch)*NE + y)*NE + x];
        sm[ch][r][w] = v;
    }
    __syncthreads();
    float wreg[27];
#pragma unroll
    for (int k = 0; k < 27; k++) wreg[k] = g_w1t[k*EMBD + oc];
    float acc[NE];
    float bias = b1[oc];
#pragma unroll
    for (int W = 0; W < NE; W++) acc[W] = bias;
#pragma unroll
    for (int ch = 0; ch < 3; ch++)
#pragma unroll
    for (int ky = 0; ky < 3; ky++) {
        const float* row = sm[ch][ky];
        float w0 = wreg[(ch*3+ky)*3+0];
        float w1 = wreg[(ch*3+ky)*3+1];
        float w2 = wreg[(ch*3+ky)*3+2];
        float r0 = row[0], r1 = row[1];
#pragma unroll
        for (int W = 0; W < NE; W++) {
            float r2 = row[W + 2];
            acc[W] += w0*r0 + w1*r1 + w2*r2;
            r0 = r1; r1 = r2;
        }
    }
    int base = ((b*EMBD + oc)*NE + H)*NE;
#pragma unroll
    for (int W = 0; W < NE; W++) g_h1[base + W] = fmaxf(acc[W], 0.f);
}

// ---------------- conv2 ----------------
__global__ void __launch_bounds__(128) k_conv2(const float* __restrict__ b2)
{
    int b = blockIdx.x, H = blockIdx.y;
    int oc = blockIdx.z * 128 + threadIdx.x;
    __shared__ float sm[32][3][44];
    float acc[NE];
    float bias = b2[oc];
#pragma unroll
    for (int W = 0; W < NE; W++) acc[W] = bias;
    for (int ict = 0; ict < 8; ict++) {
        for (int idx = threadIdx.x; idx < 4224; idx += 128) {
            int ic = idx / 132, rem = idx - ic*132;
            int r = rem / 44, w = rem - r*44;
            int y = H + r - 1, x = w - 1;
            float v = 0.f;
            if (y >= 0 && y < NE && x >= 0 && x < NE)
                v = g_h1[((b*EMBD + ict*32 + ic)*NE + y)*NE + x];
            sm[ic][r][w] = v;
        }
        __syncthreads();
        for (int ic = 0; ic < 32; ic++) {
            float w9[9];
#pragma unroll
            for (int k = 0; k < 9; k++)
                w9[k] = g_w2t[((ict*32 + ic)*9 + k)*EMBD + oc];
#pragma unroll
            for (int ky = 0; ky < 3; ky++) {
                const float* row = sm[ic][ky];
                float r0 = row[0], r1 = row[1];
#pragma unroll
                for (int W = 0; W < NE; W++) {
                    float r2 = row[W + 2];
                    acc[W] += w9[ky*3+0]*r0 + w9[ky*3+1]*r1 + w9[ky*3+2]*r2;
                    r0 = r1; r1 = r2;
                }
            }
        }
        __syncthreads();
    }
    int base = ((b*EMBD + oc)*NE + H)*NE;
#pragma unroll
    for (int W = 0; W < NE; W++) g_h2[base + W] = acc[W];
}

// ---------------- zs/zo: tanh + bf16 hi/lo split (padded to 7168 rows) ----------
__global__ void k_zszo()
{
    int pq = blockIdx.x;
    int c  = threadIdx.x;
    float zs = 0.f, zo = 0.f;
    if (pq < NPAIR) {
        int b   = pq / NPIX;
        int rem = pq - b*NPIX;
        int a1  = rem / NE;
        int a2  = rem - a1*NE;
        float a = g_attn[pq*EMBD + c];
        zs = tanhf(g_S[(b*NE + a1)*EMBD + c] + a);
        zo = tanhf(g_O[(b*NE + a2)*EMBD + c] + a);
    }
    __nv_bfloat16 hi = __float2bfloat16(zs);
    __nv_bfloat16 lo = __float2bfloat16(zs - __bfloat162float(hi));
    g_zs_hi[pq*EMBD + c] = hi;
    g_zs_lo[pq*EMBD + c] = lo;
    g_zo  [pq*EMBD + c] = zo;
}

// ======================= final bilinear via mma.sync bf16 ======================
// Per CTA (o, 128-pair tile): D[p,m] = sum_n zs[p,n]*Wt[o][m][n] (3-pass hi/lo,
// separate accumulators per pass), epilogue out[pq,o] = sum_m D[p,m]*zo[p,m]+b[o].
// cp.async double-buffers the W chunks; zs tile staged once via cp.async.
#define FB_ZS_HI   0
#define FB_ZS_LO   67584              // 128 rows * 528 B
#define FB_W       135168             // 2 bufs * 33792 (hi 16896 + lo 16896)
#define FB_WBUF    33792
#define FB_ZO      202752             // 32 m * 133 floats * 4 = 17024
#define FB_SUMS    219776             // 128 p * 2 * 4 = 1024
#define FB_SMEM    220800
#define FB_RSTR    528                // row stride bytes (264 bf16)

__device__ __forceinline__ void ldm_x4(uint32_t* r, uint32_t addr) {
    asm volatile("ldmatrix.sync.aligned.m8n8.x4.shared.b16 {%0,%1,%2,%3}, [%4];"
                 : "=r"(r[0]), "=r"(r[1]), "=r"(r[2]), "=r"(r[3]) : "r"(addr));
}
__device__ __forceinline__ void mma_bf16(float* c, const uint32_t* a, const uint32_t* b) {
    asm volatile("mma.sync.aligned.m16n8k16.row.col.f32.bf16.bf16.f32 "
                 "{%0,%1,%2,%3}, {%4,%5,%6,%7}, {%8,%9}, {%0,%1,%2,%3};"
                 : "+f"(c[0]), "+f"(c[1]), "+f"(c[2]), "+f"(c[3])
                 : "r"(a[0]), "r"(a[1]), "r"(a[2]), "r"(a[3]), "r"(b[0]), "r"(b[1]));
}
__device__ __forceinline__ uint32_t smem_u32(const void* p) {
    uint32_t a;
    asm("{ .reg .u64 t; cvta.to.shared.u64 t, %1; cvt.u32.u64 %0, t; }" : "=r"(a) : "l"(p));
    return a;
}
__device__ __forceinline__ void cp16(uint32_t dst, const void* src) {
    asm volatile("cp.async.cg.shared.global [%0], [%1], 16;" :: "r"(dst), "l"(src));
}
#define CP_COMMIT() asm volatile("cp.async.commit_group;" ::: "memory")
#define CP_WAIT0()  asm volatile("cp.async.wait_group 0;" ::: "memory")

__global__ void __launch_bounds__(256) k_final_mma(const float* __restrict__ bb,
                                                   float* __restrict__ out)
{
    extern __shared__ char smem[];
    const uint32_t sb = smem_u32(smem);
    const int tid  = threadIdx.x;
    const int lane = tid & 31;
    const int w    = tid >> 5;           // 8 warps
    const int pgrp = w >> 1;             // 0..3  (32 p each)
    const int wm   = w & 1;              // 0..1  (16 m each)
    const int pq0  = blockIdx.x * FB_TILE;
    const int o    = blockIdx.y;

    // ---- stage zs tile (128 x 256 bf16 hi & lo) via cp.async, 16B chunks ----
    for (int i = tid; i < 128*32; i += 256) {
        int row = i >> 5, c = i & 31;
        uint32_t off = (uint32_t)row * FB_RSTR + (uint32_t)c * 16;
        size_t gsrc = ((size_t)(pq0 + row) * 256 + (size_t)c * 8) * 2;  // bytes
        cp16(sb + FB_ZS_HI + off, (const char*)g_zs_hi + gsrc);
        cp16(sb + FB_ZS_LO + off, (const char*)g_zs_lo + gsrc);
    }
    // ---- prefetch W chunk 0 (hi & lo) ----
    {
        for (int i = tid; i < 1024; i += 256) {
            int r = i >> 5, c = i & 31;
            uint32_t off = (uint32_t)r * FB_RSTR + (uint32_t)c * 16;
            size_t gsrc = ((size_t)o * 32768 + (size_t)r * 128 + (size_t)c * 4) * 4;
            cp16(sb + FB_W + off,         (const char*)g_Wt_hi + gsrc);
            cp16(sb + FB_W + 16896 + off, (const char*)g_Wt_lo + gsrc);
        }
    }
    CP_COMMIT();

    // A ldmatrix address pieces (per lane): row-within-16 and k-half
    const int a_sub = (((lane >> 3) & 1) << 3) + (lane & 7);   // 0..15
    const int a_kh  = ((lane >> 4) & 1) << 3;                  // 0 or 8
    // B ldmatrix: m-within-16 and k-half
    const int b_sub = (((lane >> 4) & 1) << 3) + (lane & 7);   // 0..15
    const int b_kh  = ((lane >> 3) & 1) << 3;                  // 0 or 8

    float psum[2][2] = {{0.f, 0.f}, {0.f, 0.f}};  // [pf][rowhalf]
    float* zo_s = (float*)(smem + FB_ZO);

    for (int mc = 0; mc < 8; mc++) {
        const int cur = mc & 1, nxt = cur ^ 1;
        CP_WAIT0();
        __syncthreads();            // W[mc] (and zs on mc==0) visible to all

        // prefetch W[mc+1] into the other buffer (overlaps with compute below)
        if (mc < 7) {
            for (int i = tid; i < 1024; i += 256) {
                int r = i >> 5, c = i & 31;
                uint32_t off = (uint32_t)r * FB_RSTR + (uint32_t)c * 16;
                size_t gsrc = ((size_t)o * 32768 +
                               (size_t)((mc + 1) * 32 + r) * 128 + (size_t)c * 4) * 4;
                cp16(sb + FB_W + nxt*FB_WBUF + off,         (const char*)g_Wt_hi + gsrc);
                cp16(sb + FB_W + nxt*FB_WBUF + 16896 + off, (const char*)g_Wt_lo + gsrc);
            }
        }
        CP_COMMIT();

        // stage zo chunk (32 m x 128 p, transposed, conflict-free stride 133)
        for (int i = tid; i < 128*32; i += 256) {
            int p = i >> 5, m = i & 31;
            zo_s[m*133 + p] = __ldg(&g_zo[(size_t)(pq0 + p)*EMBD + mc*32 + m]);
        }
        __syncthreads();            // zo visible; W[mc+1] still in flight

        // ---- mainloop: 3 independent accumulator sets (12 indep chains/warp) ----
        float acc0[2][2][4], acc1[2][2][4], acc2[2][2][4];
#pragma unroll
        for (int pf = 0; pf < 2; pf++)
#pragma unroll
            for (int mf = 0; mf < 2; mf++)
#pragma unroll
                for (int q = 0; q < 4; q++) {
                    acc0[pf][mf][q] = 0.f; acc1[pf][mf][q] = 0.f; acc2[pf][mf][q] = 0.f;
                }

        const uint32_t wbase = sb + FB_W + cur*FB_WBUF;
#pragma unroll 4
        for (int k0 = 0; k0 < 256; k0 += 16) {
            uint32_t ah[2][4], al[2][4], bh[4], bl[4];
#pragma unroll
            for (int pf = 0; pf < 2; pf++) {
                uint32_t arow = (uint32_t)(pgrp*32 + pf*16 + a_sub);
                uint32_t aoff = arow * FB_RSTR + (uint32_t)(k0 + a_kh) * 2;
                ldm_x4(ah[pf], sb + FB_ZS_HI + aoff);
                ldm_x4(al[pf], sb + FB_ZS_LO + aoff);
            }
            {
                uint32_t brow = (uint32_t)(wm*16 + b_sub);
                uint32_t boff = brow * FB_RSTR + (uint32_t)(k0 + b_kh) * 2;
                ldm_x4(bh, wbase + boff);
                ldm_x4(bl, wbase + 16896 + boff);
            }
#pragma unroll
            for (int pf = 0; pf < 2; pf++)
#pragma unroll
                for (int mf = 0; mf < 2; mf++) {
                    mma_bf16(acc0[pf][mf], ah[pf], bh + mf*2);
                    mma_bf16(acc1[pf][mf], ah[pf], bl + mf*2);
                    mma_bf16(acc2[pf][mf], al[pf], bh + mf*2);
                }
        }

        // ---- epilogue for this m-chunk: combine passes, dot with zo ----
        const int mbase = wm*16 + (lane & 3)*2;
        const int prow  = (lane >> 2);
#pragma unroll
        for (int pf = 0; pf < 2; pf++) {
            int pl0 = pgrp*32 + pf*16 + prow;
#pragma unroll
            for (int mf = 0; mf < 2; mf++) {
                int ml = mbase + mf*8;
                float d0 = acc0[pf][mf][0] + acc1[pf][mf][0] + acc2[pf][mf][0];
                float d1 = acc0[pf][mf][1] + acc1[pf][mf][1] + acc2[pf][mf][1];
                float d2 = acc0[pf][mf][2] + acc1[pf][mf][2] + acc2[pf][mf][2];
                float d3 = acc0[pf][mf][3] + acc1[pf][mf][3] + acc2[pf][mf][3];
                float z0 = zo_s[ml*133 + pl0];
                float z1 = zo_s[(ml+1)*133 + pl0];
                float z2 = zo_s[ml*133 + pl0 + 8];
                float z3 = zo_s[(ml+1)*133 + pl0 + 8];
                psum[pf][0] += d0*z0 + d1*z1;
                psum[pf][1] += d2*z2 + d3*z3;
            }
        }
    }

    // ---- reduce across the 4 lanes of each quad (different m) ----
    __syncthreads();
    float* sums = (float*)(smem + FB_SUMS);
#pragma unroll
    for (int pf = 0; pf < 2; pf++)
#pragma unroll
        for (int rh = 0; rh < 2; rh++) {
            float v = psum[pf][rh];
            v += __shfl_xor_sync(0xffffffffu, v, 1);
            v += __shfl_xor_sync(0xffffffffu, v, 2);
            if ((lane & 3) == 0) {
                int p = pgrp*32 + pf*16 + rh*8 + (lane >> 2);
                sums[p*2 + wm] = v;
            }
        }
    __syncthreads();

    if (tid < 128) {
        int pq = pq0 + tid;
        if (pq < NPAIR) {
            float tot = sums[tid*2] + sums[tid*2 + 1] + __ldg(&bb[o]);
            out[(size_t)pq*NREL + o] = tot;
        }
    }
}

// ---------------- launcher ----------------
extern "C" void kernel_launch(void* const* d_in, const int* in_sizes, int n_in,
                              void* d_out, int out_size)
{
    const float* entity  = (const float*)d_in[0];
    const float* w_red   = (const float*)d_in[1];
    const float* w_sim3  = (const float*)d_in[2];
    const float* c1w     = (const float*)d_in[3];
    const float* c1b     = (const float*)d_in[4];
    const float* c2w     = (const float*)d_in[5];
    const float* c2b     = (const float*)d_in[6];
    const float* w_lin   = (const float*)d_in[7];
    const float* b_lin   = (const float*)d_in[8];
    const float* w_s     = (const float*)d_in[9];
    const float* w_o     = (const float*)d_in[10];
    const float* w_bil   = (const float*)d_in[11];
    const float* b_bil   = (const float*)d_in[12];
    float* out = (float*)d_out;

    // idempotent, deterministic — same call every invocation (no static guards)
    cudaFuncSetAttribute(k_final_mma, cudaFuncAttributeMaxDynamicSharedMemorySize,
                         FB_SMEM);

    k_prep<<<(NE*EMBD*EMBD + 255)/256, 256>>>(c1w, c2w, w_sim3);
    k_wsplit<<<dim3(64, NREL), 256>>>(w_bil);

    k_gemm_E<<<dim3((EMBD+63)/64, (NROWS+63)/64), 256>>>(entity, w_red);
    k_norms<<<NROWS, 256>>>();

    k_gemm_T<<<dim3((NE*EMBD)/64, (NROWS+63)/64), 256>>>();

    k_sims<<<dim3(BATCH, NE), 256>>>();
    k_sim3b<<<NROWS, 256>>>();

    k_conv1<<<dim3(BATCH, NE), 256>>>(c1b);
    k_conv2<<<dim3(BATCH, NE, 2), 128>>>(c2b);

    k_gemm_attn<<<dim3(EMBD/64, (NPAIR+63)/64), 256>>>(w_lin, b_lin);
    k_gemm_SO<<<dim3(EMBD/64, (NROWS+63)/64, 2), 256>>>(w_s, w_o);

    k_zszo<<<NPAIR_PAD, 256>>>();

    k_final_mma<<<dim3(NPAIR_PAD/FB_TILE, NREL), 256, FB_SMEM>>>(b_bil, out);
}

// round 7
// speedup vs baseline: 2.3364x; 1.1507x over previous
#include <cuda_runtime.h>
#include <cuda_bf16.h>
#include <cstdint>
#include <math.h>

#define NE    42
#define BATCH 4
#define EMBD  256
#define IN_D  768
#define NREL  97
#define NPIX  (NE*NE)          // 1764
#define NROWS (BATCH*NE)       // 168
#define NPAIR (BATCH*NPIX)     // 7056
#define FB_TILE 128
#define NPAIR_PAD (56*FB_TILE) // 7168

// ---------------- scratch (static device memory; no allocation) ----------------
__device__ float g_e   [NROWS*EMBD];
__device__ float g_norm[NROWS];
__device__ float g_W3  [NE*EMBD*EMBD];
__device__ float g_T   [NROWS*NE*EMBD];
__device__ float g_fm  [BATCH*3*NE*NE];
__device__ float g_w1t [27*EMBD];
__device__ float g_w2t [EMBD*9*EMBD];
__device__ float g_h1  [BATCH*EMBD*NE*NE];
__device__ float g_h2  [BATCH*EMBD*NE*NE];
__device__ float g_attn[NPAIR*EMBD];
__device__ float g_S   [NROWS*EMBD];
__device__ float g_O   [NROWS*EMBD];
__device__ __nv_bfloat16 g_zs_hi[NPAIR_PAD*EMBD];
__device__ __nv_bfloat16 g_zs_lo[NPAIR_PAD*EMBD];
__device__ float         g_zo  [NPAIR_PAD*EMBD];   // [pq][m]
__device__ float         g_zoT [EMBD*NPAIR_PAD];   // [m][pq]
__device__ __nv_bfloat16 g_Wt_hi[NREL*EMBD*EMBD];  // [o][m][n] = W_bil[o][n][m]
__device__ __nv_bfloat16 g_Wt_lo[NREL*EMBD*EMBD];

// ---------------- prep: conv + sim3 weight permutes ----------------
__global__ void k_prep(const float* __restrict__ c1w,
                       const float* __restrict__ c2w,
                       const float* __restrict__ wsim3)
{
    int i = blockIdx.x * 256 + threadIdx.x;
    if (i < 27*EMBD) {
        int oc = i & 255, k = i >> 8;
        g_w1t[i] = c1w[oc*27 + k];
    }
    if (i < EMBD*9*EMBD) {
        int oc = i & 255, r = i >> 8;
        g_w2t[i] = c2w[oc*2304 + r];
    }
    if (i < NE*EMBD*EMBD) {
        int n = i & 255;
        int c = i >> 8;
        int j = c >> 8, m = c & 255;
        g_W3[i] = wsim3[j*65536 + n*256 + m];
    }
}

// ---------------- prep: W_bil transpose + bf16 hi/lo split ----------------
__global__ void __launch_bounds__(256) k_wsplit(const float* __restrict__ wbil)
{
    __shared__ float tile[32][33];
    int o = blockIdx.y;
    int t = blockIdx.x;
    int m0 = (t & 7) * 32, n0 = (t >> 3) * 32;
    int tx = threadIdx.x & 31, ty = threadIdx.x >> 5;
    for (int rr = ty; rr < 32; rr += 8)
        tile[rr][tx] = wbil[(size_t)o*65536 + (n0+rr)*256 + (m0+tx)];
    __syncthreads();
    for (int rr = ty; rr < 32; rr += 8) {
        float v = tile[tx][rr];                 // = w[o][n0+tx][m0+rr]
        __nv_bfloat16 hi = __float2bfloat16(v);
        __nv_bfloat16 lo = __float2bfloat16(v - __bfloat162float(hi));
        size_t di = (size_t)o*65536 + (size_t)(m0+rr)*256 + (n0+tx);
        g_Wt_hi[di] = hi;
        g_Wt_lo[di] = lo;
    }
}

// ---------------- shared tiled SGEMM-NT:  C[M,N] = A[M,K] * W[N,K]^T (+bias) ------
__device__ __forceinline__ void gemm_nt_dev(
    const float* __restrict__ A, const float* __restrict__ W,
    float* __restrict__ C, const float* __restrict__ bias,
    int M, int N, int K, int amode)
{
    __shared__ float As[16][68];
    __shared__ float Bs[16][68];
    const int tid = threadIdx.x;
    const int tx = tid & 15, ty = tid >> 4;
    const int m0 = blockIdx.y * 64, n0 = blockIdx.x * 64;
    float acc[4][4];
#pragma unroll
    for (int i = 0; i < 4; i++)
#pragma unroll
        for (int j = 0; j < 4; j++) acc[i][j] = 0.f;

    for (int k0 = 0; k0 < K; k0 += 16) {
        if (amode == 0) {
            for (int e = tid; e < 1024; e += 256) {
                int kk = e & 15, m = e >> 4;
                int gm = m0 + m;
                As[kk][m] = (gm < M) ? A[gm * K + k0 + kk] : 0.f;
            }
        } else {
            for (int e = tid; e < 1024; e += 256) {
                int kk = e >> 6, m = e & 63;
                int gm = m0 + m;
                float v = 0.f;
                if (gm < M) {
                    int bb  = gm / NPIX;
                    int pix = gm - bb * NPIX;
                    v = A[bb * (EMBD*NPIX) + (k0 + kk) * NPIX + pix];
                }
                As[kk][m] = v;
            }
        }
        for (int e = tid; e < 1024; e += 256) {
            int kk = e & 15, n = e >> 4;
            int gn = n0 + n;
            Bs[kk][n] = (gn < N) ? W[gn * K + k0 + kk] : 0.f;
        }
        __syncthreads();
#pragma unroll
        for (int kk = 0; kk < 16; kk++) {
            float a0 = As[kk][ty*4+0], a1 = As[kk][ty*4+1];
            float a2 = As[kk][ty*4+2], a3 = As[kk][ty*4+3];
            float b0 = Bs[kk][tx*4+0], b1 = Bs[kk][tx*4+1];
            float b2 = Bs[kk][tx*4+2], b3 = Bs[kk][tx*4+3];
            acc[0][0] += a0*b0; acc[0][1] += a0*b1; acc[0][2] += a0*b2; acc[0][3] += a0*b3;
            acc[1][0] += a1*b0; acc[1][1] += a1*b1; acc[1][2] += a1*b2; acc[1][3] += a1*b3;
            acc[2][0] += a2*b0; acc[2][1] += a2*b1; acc[2][2] += a2*b2; acc[2][3] += a2*b3;
            acc[3][0] += a3*b0; acc[3][1] += a3*b1; acc[3][2] += a3*b2; acc[3][3] += a3*b3;
        }
        __syncthreads();
    }
#pragma unroll
    for (int i = 0; i < 4; i++) {
        int gm = m0 + ty*4 + i;
        if (gm >= M) continue;
#pragma unroll
        for (int j = 0; j < 4; j++) {
            int gn = n0 + tx*4 + j;
            if (gn < N)
                C[gm * N + gn] = acc[i][j] + (bias ? bias[gn] : 0.f);
        }
    }
}

__global__ void __launch_bounds__(256) k_gemm_E(const float* __restrict__ ent,
                                                const float* __restrict__ wred)
{ gemm_nt_dev(ent, wred, g_e, nullptr, NROWS, EMBD, IN_D, 0); }

__global__ void __launch_bounds__(256) k_gemm_T()
{ gemm_nt_dev(g_e, g_W3, g_T, nullptr, NROWS, NE*EMBD, EMBD, 0); }

__global__ void __launch_bounds__(256) k_gemm_attn(const float* __restrict__ wlin,
                                                   const float* __restrict__ blin)
{ gemm_nt_dev(g_h2, wlin, g_attn, blin, NPAIR, EMBD, EMBD, 1); }

__global__ void __launch_bounds__(256) k_gemm_SO(const float* __restrict__ ws,
                                                 const float* __restrict__ wo)
{
    if (blockIdx.z == 0)
        gemm_nt_dev(g_e, ws, g_S, nullptr, NROWS, EMBD, EMBD, 0);
    else
        gemm_nt_dev(g_e, wo, g_O, nullptr, NROWS, EMBD, EMBD, 0);
}

// ---------------- norms ----------------
__global__ void k_norms()
{
    int bi = blockIdx.x;
    int tid = threadIdx.x;
    float v = g_e[bi*EMBD + tid];
    float s = v * v;
    __shared__ float red[8];
    for (int off = 16; off; off >>= 1) s += __shfl_down_sync(0xffffffffu, s, off);
    if ((tid & 31) == 0) red[tid >> 5] = s;
    __syncthreads();
    if (tid == 0) {
        float t = 0.f;
#pragma unroll
        for (int i = 0; i < 8; i++) t += red[i];
        g_norm[bi] = sqrtf(t);
    }
}

// ---------------- sim1/sim2 ----------------
__global__ void k_sims()
{
    int b = blockIdx.x, H = blockIdx.y;
    int tid = threadIdx.x, lane = tid & 31, wid = tid >> 5;
    __shared__ float eH[EMBD];
    eH[tid] = g_e[(b*NE + H)*EMBD + tid];
    __syncthreads();
    float nH = fmaxf(g_norm[b*NE + H], 1e-6f);
    for (int Wc = wid; Wc < NE; Wc += 8) {
        const float* eW = &g_e[(b*NE + Wc)*EMBD];
        float s = 0.f;
        for (int k = lane; k < EMBD; k += 32) s += eH[k] * eW[k];
        for (int off = 16; off; off >>= 1) s += __shfl_down_sync(0xffffffffu, s, off);
        if (lane == 0) {
            float nW = fmaxf(g_norm[b*NE + Wc], 1e-6f);
            g_fm[((b*3 + 0)*NE + H)*NE + Wc] = s;
            g_fm[((b*3 + 1)*NE + H)*NE + Wc] = s / (nH * nW);
        }
    }
}

// ---------------- sim3 epilogue ----------------
__global__ void k_sim3b()
{
    int bi = blockIdx.x;
    int tid = threadIdx.x, lane = tid & 31, wid = tid >> 5;
    __shared__ float ev[EMBD];
    ev[tid] = g_e[bi*EMBD + tid];
    __syncthreads();
    int b = bi / NE, r = bi - b*NE;
    for (int j = wid; j < NE; j += 8) {
        const float* Trow = &g_T[bi*(NE*EMBD) + j*EMBD];
        float s = 0.f;
        for (int k = lane; k < EMBD; k += 32) s += Trow[k] * ev[k];
        for (int off = 16; off; off >>= 1) s += __shfl_down_sync(0xffffffffu, s, off);
        if (lane == 0) g_fm[((b*3 + 2)*NE + j)*NE + r] = s;
    }
}

// ---------------- conv1 ----------------
__global__ void __launch_bounds__(256) k_conv1(const float* __restrict__ b1)
{
    int b = blockIdx.x, H = blockIdx.y;
    int oc = threadIdx.x;
    __shared__ float sm[3][3][44];
    for (int idx = threadIdx.x; idx < 396; idx += 256) {
        int ch = idx / 132, rem = idx - ch*132;
        int r = rem / 44, w = rem - r*44;
        int y = H + r - 1, x = w - 1;
        float v = 0.f;
        if (y >= 0 && y < NE && x >= 0 && x < NE)
            v = g_fm[((b*3 + ch)*NE + y)*NE + x];
        sm[ch][r][w] = v;
    }
    __syncthreads();
    float wreg[27];
#pragma unroll
    for (int k = 0; k < 27; k++) wreg[k] = g_w1t[k*EMBD + oc];
    float acc[NE];
    float bias = b1[oc];
#pragma unroll
    for (int W = 0; W < NE; W++) acc[W] = bias;
#pragma unroll
    for (int ch = 0; ch < 3; ch++)
#pragma unroll
    for (int ky = 0; ky < 3; ky++) {
        const float* row = sm[ch][ky];
        float w0 = wreg[(ch*3+ky)*3+0];
        float w1 = wreg[(ch*3+ky)*3+1];
        float w2 = wreg[(ch*3+ky)*3+2];
        float r0 = row[0], r1 = row[1];
#pragma unroll
        for (int W = 0; W < NE; W++) {
            float r2 = row[W + 2];
            acc[W] += w0*r0 + w1*r1 + w2*r2;
            r0 = r1; r1 = r2;
        }
    }
    int base = ((b*EMBD + oc)*NE + H)*NE;
#pragma unroll
    for (int W = 0; W < NE; W++) g_h1[base + W] = fmaxf(acc[W], 0.f);
}

// ---------------- conv2: 256 threads, 2 threads split the 42-wide row ----------
__global__ void __launch_bounds__(256) k_conv2(const float* __restrict__ b2)
{
    int b = blockIdx.x, H = blockIdx.y;
    int half = threadIdx.x >> 7;                   // 0: W 0..20, 1: W 21..41
    int oc = blockIdx.z * 128 + (threadIdx.x & 127);
    __shared__ float sm[32][3][44];
    float acc[21];
    float bias = b2[oc];
#pragma unroll
    for (int W = 0; W < 21; W++) acc[W] = bias;
    for (int ict = 0; ict < 8; ict++) {
        for (int idx = threadIdx.x; idx < 4224; idx += 256) {
            int ic = idx / 132, rem = idx - ic*132;
            int r = rem / 44, w = rem - r*44;
            int y = H + r - 1, x = w - 1;
            float v = 0.f;
            if (y >= 0 && y < NE && x >= 0 && x < NE)
                v = g_h1[((b*EMBD + ict*32 + ic)*NE + y)*NE + x];
            sm[ic][r][w] = v;
        }
        __syncthreads();
        for (int ic = 0; ic < 32; ic++) {
            float w9[9];
#pragma unroll
            for (int k = 0; k < 9; k++)
                w9[k] = g_w2t[((ict*32 + ic)*9 + k)*EMBD + oc];
#pragma unroll
            for (int ky = 0; ky < 3; ky++) {
                const float* row = sm[ic][ky] + half*21;
                float r0 = row[0], r1 = row[1];
#pragma unroll
                for (int W = 0; W < 21; W++) {
                    float r2 = row[W + 2];
                    acc[W] += w9[ky*3+0]*r0 + w9[ky*3+1]*r1 + w9[ky*3+2]*r2;
                    r0 = r1; r1 = r2;
                }
            }
        }
        __syncthreads();
    }
    int base = ((b*EMBD + oc)*NE + H)*NE + half*21;
#pragma unroll
    for (int W = 0; W < 21; W++) g_h2[base + W] = acc[W];
}

// ---------------- zs/zo: tanh + bf16 hi/lo split (padded to 7168 rows) ----------
__global__ void k_zszo()
{
    int pq = blockIdx.x;
    int c  = threadIdx.x;
    float zs = 0.f, zo = 0.f;
    if (pq < NPAIR) {
        int b   = pq / NPIX;
        int rem = pq - b*NPIX;
        int a1  = rem / NE;
        int a2  = rem - a1*NE;
        float a = g_attn[pq*EMBD + c];
        zs = tanhf(g_S[(b*NE + a1)*EMBD + c] + a);
        zo = tanhf(g_O[(b*NE + a2)*EMBD + c] + a);
    }
    __nv_bfloat16 hi = __float2bfloat16(zs);
    __nv_bfloat16 lo = __float2bfloat16(zs - __bfloat162float(hi));
    g_zs_hi[pq*EMBD + c] = hi;
    g_zs_lo[pq*EMBD + c] = lo;
    g_zo  [pq*EMBD + c] = zo;
}

// ---------------- zo transpose: g_zoT[m][pq] = g_zo[pq][m] ----------------
__global__ void __launch_bounds__(256) k_zot()
{
    __shared__ float tile[32][33];
    int pq0 = blockIdx.x * 32;
    int m0  = blockIdx.y * 32;
    int tx = threadIdx.x & 31, ty = threadIdx.x >> 5;
    for (int r = ty; r < 32; r += 8)
        tile[r][tx] = g_zo[(size_t)(pq0 + r)*EMBD + m0 + tx];
    __syncthreads();
    for (int r = ty; r < 32; r += 8)
        g_zoT[(size_t)(m0 + r)*NPAIR_PAD + pq0 + tx] = tile[tx][r];
}

// ======================= final bilinear via mma.sync bf16 ======================
// Per CTA (o, 128-pair tile): D[p,m] = sum_n zs[p,n]*Wt[o][m][n] (3-pass hi/lo,
// separate accumulators per pass), epilogue out[pq,o] = sum_m D[p,m]*zo[p,m]+b[o].
// All staging via cp.async: zs once; W double-buffered; zo per-chunk, waited only
// after the mainloop (latency hidden).
#define FB_ZS_HI   0
#define FB_ZS_LO   67584              // 128 rows * 528 B
#define FB_W       135168             // 2 bufs * 33792 (hi 16896 + lo 16896)
#define FB_WBUF    33792
#define FB_ZO      202752             // 32 m * 528 B = 16896
#define FB_SUMS    219648             // 128 p * 2 * 4 = 1024
#define FB_SMEM    220672
#define FB_RSTR    528                // row stride bytes (zs/W: 264 bf16; zo: 132 f32)

__device__ __forceinline__ void ldm_x4(uint32_t* r, uint32_t addr) {
    asm volatile("ldmatrix.sync.aligned.m8n8.x4.shared.b16 {%0,%1,%2,%3}, [%4];"
                 : "=r"(r[0]), "=r"(r[1]), "=r"(r[2]), "=r"(r[3]) : "r"(addr));
}
__device__ __forceinline__ void mma_bf16(float* c, const uint32_t* a, const uint32_t* b) {
    asm volatile("mma.sync.aligned.m16n8k16.row.col.f32.bf16.bf16.f32 "
                 "{%0,%1,%2,%3}, {%4,%5,%6,%7}, {%8,%9}, {%0,%1,%2,%3};"
                 : "+f"(c[0]), "+f"(c[1]), "+f"(c[2]), "+f"(c[3])
                 : "r"(a[0]), "r"(a[1]), "r"(a[2]), "r"(a[3]), "r"(b[0]), "r"(b[1]));
}
__device__ __forceinline__ uint32_t smem_u32(const void* p) {
    uint32_t a;
    asm("{ .reg .u64 t; cvta.to.shared.u64 t, %1; cvt.u32.u64 %0, t; }" : "=r"(a) : "l"(p));
    return a;
}
__device__ __forceinline__ void cp16(uint32_t dst, const void* src) {
    asm volatile("cp.async.cg.shared.global [%0], [%1], 16;" :: "r"(dst), "l"(src));
}
#define CP_COMMIT() asm volatile("cp.async.commit_group;" ::: "memory")
#define CP_WAIT0()  asm volatile("cp.async.wait_group 0;" ::: "memory")
#define CP_WAIT1()  asm volatile("cp.async.wait_group 1;" ::: "memory")

__global__ void __launch_bounds__(256) k_final_mma(const float* __restrict__ bb,
                                                   float* __restrict__ out)
{
    extern __shared__ char smem[];
    const uint32_t sb = smem_u32(smem);
    const int tid  = threadIdx.x;
    const int lane = tid & 31;
    const int w    = tid >> 5;           // 8 warps
    const int pgrp = w >> 1;             // 0..3  (32 p each)
    const int wm   = w & 1;              // 0..1  (16 m each)
    const int pq0  = blockIdx.x * FB_TILE;
    const int o    = blockIdx.y;

    // ---- stage zs tile (128 x 256 bf16 hi & lo) + W chunk 0 via cp.async ----
    for (int i = tid; i < 128*32; i += 256) {
        int row = i >> 5, c = i & 31;
        uint32_t off = (uint32_t)row * FB_RSTR + (uint32_t)c * 16;
        size_t gsrc = ((size_t)(pq0 + row) * 256 + (size_t)c * 8) * 2;  // bytes
        cp16(sb + FB_ZS_HI + off, (const char*)g_zs_hi + gsrc);
        cp16(sb + FB_ZS_LO + off, (const char*)g_zs_lo + gsrc);
    }
    for (int i = tid; i < 1024; i += 256) {
        int r = i >> 5, c = i & 31;
        uint32_t off = (uint32_t)r * FB_RSTR + (uint32_t)c * 16;
        size_t gsrc = ((size_t)o * 32768 + (size_t)r * 128 + (size_t)c * 4) * 4;
        cp16(sb + FB_W + off,         (const char*)g_Wt_hi + gsrc);
        cp16(sb + FB_W + 16896 + off, (const char*)g_Wt_lo + gsrc);
    }
    CP_COMMIT();

    // A ldmatrix address pieces (per lane): row-within-16 and k-half
    const int a_sub = (((lane >> 3) & 1) << 3) + (lane & 7);   // 0..15
    const int a_kh  = ((lane >> 4) & 1) << 3;                  // 0 or 8
    // B ldmatrix: m-within-16 and k-half
    const int b_sub = (((lane >> 4) & 1) << 3) + (lane & 7);   // 0..15
    const int b_kh  = ((lane >> 3) & 1) << 3;                  // 0 or 8

    float psum[2][2] = {{0.f, 0.f}, {0.f, 0.f}};  // [pf][rowhalf]
    const float* zo_s = (const float*)(smem + FB_ZO);

    for (int mc = 0; mc < 8; mc++) {
        const int cur = mc & 1, nxt = cur ^ 1;
        CP_WAIT0();
        __syncthreads();            // W[mc] (and zs on mc==0) visible; zo buf free

        // group A: zo chunk [32 m x 128 pq] from m-major layout (contiguous rows)
        for (int i = tid; i < 1024; i += 256) {
            int m = i >> 5, c = i & 31;
            uint32_t off = (uint32_t)m * FB_RSTR + (uint32_t)c * 16;
            size_t gsrc = ((size_t)(mc*32 + m) * NPAIR_PAD + pq0) * 4 + (size_t)c * 16;
            cp16(sb + FB_ZO + off, (const char*)g_zoT + gsrc);
        }
        CP_COMMIT();

        // group B: prefetch W[mc+1] (in flight through mainloop AND epilogue)
        if (mc < 7) {
            for (int i = tid; i < 1024; i += 256) {
                int r = i >> 5, c = i & 31;
                uint32_t off = (uint32_t)r * FB_RSTR + (uint32_t)c * 16;
                size_t gsrc = ((size_t)o * 32768 +
                               (size_t)((mc + 1) * 32 + r) * 128 + (size_t)c * 4) * 4;
                cp16(sb + FB_W + nxt*FB_WBUF + off,         (const char*)g_Wt_hi + gsrc);
                cp16(sb + FB_W + nxt*FB_WBUF + 16896 + off, (const char*)g_Wt_lo + gsrc);
            }
            CP_COMMIT();
        }

        // ---- mainloop: 3 independent accumulator sets (12 indep chains/warp) ----
        float acc0[2][2][4], acc1[2][2][4], acc2[2][2][4];
#pragma unroll
        for (int pf = 0; pf < 2; pf++)
#pragma unroll
            for (int mf = 0; mf < 2; mf++)
#pragma unroll
                for (int q = 0; q < 4; q++) {
                    acc0[pf][mf][q] = 0.f; acc1[pf][mf][q] = 0.f; acc2[pf][mf][q] = 0.f;
                }

        const uint32_t wbase = sb + FB_W + cur*FB_WBUF;
#pragma unroll 8
        for (int k0 = 0; k0 < 256; k0 += 16) {
            uint32_t ah[2][4], al[2][4], bh[4], bl[4];
#pragma unroll
            for (int pf = 0; pf < 2; pf++) {
                uint32_t arow = (uint32_t)(pgrp*32 + pf*16 + a_sub);
                uint32_t aoff = arow * FB_RSTR + (uint32_t)(k0 + a_kh) * 2;
                ldm_x4(ah[pf], sb + FB_ZS_HI + aoff);
                ldm_x4(al[pf], sb + FB_ZS_LO + aoff);
            }
            {
                uint32_t brow = (uint32_t)(wm*16 + b_sub);
                uint32_t boff = brow * FB_RSTR + (uint32_t)(k0 + b_kh) * 2;
                ldm_x4(bh, wbase + boff);
                ldm_x4(bl, wbase + 16896 + boff);
            }
#pragma unroll
            for (int pf = 0; pf < 2; pf++)
#pragma unroll
                for (int mf = 0; mf < 2; mf++) {
                    mma_bf16(acc0[pf][mf], ah[pf], bh + mf*2);
                    mma_bf16(acc1[pf][mf], ah[pf], bl + mf*2);
                    mma_bf16(acc2[pf][mf], al[pf], bh + mf*2);
                }
        }

        // ---- wait for zo (group A); W group B may stay in flight ----
        if (mc < 7) { CP_WAIT1(); } else { CP_WAIT0(); }
        __syncthreads();

        // ---- epilogue for this m-chunk: combine passes, dot with zo ----
        const int mbase = wm*16 + (lane & 3)*2;
        const int prow  = (lane >> 2);
#pragma unroll
        for (int pf = 0; pf < 2; pf++) {
            int pl0 = pgrp*32 + pf*16 + prow;
#pragma unroll
            for (int mf = 0; mf < 2; mf++) {
                int ml = mbase + mf*8;
                float d0 = acc0[pf][mf][0] + acc1[pf][mf][0] + acc2[pf][mf][0];
                float d1 = acc0[pf][mf][1] + acc1[pf][mf][1] + acc2[pf][mf][1];
                float d2 = acc0[pf][mf][2] + acc1[pf][mf][2] + acc2[pf][mf][2];
                float d3 = acc0[pf][mf][3] + acc1[pf][mf][3] + acc2[pf][mf][3];
                float z0 = zo_s[ml*132 + pl0];
                float z1 = zo_s[(ml+1)*132 + pl0];
                float z2 = zo_s[ml*132 + pl0 + 8];
                float z3 = zo_s[(ml+1)*132 + pl0 + 8];
                psum[pf][0] += d0*z0 + d1*z1;
                psum[pf][1] += d2*z2 + d3*z3;
            }
        }
    }

    // ---- reduce across the 4 lanes of each quad (different m) ----
    __syncthreads();
    float* sums = (float*)(smem + FB_SUMS);
#pragma unroll
    for (int pf = 0; pf < 2; pf++)
#pragma unroll
        for (int rh = 0; rh < 2; rh++) {
            float v = psum[pf][rh];
            v += __shfl_xor_sync(0xffffffffu, v, 1);
            v += __shfl_xor_sync(0xffffffffu, v, 2);
            if ((lane & 3) == 0) {
                int p = pgrp*32 + pf*16 + rh*8 + (lane >> 2);
                sums[p*2 + wm] = v;
            }
        }
    __syncthreads();

    if (tid < 128) {
        int pq = pq0 + tid;
        if (pq < NPAIR) {
            float tot = sums[tid*2] + sums[tid*2 + 1] + __ldg(&bb[o]);
            out[(size_t)pq*NREL + o] = tot;
        }
    }
}

// ---------------- launcher ----------------
extern "C" void kernel_launch(void* const* d_in, const int* in_sizes, int n_in,
                              void* d_out, int out_size)
{
    const float* entity  = (const float*)d_in[0];
    const float* w_red   = (const float*)d_in[1];
    const float* w_sim3  = (const float*)d_in[2];
    const float* c1w     = (const float*)d_in[3];
    const float* c1b     = (const float*)d_in[4];
    const float* c2w     = (const float*)d_in[5];
    const float* c2b     = (const float*)d_in[6];
    const float* w_lin   = (const float*)d_in[7];
    const float* b_lin   = (const float*)d_in[8];
    const float* w_s     = (const float*)d_in[9];
    const float* w_o     = (const float*)d_in[10];
    const float* w_bil   = (const float*)d_in[11];
    const float* b_bil   = (const float*)d_in[12];
    float* out = (float*)d_out;

    // idempotent, deterministic — same call every invocation (no static guards)
    cudaFuncSetAttribute(k_final_mma, cudaFuncAttributeMaxDynamicSharedMemorySize,
                         FB_SMEM);

    k_prep<<<(NE*EMBD*EMBD + 255)/256, 256>>>(c1w, c2w, w_sim3);
    k_wsplit<<<dim3(64, NREL), 256>>>(w_bil);

    k_gemm_E<<<dim3((EMBD+63)/64, (NROWS+63)/64), 256>>>(entity, w_red);
    k_norms<<<NROWS, 256>>>();

    k_gemm_T<<<dim3((NE*EMBD)/64, (NROWS+63)/64), 256>>>();

    k_sims<<<dim3(BATCH, NE), 256>>>();
    k_sim3b<<<NROWS, 256>>>();

    k_conv1<<<dim3(BATCH, NE), 256>>>(c1b);
    k_conv2<<<dim3(BATCH, NE, 2), 256>>>(c2b);

    k_gemm_attn<<<dim3(EMBD/64, (NPAIR+63)/64), 256>>>(w_lin, b_lin);
    k_gemm_SO<<<dim3(EMBD/64, (NROWS+63)/64, 2), 256>>>(w_s, w_o);

    k_zszo<<<NPAIR_PAD, 256>>>();
    k_zot<<<dim3(NPAIR_PAD/32, EMBD/32), 256>>>();

    k_final_mma<<<dim3(NPAIR_PAD/FB_TILE, NREL), 256, FB_SMEM>>>(b_bil, out);
}

// round 8
// speedup vs baseline: 2.9257x; 1.2522x over previous
#include <cuda_runtime.h>
#include <cuda_bf16.h>
#include <cuda_fp16.h>
#include <cstdint>
#include <math.h>

#define NE    42
#define BATCH 4
#define EMBD  256
#define IN_D  768
#define NREL  97
#define NPIX  (NE*NE)          // 1764
#define NROWS (BATCH*NE)       // 168
#define NPAIR (BATCH*NPIX)     // 7056
#define FB_TILE 256
#define NPAIR_PAD (28*FB_TILE) // 7168

// ---------------- scratch (static device memory; no allocation) ----------------
__device__ float g_e   [NROWS*EMBD];
__device__ float g_norm[NROWS];
__device__ float g_W3  [NE*EMBD*EMBD];
__device__ float g_T   [NROWS*NE*EMBD];
__device__ float g_fm  [BATCH*3*NE*NE];
__device__ float g_w1t [27*EMBD];
__device__ float g_w2t [EMBD*9*EMBD];
__device__ float g_h1  [BATCH*EMBD*NE*NE];
__device__ float g_h2  [BATCH*EMBD*NE*NE];
__device__ float g_attn[NPAIR*EMBD];
__device__ float g_S   [NROWS*EMBD];
__device__ float g_O   [NROWS*EMBD];
__device__ __half g_zs_h[NPAIR_PAD*EMBD];          // fp16 zs
__device__ float  g_zo  [NPAIR_PAD*EMBD];          // [pq][m] fp32 (transpose src)
__device__ __half g_zoT [EMBD*NPAIR_PAD];          // [m][pq] fp16
__device__ __half g_Wt_hi[NREL*EMBD*EMBD];         // [o][m][n] = W_bil[o][n][m]
__device__ __half g_Wt_lo[NREL*EMBD*EMBD];

// ---------------- prep: conv + sim3 weight permutes ----------------
__global__ void k_prep(const float* __restrict__ c1w,
                       const float* __restrict__ c2w,
                       const float* __restrict__ wsim3)
{
    int i = blockIdx.x * 256 + threadIdx.x;
    if (i < 27*EMBD) {
        int oc = i & 255, k = i >> 8;
        g_w1t[i] = c1w[oc*27 + k];
    }
    if (i < EMBD*9*EMBD) {
        int oc = i & 255, r = i >> 8;
        g_w2t[i] = c2w[oc*2304 + r];
    }
    if (i < NE*EMBD*EMBD) {
        int n = i & 255;
        int c = i >> 8;
        int j = c >> 8, m = c & 255;
        g_W3[i] = wsim3[j*65536 + n*256 + m];
    }
}

// ---------------- prep: W_bil transpose + fp16 hi/lo split ----------------
__global__ void __launch_bounds__(256) k_wsplit(const float* __restrict__ wbil)
{
    __shared__ float tile[32][33];
    int o = blockIdx.y;
    int t = blockIdx.x;
    int m0 = (t & 7) * 32, n0 = (t >> 3) * 32;
    int tx = threadIdx.x & 31, ty = threadIdx.x >> 5;
    for (int rr = ty; rr < 32; rr += 8)
        tile[rr][tx] = wbil[(size_t)o*65536 + (n0+rr)*256 + (m0+tx)];
    __syncthreads();
    for (int rr = ty; rr < 32; rr += 8) {
        float v = tile[tx][rr];                 // = w[o][n0+tx][m0+rr]
        __half hi = __float2half(v);
        __half lo = __float2half(v - __half2float(hi));
        size_t di = (size_t)o*65536 + (size_t)(m0+rr)*256 + (n0+tx);
        g_Wt_hi[di] = hi;
        g_Wt_lo[di] = lo;
    }
}

// ---------------- shared tiled SGEMM-NT:  C[M,N] = A[M,K] * W[N,K]^T (+bias) ------
__device__ __forceinline__ void gemm_nt_dev(
    const float* __restrict__ A, const float* __restrict__ W,
    float* __restrict__ C, const float* __restrict__ bias,
    int M, int N, int K, int amode)
{
    __shared__ float As[16][68];
    __shared__ float Bs[16][68];
    const int tid = threadIdx.x;
    const int tx = tid & 15, ty = tid >> 4;
    const int m0 = blockIdx.y * 64, n0 = blockIdx.x * 64;
    float acc[4][4];
#pragma unroll
    for (int i = 0; i < 4; i++)
#pragma unroll
        for (int j = 0; j < 4; j++) acc[i][j] = 0.f;

    for (int k0 = 0; k0 < K; k0 += 16) {
        if (amode == 0) {
            for (int e = tid; e < 1024; e += 256) {
                int kk = e & 15, m = e >> 4;
                int gm = m0 + m;
                As[kk][m] = (gm < M) ? A[gm * K + k0 + kk] : 0.f;
            }
        } else {
            for (int e = tid; e < 1024; e += 256) {
                int kk = e >> 6, m = e & 63;
                int gm = m0 + m;
                float v = 0.f;
                if (gm < M) {
                    int bb  = gm / NPIX;
                    int pix = gm - bb * NPIX;
                    v = A[bb * (EMBD*NPIX) + (k0 + kk) * NPIX + pix];
                }
                As[kk][m] = v;
            }
        }
        for (int e = tid; e < 1024; e += 256) {
            int kk = e & 15, n = e >> 4;
            int gn = n0 + n;
            Bs[kk][n] = (gn < N) ? W[gn * K + k0 + kk] : 0.f;
        }
        __syncthreads();
#pragma unroll
        for (int kk = 0; kk < 16; kk++) {
            float a0 = As[kk][ty*4+0], a1 = As[kk][ty*4+1];
            float a2 = As[kk][ty*4+2], a3 = As[kk][ty*4+3];
            float b0 = Bs[kk][tx*4+0], b1 = Bs[kk][tx*4+1];
            float b2 = Bs[kk][tx*4+2], b3 = Bs[kk][tx*4+3];
            acc[0][0] += a0*b0; acc[0][1] += a0*b1; acc[0][2] += a0*b2; acc[0][3] += a0*b3;
            acc[1][0] += a1*b0; acc[1][1] += a1*b1; acc[1][2] += a1*b2; acc[1][3] += a1*b3;
            acc[2][0] += a2*b0; acc[2][1] += a2*b1; acc[2][2] += a2*b2; acc[2][3] += a2*b3;
            acc[3][0] += a3*b0; acc[3][1] += a3*b1; acc[3][2] += a3*b2; acc[3][3] += a3*b3;
        }
        __syncthreads();
    }
#pragma unroll
    for (int i = 0; i < 4; i++) {
        int gm = m0 + ty*4 + i;
        if (gm >= M) continue;
#pragma unroll
        for (int j = 0; j < 4; j++) {
            int gn = n0 + tx*4 + j;
            if (gn < N)
                C[gm * N + gn] = acc[i][j] + (bias ? bias[gn] : 0.f);
        }
    }
}

__global__ void __launch_bounds__(256) k_gemm_E(const float* __restrict__ ent,
                                                const float* __restrict__ wred)
{ gemm_nt_dev(ent, wred, g_e, nullptr, NROWS, EMBD, IN_D, 0); }

__global__ void __launch_bounds__(256) k_gemm_T()
{ gemm_nt_dev(g_e, g_W3, g_T, nullptr, NROWS, NE*EMBD, EMBD, 0); }

__global__ void __launch_bounds__(256) k_gemm_attn(const float* __restrict__ wlin,
                                                   const float* __restrict__ blin)
{ gemm_nt_dev(g_h2, wlin, g_attn, blin, NPAIR, EMBD, EMBD, 1); }

__global__ void __launch_bounds__(256) k_gemm_SO(const float* __restrict__ ws,
                                                 const float* __restrict__ wo)
{
    if (blockIdx.z == 0)
        gemm_nt_dev(g_e, ws, g_S, nullptr, NROWS, EMBD, EMBD, 0);
    else
        gemm_nt_dev(g_e, wo, g_O, nullptr, NROWS, EMBD, EMBD, 0);
}

// ---------------- norms ----------------
__global__ void k_norms()
{
    int bi = blockIdx.x;
    int tid = threadIdx.x;
    float v = g_e[bi*EMBD + tid];
    float s = v * v;
    __shared__ float red[8];
    for (int off = 16; off; off >>= 1) s += __shfl_down_sync(0xffffffffu, s, off);
    if ((tid & 31) == 0) red[tid >> 5] = s;
    __syncthreads();
    if (tid == 0) {
        float t = 0.f;
#pragma unroll
        for (int i = 0; i < 8; i++) t += red[i];
        g_norm[bi] = sqrtf(t);
    }
}

// ---------------- sim1/sim2 ----------------
__global__ void k_sims()
{
    int b = blockIdx.x, H = blockIdx.y;
    int tid = threadIdx.x, lane = tid & 31, wid = tid >> 5;
    __shared__ float eH[EMBD];
    eH[tid] = g_e[(b*NE + H)*EMBD + tid];
    __syncthreads();
    float nH = fmaxf(g_norm[b*NE + H], 1e-6f);
    for (int Wc = wid; Wc < NE; Wc += 8) {
        const float* eW = &g_e[(b*NE + Wc)*EMBD];
        float s = 0.f;
        for (int k = lane; k < EMBD; k += 32) s += eH[k] * eW[k];
        for (int off = 16; off; off >>= 1) s += __shfl_down_sync(0xffffffffu, s, off);
        if (lane == 0) {
            float nW = fmaxf(g_norm[b*NE + Wc], 1e-6f);
            g_fm[((b*3 + 0)*NE + H)*NE + Wc] = s;
            g_fm[((b*3 + 1)*NE + H)*NE + Wc] = s / (nH * nW);
        }
    }
}

// ---------------- sim3 epilogue ----------------
__global__ void k_sim3b()
{
    int bi = blockIdx.x;
    int tid = threadIdx.x, lane = tid & 31, wid = tid >> 5;
    __shared__ float ev[EMBD];
    ev[tid] = g_e[bi*EMBD + tid];
    __syncthreads();
    int b = bi / NE, r = bi - b*NE;
    for (int j = wid; j < NE; j += 8) {
        const float* Trow = &g_T[bi*(NE*EMBD) + j*EMBD];
        float s = 0.f;
        for (int k = lane; k < EMBD; k += 32) s += Trow[k] * ev[k];
        for (int off = 16; off; off >>= 1) s += __shfl_down_sync(0xffffffffu, s, off);
        if (lane == 0) g_fm[((b*3 + 2)*NE + j)*NE + r] = s;
    }
}

// ---------------- conv1 ----------------
__global__ void __launch_bounds__(256) k_conv1(const float* __restrict__ b1)
{
    int b = blockIdx.x, H = blockIdx.y;
    int oc = threadIdx.x;
    __shared__ float sm[3][3][44];
    for (int idx = threadIdx.x; idx < 396; idx += 256) {
        int ch = idx / 132, rem = idx - ch*132;
        int r = rem / 44, w = rem - r*44;
        int y = H + r - 1, x = w - 1;
        float v = 0.f;
        if (y >= 0 && y < NE && x >= 0 && x < NE)
            v = g_fm[((b*3 + ch)*NE + y)*NE + x];
        sm[ch][r][w] = v;
    }
    __syncthreads();
    float wreg[27];
#pragma unroll
    for (int k = 0; k < 27; k++) wreg[k] = g_w1t[k*EMBD + oc];
    float acc[NE];
    float bias = b1[oc];
#pragma unroll
    for (int W = 0; W < NE; W++) acc[W] = bias;
#pragma unroll
    for (int ch = 0; ch < 3; ch++)
#pragma unroll
    for (int ky = 0; ky < 3; ky++) {
        const float* row = sm[ch][ky];
        float w0 = wreg[(ch*3+ky)*3+0];
        float w1 = wreg[(ch*3+ky)*3+1];
        float w2 = wreg[(ch*3+ky)*3+2];
        float r0 = row[0], r1 = row[1];
#pragma unroll
        for (int W = 0; W < NE; W++) {
            float r2 = row[W + 2];
            acc[W] += w0*r0 + w1*r1 + w2*r2;
            r0 = r1; r1 = r2;
        }
    }
    int base = ((b*EMBD + oc)*NE + H)*NE;
#pragma unroll
    for (int W = 0; W < NE; W++) g_h1[base + W] = fmaxf(acc[W], 0.f);
}

// ---------------- conv2: 256 threads, 2 threads split the 42-wide row ----------
__global__ void __launch_bounds__(256) k_conv2(const float* __restrict__ b2)
{
    int b = blockIdx.x, H = blockIdx.y;
    int half = threadIdx.x >> 7;                   // 0: W 0..20, 1: W 21..41
    int oc = blockIdx.z * 128 + (threadIdx.x & 127);
    __shared__ float sm[32][3][44];
    float acc[21];
    float bias = b2[oc];
#pragma unroll
    for (int W = 0; W < 21; W++) acc[W] = bias;
    for (int ict = 0; ict < 8; ict++) {
        for (int idx = threadIdx.x; idx < 4224; idx += 256) {
            int ic = idx / 132, rem = idx - ic*132;
            int r = rem / 44, w = rem - r*44;
            int y = H + r - 1, x = w - 1;
            float v = 0.f;
            if (y >= 0 && y < NE && x >= 0 && x < NE)
                v = g_h1[((b*EMBD + ict*32 + ic)*NE + y)*NE + x];
            sm[ic][r][w] = v;
        }
        __syncthreads();
        for (int ic = 0; ic < 32; ic++) {
            float w9[9];
#pragma unroll
            for (int k = 0; k < 9; k++)
                w9[k] = g_w2t[((ict*32 + ic)*9 + k)*EMBD + oc];
#pragma unroll
            for (int ky = 0; ky < 3; ky++) {
                const float* row = sm[ic][ky] + half*21;
                float r0 = row[0], r1 = row[1];
#pragma unroll
                for (int W = 0; W < 21; W++) {
                    float r2 = row[W + 2];
                    acc[W] += w9[ky*3+0]*r0 + w9[ky*3+1]*r1 + w9[ky*3+2]*r2;
                    r0 = r1; r1 = r2;
                }
            }
        }
        __syncthreads();
    }
    int base = ((b*EMBD + oc)*NE + H)*NE + half*21;
#pragma unroll
    for (int W = 0; W < 21; W++) g_h2[base + W] = acc[W];
}

// ---------------- zs/zo: tanh + fp16 zs (padded to 7168 rows) ----------
__global__ void k_zszo()
{
    int pq = blockIdx.x;
    int c  = threadIdx.x;
    float zs = 0.f, zo = 0.f;
    if (pq < NPAIR) {
        int b   = pq / NPIX;
        int rem = pq - b*NPIX;
        int a1  = rem / NE;
        int a2  = rem - a1*NE;
        float a = g_attn[pq*EMBD + c];
        zs = tanhf(g_S[(b*NE + a1)*EMBD + c] + a);
        zo = tanhf(g_O[(b*NE + a2)*EMBD + c] + a);
    }
    g_zs_h[pq*EMBD + c] = __float2half(zs);
    g_zo [pq*EMBD + c] = zo;
}

// ---------------- zo transpose: g_zoT[m][pq] = fp16(g_zo[pq][m]) ----------------
__global__ void __launch_bounds__(256) k_zot()
{
    __shared__ float tile[32][33];
    int pq0 = blockIdx.x * 32;
    int m0  = blockIdx.y * 32;
    int tx = threadIdx.x & 31, ty = threadIdx.x >> 5;
    for (int r = ty; r < 32; r += 8)
        tile[r][tx] = g_zo[(size_t)(pq0 + r)*EMBD + m0 + tx];
    __syncthreads();
    for (int r = ty; r < 32; r += 8)
        g_zoT[(size_t)(m0 + r)*NPAIR_PAD + pq0 + tx] = __float2half(tile[tx][r]);
}

// ======================= final bilinear via mma.sync fp16 ======================
// Per CTA (o, 256-pair tile): D[p,m] = sum_n zs[p,n]*(Whi+Wlo)[o][m][n] (2-pass
// fp16 split, separate accumulators), epilogue out = sum_m D[p,m]*zo[p,m]+b[o].
// zs staged once; W hi/lo double-buffered; zo per-chunk, all via cp.async.
#define FB_ZS      0                  // 256 rows * 528 B = 135168
#define FB_W       135168             // 2 bufs * 33792 (hi 16896 + lo 16896)
#define FB_WBUF    33792
#define FB_ZO      202752             // 32 m * 528 B = 16896 (fp16 rows of 256)
#define FB_SUMS    219648             // 256 p * 2 * 4 = 2048
#define FB_SMEM    221696
#define FB_RSTR    528                // row stride bytes (256 fp16 + 16B pad)

__device__ __forceinline__ void ldm_x4(uint32_t* r, uint32_t addr) {
    asm volatile("ldmatrix.sync.aligned.m8n8.x4.shared.b16 {%0,%1,%2,%3}, [%4];"
                 : "=r"(r[0]), "=r"(r[1]), "=r"(r[2]), "=r"(r[3]) : "r"(addr));
}
__device__ __forceinline__ void mma_f16(float* c, const uint32_t* a, const uint32_t* b) {
    asm volatile("mma.sync.aligned.m16n8k16.row.col.f32.f16.f16.f32 "
                 "{%0,%1,%2,%3}, {%4,%5,%6,%7}, {%8,%9}, {%0,%1,%2,%3};"
                 : "+f"(c[0]), "+f"(c[1]), "+f"(c[2]), "+f"(c[3])
                 : "r"(a[0]), "r"(a[1]), "r"(a[2]), "r"(a[3]), "r"(b[0]), "r"(b[1]));
}
__device__ __forceinline__ uint32_t smem_u32(const void* p) {
    uint32_t a;
    asm("{ .reg .u64 t; cvta.to.shared.u64 t, %1; cvt.u32.u64 %0, t; }" : "=r"(a) : "l"(p));
    return a;
}
__device__ __forceinline__ void cp16(uint32_t dst, const void* src) {
    asm volatile("cp.async.cg.shared.global [%0], [%1], 16;" :: "r"(dst), "l"(src));
}
#define CP_COMMIT() asm volatile("cp.async.commit_group;" ::: "memory")
#define CP_WAIT0()  asm volatile("cp.async.wait_group 0;" ::: "memory")
#define CP_WAIT1()  asm volatile("cp.async.wait_group 1;" ::: "memory")

__global__ void __launch_bounds__(256) k_final_mma(const float* __restrict__ bb,
                                                   float* __restrict__ out)
{
    extern __shared__ char smem[];
    const uint32_t sb = smem_u32(smem);
    const int tid  = threadIdx.x;
    const int lane = tid & 31;
    const int w    = tid >> 5;           // 8 warps
    const int pgrp = w >> 1;             // 0..3  (64 p each)
    const int wm   = w & 1;              // 0..1  (16 m each)
    const int pq0  = blockIdx.x * FB_TILE;
    const int o    = blockIdx.y;

    // ---- stage zs tile (256 x 256 fp16) + W chunk 0 (hi & lo) via cp.async ----
    for (int i = tid; i < 256*32; i += 256) {
        int row = i >> 5, c = i & 31;
        uint32_t off = (uint32_t)row * FB_RSTR + (uint32_t)c * 16;
        size_t gsrc = ((size_t)(pq0 + row) * 256 + (size_t)c * 8) * 2;  // bytes
        cp16(sb + FB_ZS + off, (const char*)g_zs_h + gsrc);
    }
    for (int i = tid; i < 1024; i += 256) {
        int r = i >> 5, c = i & 31;
        uint32_t off = (uint32_t)r * FB_RSTR + (uint32_t)c * 16;
        size_t gsrc = ((size_t)o * 65536 + (size_t)r * 256 + (size_t)c * 8) * 2;
        cp16(sb + FB_W + off,         (const char*)g_Wt_hi + gsrc);
        cp16(sb + FB_W + 16896 + off, (const char*)g_Wt_lo + gsrc);
    }
    CP_COMMIT();

    // A ldmatrix address pieces (per lane): row-within-16 and k-half
    const int a_sub = (((lane >> 3) & 1) << 3) + (lane & 7);   // 0..15
    const int a_kh  = ((lane >> 4) & 1) << 3;                  // 0 or 8
    // B ldmatrix: m-within-16 and k-half
    const int b_sub = (((lane >> 4) & 1) << 3) + (lane & 7);   // 0..15
    const int b_kh  = ((lane >> 3) & 1) << 3;                  // 0 or 8

    float psum[4][2];                   // [pf][rowhalf]
#pragma unroll
    for (int pf = 0; pf < 4; pf++) { psum[pf][0] = 0.f; psum[pf][1] = 0.f; }
    const __half* zo_s = (const __half*)(smem + FB_ZO);

    for (int mc = 0; mc < 8; mc++) {
        const int cur = mc & 1, nxt = cur ^ 1;
        CP_WAIT0();
        __syncthreads();            // W[mc] (and zs on mc==0) visible; zo buf free

        // group A: zo chunk [32 m x 256 pq] fp16 (contiguous m-major rows)
        for (int i = tid; i < 1024; i += 256) {
            int m = i >> 5, c = i & 31;
            uint32_t off = (uint32_t)m * FB_RSTR + (uint32_t)c * 16;
            size_t gsrc = ((size_t)(mc*32 + m) * NPAIR_PAD + pq0) * 2 + (size_t)c * 16;
            cp16(sb + FB_ZO + off, (const char*)g_zoT + gsrc);
        }
        CP_COMMIT();

        // group B: prefetch W[mc+1] (in flight through mainloop AND epilogue)
        if (mc < 7) {
            for (int i = tid; i < 1024; i += 256) {
                int r = i >> 5, c = i & 31;
                uint32_t off = (uint32_t)r * FB_RSTR + (uint32_t)c * 16;
                size_t gsrc = ((size_t)o * 65536 +
                               (size_t)((mc + 1) * 32 + r) * 256 + (size_t)c * 8) * 2;
                cp16(sb + FB_W + nxt*FB_WBUF + off,         (const char*)g_Wt_hi + gsrc);
                cp16(sb + FB_W + nxt*FB_WBUF + 16896 + off, (const char*)g_Wt_lo + gsrc);
            }
            CP_COMMIT();
        }

        // ---- mainloop: 2 pass sets x 4 pf x 2 mf = 16 independent chains ----
        float acch[4][2][4], accl[4][2][4];
#pragma unroll
        for (int pf = 0; pf < 4; pf++)
#pragma unroll
            for (int mf = 0; mf < 2; mf++)
#pragma unroll
                for (int q = 0; q < 4; q++) { acch[pf][mf][q] = 0.f; accl[pf][mf][q] = 0.f; }

        const uint32_t wbase = sb + FB_W + cur*FB_WBUF;
#pragma unroll 4
        for (int k0 = 0; k0 < 256; k0 += 16) {
            uint32_t av[4][4], bh[4], bl[4];
#pragma unroll
            for (int pf = 0; pf < 4; pf++) {
                uint32_t arow = (uint32_t)(pgrp*64 + pf*16 + a_sub);
                uint32_t aoff = arow * FB_RSTR + (uint32_t)(k0 + a_kh) * 2;
                ldm_x4(av[pf], sb + FB_ZS + aoff);
            }
            {
                uint32_t brow = (uint32_t)(wm*16 + b_sub);
                uint32_t boff = brow * FB_RSTR + (uint32_t)(k0 + b_kh) * 2;
                ldm_x4(bh, wbase + boff);
                ldm_x4(bl, wbase + 16896 + boff);
            }
#pragma unroll
            for (int pf = 0; pf < 4; pf++)
#pragma unroll
                for (int mf = 0; mf < 2; mf++) {
                    mma_f16(acch[pf][mf], av[pf], bh + mf*2);
                    mma_f16(accl[pf][mf], av[pf], bl + mf*2);
                }
        }

        // ---- wait for zo (group A); W group B may stay in flight ----
        if (mc < 7) { CP_WAIT1(); } else { CP_WAIT0(); }
        __syncthreads();

        // ---- epilogue for this m-chunk: combine passes, dot with zo ----
        const int mbase = wm*16 + (lane & 3)*2;
        const int prow  = (lane >> 2);
#pragma unroll
        for (int pf = 0; pf < 4; pf++) {
            int pl0 = pgrp*64 + pf*16 + prow;
#pragma unroll
            for (int mf = 0; mf < 2; mf++) {
                int ml = mbase + mf*8;
                float d0 = acch[pf][mf][0] + accl[pf][mf][0];
                float d1 = acch[pf][mf][1] + accl[pf][mf][1];
                float d2 = acch[pf][mf][2] + accl[pf][mf][2];
                float d3 = acch[pf][mf][3] + accl[pf][mf][3];
                float z0 = __half2float(zo_s[ml*264 + pl0]);
                float z1 = __half2float(zo_s[(ml+1)*264 + pl0]);
                float z2 = __half2float(zo_s[ml*264 + pl0 + 8]);
                float z3 = __half2float(zo_s[(ml+1)*264 + pl0 + 8]);
                psum[pf][0] += d0*z0 + d1*z1;
                psum[pf][1] += d2*z2 + d3*z3;
            }
        }
    }

    // ---- reduce across the 4 lanes of each quad (different m) ----
    __syncthreads();
    float* sums = (float*)(smem + FB_SUMS);
#pragma unroll
    for (int pf = 0; pf < 4; pf++)
#pragma unroll
        for (int rh = 0; rh < 2; rh++) {
            float v = psum[pf][rh];
            v += __shfl_xor_sync(0xffffffffu, v, 1);
            v += __shfl_xor_sync(0xffffffffu, v, 2);
            if ((lane & 3) == 0) {
                int p = pgrp*64 + pf*16 + rh*8 + (lane >> 2);
                sums[p*2 + wm] = v;
            }
        }
    __syncthreads();

    {
        int pq = pq0 + tid;
        if (pq < NPAIR) {
            float tot = sums[tid*2] + sums[tid*2 + 1] + __ldg(&bb[o]);
            out[(size_t)pq*NREL + o] = tot;
        }
    }
}

// ---------------- launcher ----------------
extern "C" void kernel_launch(void* const* d_in, const int* in_sizes, int n_in,
                              void* d_out, int out_size)
{
    const float* entity  = (const float*)d_in[0];
    const float* w_red   = (const float*)d_in[1];
    const float* w_sim3  = (const float*)d_in[2];
    const float* c1w     = (const float*)d_in[3];
    const float* c1b     = (const float*)d_in[4];
    const float* c2w     = (const float*)d_in[5];
    const float* c2b     = (const float*)d_in[6];
    const float* w_lin   = (const float*)d_in[7];
    const float* b_lin   = (const float*)d_in[8];
    const float* w_s     = (const float*)d_in[9];
    const float* w_o     = (const float*)d_in[10];
    const float* w_bil   = (const float*)d_in[11];
    const float* b_bil   = (const float*)d_in[12];
    float* out = (float*)d_out;

    // idempotent, deterministic — same call every invocation (no static guards)
    cudaFuncSetAttribute(k_final_mma, cudaFuncAttributeMaxDynamicSharedMemorySize,
                         FB_SMEM);

    k_prep<<<(NE*EMBD*EMBD + 255)/256, 256>>>(c1w, c2w, w_sim3);
    k_wsplit<<<dim3(64, NREL), 256>>>(w_bil);

    k_gemm_E<<<dim3((EMBD+63)/64, (NROWS+63)/64), 256>>>(entity, w_red);
    k_norms<<<NROWS, 256>>>();

    k_gemm_T<<<dim3((NE*EMBD)/64, (NROWS+63)/64), 256>>>();

    k_sims<<<dim3(BATCH, NE), 256>>>();
    k_sim3b<<<NROWS, 256>>>();

    k_conv1<<<dim3(BATCH, NE), 256>>>(c1b);
    k_conv2<<<dim3(BATCH, NE, 2), 256>>>(c2b);

    k_gemm_attn<<<dim3(EMBD/64, (NPAIR+63)/64), 256>>>(w_lin, b_lin);
    k_gemm_SO<<<dim3(EMBD/64, (NROWS+63)/64, 2), 256>>>(w_s, w_o);

    k_zszo<<<NPAIR_PAD, 256>>>();
    k_zot<<<dim3(NPAIR_PAD/32, EMBD/32), 256>>>();

    k_final_mma<<<dim3(NPAIR_PAD/FB_TILE, NREL), 256, FB_SMEM>>>(b_bil, out);
}

// round 10
// speedup vs baseline: 3.6717x; 1.2550x over previous
#include <cuda_runtime.h>
#include <cuda_fp16.h>
#include <cstdint>
#include <math.h>

#define NE    42
#define BATCH 4
#define EMBD  256
#define IN_D  768
#define NREL  97
#define NPIX  (NE*NE)          // 1764
#define NROWS (BATCH*NE)       // 168
#define NPAIR (BATCH*NPIX)     // 7056
#define FB_TILE 256
#define NPAIR_PAD (28*FB_TILE) // 7168
#define K2    2304             // conv2 GEMM K = 256*9

// ---------------- scratch (static device memory; no allocation) ----------------
__device__ float g_e   [NROWS*EMBD];
__device__ float g_norm[NROWS];
__device__ float g_W3  [NE*EMBD*EMBD];
__device__ float g_T   [NROWS*NE*EMBD];
__device__ float g_fm  [BATCH*3*NE*NE];
__device__ float g_w1t [27*EMBD];
__device__ float g_h1  [BATCH*EMBD*NE*NE];
__device__ float g_h2p [NPAIR_PAD*EMBD];           // conv2 out [pq][oc]
__device__ float g_attn[NPAIR*EMBD];
__device__ float g_S   [NROWS*EMBD];
__device__ float g_O   [NROWS*EMBD];
__device__ __half g_w2h[EMBD*K2];                  // conv2 weights fp16 hi
__device__ __half g_w2l[EMBD*K2];                  // conv2 weights fp16 lo
__device__ __half g_x2h[NPAIR_PAD*K2];             // im2col fp16 hi
__device__ __half g_x2l[NPAIR_PAD*K2];             // im2col fp16 lo
__device__ __half g_zs_h[NPAIR_PAD*EMBD];          // fp16 zs
__device__ float  g_zo  [NPAIR_PAD*EMBD];          // [pq][m] fp32 (transpose src)
__device__ __half g_zoT [EMBD*NPAIR_PAD];          // [m][pq] fp16
__device__ __half g_Wt_hi[NREL*EMBD*EMBD];         // [o][m][n] = W_bil[o][n][m]
__device__ __half g_Wt_lo[NREL*EMBD*EMBD];

// ---------------- common helpers ----------------
__device__ __forceinline__ void ldm_x4(uint32_t* r, uint32_t addr) {
    asm volatile("ldmatrix.sync.aligned.m8n8.x4.shared.b16 {%0,%1,%2,%3}, [%4];"
                 : "=r"(r[0]), "=r"(r[1]), "=r"(r[2]), "=r"(r[3]) : "r"(addr));
}
__device__ __forceinline__ void mma_f16(float* c, const uint32_t* a, const uint32_t* b) {
    asm volatile("mma.sync.aligned.m16n8k16.row.col.f32.f16.f16.f32 "
                 "{%0,%1,%2,%3}, {%4,%5,%6,%7}, {%8,%9}, {%0,%1,%2,%3};"
                 : "+f"(c[0]), "+f"(c[1]), "+f"(c[2]), "+f"(c[3])
                 : "r"(a[0]), "r"(a[1]), "r"(a[2]), "r"(a[3]), "r"(b[0]), "r"(b[1]));
}
__device__ __forceinline__ uint32_t smem_u32(const void* p) {
    uint32_t a;
    asm("{ .reg .u64 t; cvta.to.shared.u64 t, %1; cvt.u32.u64 %0, t; }" : "=r"(a) : "l"(p));
    return a;
}
__device__ __forceinline__ void cp16(uint32_t dst, const void* src) {
    asm volatile("cp.async.cg.shared.global [%0], [%1], 16;" :: "r"(dst), "l"(src));
}
#define CP_COMMIT() asm volatile("cp.async.commit_group;" ::: "memory")
#define CP_WAIT0()  asm volatile("cp.async.wait_group 0;" ::: "memory")
#define CP_WAIT1()  asm volatile("cp.async.wait_group 1;" ::: "memory")

// ---------------- prep: conv1/sim3 permutes + conv2 fp16 split ----------------
__global__ void k_prep(const float* __restrict__ c1w,
                       const float* __restrict__ c2w,
                       const float* __restrict__ wsim3)
{
    int i = blockIdx.x * 256 + threadIdx.x;
    if (i < 27*EMBD) {
        int oc = i & 255, k = i >> 8;
        g_w1t[i] = c1w[oc*27 + k];
    }
    if (i < EMBD*K2) {                        // same layout, just split
        float v = c2w[i];
        __half hi = __float2half(v);
        g_w2h[i] = hi;
        g_w2l[i] = __float2half(v - __half2float(hi));
    }
    if (i < NE*EMBD*EMBD) {
        int n = i & 255;
        int c = i >> 8;
        int j = c >> 8, m = c & 255;
        g_W3[i] = wsim3[j*65536 + n*256 + m];
    }
}

// ---------------- prep: W_bil transpose + fp16 hi/lo split ----------------
__global__ void __launch_bounds__(256) k_wsplit(const float* __restrict__ wbil)
{
    __shared__ float tile[32][33];
    int o = blockIdx.y;
    int t = blockIdx.x;
    int m0 = (t & 7) * 32, n0 = (t >> 3) * 32;
    int tx = threadIdx.x & 31, ty = threadIdx.x >> 5;
    for (int rr = ty; rr < 32; rr += 8)
        tile[rr][tx] = wbil[(size_t)o*65536 + (n0+rr)*256 + (m0+tx)];
    __syncthreads();
    for (int rr = ty; rr < 32; rr += 8) {
        float v = tile[tx][rr];                 // = w[o][n0+tx][m0+rr]
        __half hi = __float2half(v);
        __half lo = __float2half(v - __half2float(hi));
        size_t di = (size_t)o*65536 + (size_t)(m0+rr)*256 + (n0+tx);
        g_Wt_hi[di] = hi;
        g_Wt_lo[di] = lo;
    }
}

// ---------------- shared tiled SGEMM-NT:  C[M,N] = A[M,K] * W[N,K]^T (+bias) ------
__device__ __forceinline__ void gemm_nt_dev(
    const float* __restrict__ A, const float* __restrict__ W,
    float* __restrict__ C, const float* __restrict__ bias,
    int M, int N, int K)
{
    __shared__ float As[16][68];
    __shared__ float Bs[16][68];
    const int tid = threadIdx.x;
    const int tx = tid & 15, ty = tid >> 4;
    const int m0 = blockIdx.y * 64, n0 = blockIdx.x * 64;
    float acc[4][4];
#pragma unroll
    for (int i = 0; i < 4; i++)
#pragma unroll
        for (int j = 0; j < 4; j++) acc[i][j] = 0.f;

    for (int k0 = 0; k0 < K; k0 += 16) {
        for (int e = tid; e < 1024; e += 256) {
            int kk = e & 15, m = e >> 4;
            int gm = m0 + m;
            As[kk][m] = (gm < M) ? A[gm * K + k0 + kk] : 0.f;
        }
        for (int e = tid; e < 1024; e += 256) {
            int kk = e & 15, n = e >> 4;
            int gn = n0 + n;
            Bs[kk][n] = (gn < N) ? W[gn * K + k0 + kk] : 0.f;
        }
        __syncthreads();
#pragma unroll
        for (int kk = 0; kk < 16; kk++) {
            float a0 = As[kk][ty*4+0], a1 = As[kk][ty*4+1];
            float a2 = As[kk][ty*4+2], a3 = As[kk][ty*4+3];
            float b0 = Bs[kk][tx*4+0], b1 = Bs[kk][tx*4+1];
            float b2 = Bs[kk][tx*4+2], b3 = Bs[kk][tx*4+3];
            acc[0][0] += a0*b0; acc[0][1] += a0*b1; acc[0][2] += a0*b2; acc[0][3] += a0*b3;
            acc[1][0] += a1*b0; acc[1][1] += a1*b1; acc[1][2] += a1*b2; acc[1][3] += a1*b3;
            acc[2][0] += a2*b0; acc[2][1] += a2*b1; acc[2][2] += a2*b2; acc[2][3] += a2*b3;
            acc[3][0] += a3*b0; acc[3][1] += a3*b1; acc[3][2] += a3*b2; acc[3][3] += a3*b3;
        }
        __syncthreads();
    }
#pragma unroll
    for (int i = 0; i < 4; i++) {
        int gm = m0 + ty*4 + i;
        if (gm >= M) continue;
#pragma unroll
        for (int j = 0; j < 4; j++) {
            int gn = n0 + tx*4 + j;
            if (gn < N)
                C[gm * N + gn] = acc[i][j] + (bias ? bias[gn] : 0.f);
        }
    }
}

__global__ void __launch_bounds__(256) k_gemm_E(const float* __restrict__ ent,
                                                const float* __restrict__ wred)
{ gemm_nt_dev(ent, wred, g_e, nullptr, NROWS, EMBD, IN_D); }

__global__ void __launch_bounds__(256) k_gemm_T()
{ gemm_nt_dev(g_e, g_W3, g_T, nullptr, NROWS, NE*EMBD, EMBD); }

__global__ void __launch_bounds__(256) k_gemm_attn(const float* __restrict__ wlin,
                                                   const float* __restrict__ blin)
{ gemm_nt_dev(g_h2p, wlin, g_attn, blin, NPAIR, EMBD, EMBD); }

__global__ void __launch_bounds__(256) k_gemm_SO(const float* __restrict__ ws,
                                                 const float* __restrict__ wo)
{
    if (blockIdx.z == 0)
        gemm_nt_dev(g_e, ws, g_S, nullptr, NROWS, EMBD, EMBD);
    else
        gemm_nt_dev(g_e, wo, g_O, nullptr, NROWS, EMBD, EMBD);
}

// ---------------- norms ----------------
__global__ void k_norms()
{
    int bi = blockIdx.x;
    int tid = threadIdx.x;
    float v = g_e[bi*EMBD + tid];
    float s = v * v;
    __shared__ float red[8];
    for (int off = 16; off; off >>= 1) s += __shfl_down_sync(0xffffffffu, s, off);
    if ((tid & 31) == 0) red[tid >> 5] = s;
    __syncthreads();
    if (tid == 0) {
        float t = 0.f;
#pragma unroll
        for (int i = 0; i < 8; i++) t += red[i];
        g_norm[bi] = sqrtf(t);
    }
}

// ---------------- sim1/sim2 ----------------
__global__ void k_sims()
{
    int b = blockIdx.x, H = blockIdx.y;
    int tid = threadIdx.x, lane = tid & 31, wid = tid >> 5;
    __shared__ float eH[EMBD];
    eH[tid] = g_e[(b*NE + H)*EMBD + tid];
    __syncthreads();
    float nH = fmaxf(g_norm[b*NE + H], 1e-6f);
    for (int Wc = wid; Wc < NE; Wc += 8) {
        const float* eW = &g_e[(b*NE + Wc)*EMBD];
        float s = 0.f;
        for (int k = lane; k < EMBD; k += 32) s += eH[k] * eW[k];
        for (int off = 16; off; off >>= 1) s += __shfl_down_sync(0xffffffffu, s, off);
        if (lane == 0) {
            float nW = fmaxf(g_norm[b*NE + Wc], 1e-6f);
            g_fm[((b*3 + 0)*NE + H)*NE + Wc] = s;
            g_fm[((b*3 + 1)*NE + H)*NE + Wc] = s / (nH * nW);
        }
    }
}

// ---------------- sim3 epilogue ----------------
__global__ void k_sim3b()
{
    int bi = blockIdx.x;
    int tid = threadIdx.x, lane = tid & 31, wid = tid >> 5;
    __shared__ float ev[EMBD];
    ev[tid] = g_e[bi*EMBD + tid];
    __syncthreads();
    int b = bi / NE, r = bi - b*NE;
    for (int j = wid; j < NE; j += 8) {
        const float* Trow = &g_T[bi*(NE*EMBD) + j*EMBD];
        float s = 0.f;
        for (int k = lane; k < EMBD; k += 32) s += Trow[k] * ev[k];
        for (int off = 16; off; off >>= 1) s += __shfl_down_sync(0xffffffffu, s, off);
        if (lane == 0) g_fm[((b*3 + 2)*NE + j)*NE + r] = s;
    }
}

// ---------------- conv1 ----------------
__global__ void __launch_bounds__(256) k_conv1(const float* __restrict__ b1)
{
    int b = blockIdx.x, H = blockIdx.y;
    int oc = threadIdx.x;
    __shared__ float sm[3][3][44];
    for (int idx = threadIdx.x; idx < 396; idx += 256) {
        int ch = idx / 132, rem = idx - ch*132;
        int r = rem / 44, w = rem - r*44;
        int y = H + r - 1, x = w - 1;
        float v = 0.f;
        if (y >= 0 && y < NE && x >= 0 && x < NE)
            v = g_fm[((b*3 + ch)*NE + y)*NE + x];
        sm[ch][r][w] = v;
    }
    __syncthreads();
    float wreg[27];
#pragma unroll
    for (int k = 0; k < 27; k++) wreg[k] = g_w1t[k*EMBD + oc];
    float acc[NE];
    float bias = b1[oc];
#pragma unroll
    for (int W = 0; W < NE; W++) acc[W] = bias;
#pragma unroll
    for (int ch = 0; ch < 3; ch++)
#pragma unroll
    for (int ky = 0; ky < 3; ky++) {
        const float* row = sm[ch][ky];
        float w0 = wreg[(ch*3+ky)*3+0];
        float w1 = wreg[(ch*3+ky)*3+1];
        float w2 = wreg[(ch*3+ky)*3+2];
        float r0 = row[0], r1 = row[1];
#pragma unroll
        for (int W = 0; W < NE; W++) {
            float r2 = row[W + 2];
            acc[W] += w0*r0 + w1*r1 + w2*r2;
            r0 = r1; r1 = r2;
        }
    }
    int base = ((b*EMBD + oc)*NE + H)*NE;
#pragma unroll
    for (int W = 0; W < NE; W++) g_h1[base + W] = fmaxf(acc[W], 0.f);
}

// ---------------- im2col: X[pq][(ic)*9+k] = h1[b][ic][H+dy-1][W+dx-1] -------------
// grid (BATCH, 42, 8 ic-groups); block 256. fp16 hi/lo exact split.
__global__ void __launch_bounds__(256) k_im2col()
{
    int b = blockIdx.x, H = blockIdx.y, icg = blockIdx.z;
    __shared__ float sm[32][3][44];
    for (int idx = threadIdx.x; idx < 4224; idx += 256) {
        int ic = idx / 132, rem = idx - ic*132;
        int r = rem / 44, w = rem - r*44;
        int y = H + r - 1, x = w - 1;
        float v = 0.f;
        if (y >= 0 && y < NE && x >= 0 && x < NE)
            v = g_h1[((b*EMBD + icg*32 + ic)*NE + y)*NE + x];
        sm[ic][r][w] = v;
    }
    __syncthreads();
    // 42 W x 32 ic x 9 k = 12096 entries
    for (int idx = threadIdx.x; idx < 42*288; idx += 256) {
        int W = idx / 288, rem = idx - W*288;
        int ic = rem / 9, k = rem - ic*9;
        int dy = k / 3, dx = k - dy*3;
        float v = sm[ic][dy][W + dx];
        __half hi = __float2half(v);
        __half lo = __float2half(v - __half2float(hi));
        size_t di = (size_t)(b*NPIX + H*NE + W) * K2 + (size_t)(icg*32 + ic)*9 + k;
        g_x2h[di] = hi;
        g_x2l[di] = lo;
    }
}

// ---------------- conv2 GEMM: h2p[pq][oc] = X @ W2^T + b2 (3-pass fp16) ----------
// grid (56, 4): tile 128 pq x 64 oc; K=2304 in 36 chunks of 64, double-buffered.
// Pipeline per chunk kc: [issue prefetch kc+1, COMMIT] -> WAIT1 (chunk kc landed)
// -> sync -> MMA(chunk kc) -> sync (retire buffer before it is overwritten).
#define C2_XH   0
#define C2_XL   18432              // 128 rows * 144 B
#define C2_WH   36864              // 64 rows * 144 B
#define C2_WL   46080
#define C2_BUF  55296
#define C2_SMEM (2*C2_BUF)         // 110592
#define C2_RSTR 144

__global__ void __launch_bounds__(256) k_c2g(const float* __restrict__ b2)
{
    extern __shared__ char smem[];
    const uint32_t sb = smem_u32(smem);
    const int tid  = threadIdx.x;
    const int lane = tid & 31;
    const int w    = tid >> 5;
    const int pgrp = w >> 1;             // 0..3 (32 pq each)
    const int wn   = w & 1;              // 0..1 (32 oc each)
    const int pq0  = blockIdx.x * 128;
    const int oc0  = blockIdx.y * 64;

    const int a_sub = (((lane >> 3) & 1) << 3) + (lane & 7);
    const int a_kh  = ((lane >> 4) & 1) << 3;
    const int b_sub = (((lane >> 4) & 1) << 3) + (lane & 7);
    const int b_kh  = ((lane >> 3) & 1) << 3;

    // prefetch chunk 0 into buffer 0
    {
        const uint32_t base = sb;
        for (int i = tid; i < 1024; i += 256) {       // X: 128 rows x 8 cp16
            int r = i >> 3, c = i & 7;
            uint32_t off = (uint32_t)r * C2_RSTR + (uint32_t)c * 16;
            size_t gsrc = ((size_t)(pq0 + r) * K2 + (size_t)c * 8) * 2;
            cp16(base + C2_XH + off, (const char*)g_x2h + gsrc);
            cp16(base + C2_XL + off, (const char*)g_x2l + gsrc);
        }
        for (int i = tid; i < 512; i += 256) {        // W: 64 rows x 8 cp16
            int r = i >> 3, c = i & 7;
            uint32_t off = (uint32_t)r * C2_RSTR + (uint32_t)c * 16;
            size_t gsrc = ((size_t)(oc0 + r) * K2 + (size_t)c * 8) * 2;
            cp16(base + C2_WH + off, (const char*)g_w2h + gsrc);
            cp16(base + C2_WL + off, (const char*)g_w2l + gsrc);
        }
        CP_COMMIT();
    }

    float acc[2][4][4];
#pragma unroll
    for (int pf = 0; pf < 2; pf++)
#pragma unroll
        for (int nf = 0; nf < 4; nf++)
#pragma unroll
            for (int q = 0; q < 4; q++) acc[pf][nf][q] = 0.f;

    for (int kc = 0; kc < 36; kc++) {
        const uint32_t cbase = sb + (kc & 1) * C2_BUF;

        // issue prefetch for chunk kc+1 into the other buffer (retired by the
        // trailing __syncthreads of iteration kc-1), THEN wait for chunk kc.
        if (kc < 35) {
            const uint32_t nbase = sb + ((kc + 1) & 1) * C2_BUF;
            int koff = (kc + 1) * 64;
            for (int i = tid; i < 1024; i += 256) {
                int r = i >> 3, c = i & 7;
                uint32_t off = (uint32_t)r * C2_RSTR + (uint32_t)c * 16;
                size_t gsrc = ((size_t)(pq0 + r) * K2 + koff + (size_t)c * 8) * 2;
                cp16(nbase + C2_XH + off, (const char*)g_x2h + gsrc);
                cp16(nbase + C2_XL + off, (const char*)g_x2l + gsrc);
            }
            for (int i = tid; i < 512; i += 256) {
                int r = i >> 3, c = i & 7;
                uint32_t off = (uint32_t)r * C2_RSTR + (uint32_t)c * 16;
                size_t gsrc = ((size_t)(oc0 + r) * K2 + koff + (size_t)c * 8) * 2;
                cp16(nbase + C2_WH + off, (const char*)g_w2h + gsrc);
                cp16(nbase + C2_WL + off, (const char*)g_w2l + gsrc);
            }
            CP_COMMIT();
            CP_WAIT1();            // chunk kc complete; kc+1 still in flight
        } else {
            CP_WAIT0();            // last chunk: wait everything
        }
        __syncthreads();

#pragma unroll
        for (int k0 = 0; k0 < 64; k0 += 16) {
            uint32_t ah[2][4], al[2][4], bh[2][4], bl[2][4];
#pragma unroll
            for (int pf = 0; pf < 2; pf++) {
                uint32_t arow = (uint32_t)(pgrp*32 + pf*16 + a_sub);
                uint32_t aoff = arow * C2_RSTR + (uint32_t)(k0 + a_kh) * 2;
                ldm_x4(ah[pf], cbase + C2_XH + aoff);
                ldm_x4(al[pf], cbase + C2_XL + aoff);
            }
#pragma unroll
            for (int bn = 0; bn < 2; bn++) {
                uint32_t brow = (uint32_t)(wn*32 + bn*16 + b_sub);
                uint32_t boff = brow * C2_RSTR + (uint32_t)(k0 + b_kh) * 2;
                ldm_x4(bh[bn], cbase + C2_WH + boff);
                ldm_x4(bl[bn], cbase + C2_WL + boff);
            }
#pragma unroll
            for (int pf = 0; pf < 2; pf++)
#pragma unroll
                for (int bn = 0; bn < 2; bn++)
#pragma unroll
                    for (int j = 0; j < 2; j++) {
                        mma_f16(acc[pf][bn*2+j], ah[pf], bh[bn] + j*2);
                        mma_f16(acc[pf][bn*2+j], ah[pf], bl[bn] + j*2);
                        mma_f16(acc[pf][bn*2+j], al[pf], bh[bn] + j*2);
                    }
        }
        __syncthreads();           // retire cbase before it is overwritten
    }

    // epilogue: write h2p[pq][oc] + bias
    const int prow = lane >> 2;
#pragma unroll
    for (int pf = 0; pf < 2; pf++) {
        int p0 = pq0 + pgrp*32 + pf*16 + prow;
#pragma unroll
        for (int nf = 0; nf < 4; nf++) {
            int col = oc0 + wn*32 + nf*8 + (lane & 3)*2;
            float bias0 = __ldg(&b2[col]);
            float bias1 = __ldg(&b2[col + 1]);
            g_h2p[(size_t)p0*EMBD + col]       = acc[pf][nf][0] + bias0;
            g_h2p[(size_t)p0*EMBD + col + 1]   = acc[pf][nf][1] + bias1;
            g_h2p[(size_t)(p0+8)*EMBD + col]   = acc[pf][nf][2] + bias0;
            g_h2p[(size_t)(p0+8)*EMBD + col+1] = acc[pf][nf][3] + bias1;
        }
    }
}

// ---------------- zs/zo: tanh + fp16 zs (padded to 7168 rows) ----------
__global__ void k_zszo()
{
    int pq = blockIdx.x;
    int c  = threadIdx.x;
    float zs = 0.f, zo = 0.f;
    if (pq < NPAIR) {
        int b   = pq / NPIX;
        int rem = pq - b*NPIX;
        int a1  = rem / NE;
        int a2  = rem - a1*NE;
        float a = g_attn[pq*EMBD + c];
        zs = tanhf(g_S[(b*NE + a1)*EMBD + c] + a);
        zo = tanhf(g_O[(b*NE + a2)*EMBD + c] + a);
    }
    g_zs_h[pq*EMBD + c] = __float2half(zs);
    g_zo [pq*EMBD + c] = zo;
}

// ---------------- zo transpose: g_zoT[m][pq] = fp16(g_zo[pq][m]) ----------------
__global__ void __launch_bounds__(256) k_zot()
{
    __shared__ float tile[32][33];
    int pq0 = blockIdx.x * 32;
    int m0  = blockIdx.y * 32;
    int tx = threadIdx.x & 31, ty = threadIdx.x >> 5;
    for (int r = ty; r < 32; r += 8)
        tile[r][tx] = g_zo[(size_t)(pq0 + r)*EMBD + m0 + tx];
    __syncthreads();
    for (int r = ty; r < 32; r += 8)
        g_zoT[(size_t)(m0 + r)*NPAIR_PAD + pq0 + tx] = __float2half(tile[tx][r]);
}

// ======================= final bilinear via mma.sync fp16 ======================
#define FB_ZS      0                  // 256 rows * 528 B = 135168
#define FB_W       135168             // 2 bufs * 33792 (hi 16896 + lo 16896)
#define FB_WBUF    33792
#define FB_ZO      202752             // 32 m * 528 B = 16896 (fp16 rows of 256)
#define FB_SUMS    219648             // 256 p * 2 * 4 = 2048
#define FB_SMEM    221696
#define FB_RSTR    528

__global__ void __launch_bounds__(256) k_final_mma(const float* __restrict__ bb,
                                                   float* __restrict__ out)
{
    extern __shared__ char smem[];
    const uint32_t sb = smem_u32(smem);
    const int tid  = threadIdx.x;
    const int lane = tid & 31;
    const int w    = tid >> 5;           // 8 warps
    const int pgrp = w >> 1;             // 0..3  (64 p each)
    const int wm   = w & 1;              // 0..1  (16 m each)
    const int pq0  = blockIdx.x * FB_TILE;
    const int o    = blockIdx.y;

    for (int i = tid; i < 256*32; i += 256) {
        int row = i >> 5, c = i & 31;
        uint32_t off = (uint32_t)row * FB_RSTR + (uint32_t)c * 16;
        size_t gsrc = ((size_t)(pq0 + row) * 256 + (size_t)c * 8) * 2;
        cp16(sb + FB_ZS + off, (const char*)g_zs_h + gsrc);
    }
    for (int i = tid; i < 1024; i += 256) {
        int r = i >> 5, c = i & 31;
        uint32_t off = (uint32_t)r * FB_RSTR + (uint32_t)c * 16;
        size_t gsrc = ((size_t)o * 65536 + (size_t)r * 256 + (size_t)c * 8) * 2;
        cp16(sb + FB_W + off,         (const char*)g_Wt_hi + gsrc);
        cp16(sb + FB_W + 16896 + off, (const char*)g_Wt_lo + gsrc);
    }
    CP_COMMIT();

    const int a_sub = (((lane >> 3) & 1) << 3) + (lane & 7);
    const int a_kh  = ((lane >> 4) & 1) << 3;
    const int b_sub = (((lane >> 4) & 1) << 3) + (lane & 7);
    const int b_kh  = ((lane >> 3) & 1) << 3;

    float psum[4][2];
#pragma unroll
    for (int pf = 0; pf < 4; pf++) { psum[pf][0] = 0.f; psum[pf][1] = 0.f; }
    const __half* zo_s = (const __half*)(smem + FB_ZO);

    for (int mc = 0; mc < 8; mc++) {
        const int cur = mc & 1, nxt = cur ^ 1;
        CP_WAIT0();
        __syncthreads();

        for (int i = tid; i < 1024; i += 256) {
            int m = i >> 5, c = i & 31;
            uint32_t off = (uint32_t)m * FB_RSTR + (uint32_t)c * 16;
            size_t gsrc = ((size_t)(mc*32 + m) * NPAIR_PAD + pq0) * 2 + (size_t)c * 16;
            cp16(sb + FB_ZO + off, (const char*)g_zoT + gsrc);
        }
        CP_COMMIT();

        if (mc < 7) {
            for (int i = tid; i < 1024; i += 256) {
                int r = i >> 5, c = i & 31;
                uint32_t off = (uint32_t)r * FB_RSTR + (uint32_t)c * 16;
                size_t gsrc = ((size_t)o * 65536 +
                               (size_t)((mc + 1) * 32 + r) * 256 + (size_t)c * 8) * 2;
                cp16(sb + FB_W + nxt*FB_WBUF + off,         (const char*)g_Wt_hi + gsrc);
                cp16(sb + FB_W + nxt*FB_WBUF + 16896 + off, (const char*)g_Wt_lo + gsrc);
            }
            CP_COMMIT();
        }

        float acch[4][2][4], accl[4][2][4];
#pragma unroll
        for (int pf = 0; pf < 4; pf++)
#pragma unroll
            for (int mf = 0; mf < 2; mf++)
#pragma unroll
                for (int q = 0; q < 4; q++) { acch[pf][mf][q] = 0.f; accl[pf][mf][q] = 0.f; }

        const uint32_t wbase = sb + FB_W + cur*FB_WBUF;
#pragma unroll 4
        for (int k0 = 0; k0 < 256; k0 += 16) {
            uint32_t av[4][4], bh[4], bl[4];
#pragma unroll
            for (int pf = 0; pf < 4; pf++) {
                uint32_t arow = (uint32_t)(pgrp*64 + pf*16 + a_sub);
                uint32_t aoff = arow * FB_RSTR + (uint32_t)(k0 + a_kh) * 2;
                ldm_x4(av[pf], sb + FB_ZS + aoff);
            }
            {
                uint32_t brow = (uint32_t)(wm*16 + b_sub);
                uint32_t boff = brow * FB_RSTR + (uint32_t)(k0 + b_kh) * 2;
                ldm_x4(bh, wbase + boff);
                ldm_x4(bl, wbase + 16896 + boff);
            }
#pragma unroll
            for (int pf = 0; pf < 4; pf++)
#pragma unroll
                for (int mf = 0; mf < 2; mf++) {
                    mma_f16(acch[pf][mf], av[pf], bh + mf*2);
                    mma_f16(accl[pf][mf], av[pf], bl + mf*2);
                }
        }

        if (mc < 7) { CP_WAIT1(); } else { CP_WAIT0(); }
        __syncthreads();

        const int mbase = wm*16 + (lane & 3)*2;
        const int prow  = (lane >> 2);
#pragma unroll
        for (int pf = 0; pf < 4; pf++) {
            int pl0 = pgrp*64 + pf*16 + prow;
#pragma unroll
            for (int mf = 0; mf < 2; mf++) {
                int ml = mbase + mf*8;
                float d0 = acch[pf][mf][0] + accl[pf][mf][0];
                float d1 = acch[pf][mf][1] + accl[pf][mf][1];
                float d2 = acch[pf][mf][2] + accl[pf][mf][2];
                float d3 = acch[pf][mf][3] + accl[pf][mf][3];
                float z0 = __half2float(zo_s[ml*264 + pl0]);
                float z1 = __half2float(zo_s[(ml+1)*264 + pl0]);
                float z2 = __half2float(zo_s[ml*264 + pl0 + 8]);
                float z3 = __half2float(zo_s[(ml+1)*264 + pl0 + 8]);
                psum[pf][0] += d0*z0 + d1*z1;
                psum[pf][1] += d2*z2 + d3*z3;
            }
        }
    }

    __syncthreads();
    float* sums = (float*)(smem + FB_SUMS);
#pragma unroll
    for (int pf = 0; pf < 4; pf++)
#pragma unroll
        for (int rh = 0; rh < 2; rh++) {
            float v = psum[pf][rh];
            v += __shfl_xor_sync(0xffffffffu, v, 1);
            v += __shfl_xor_sync(0xffffffffu, v, 2);
            if ((lane & 3) == 0) {
                int p = pgrp*64 + pf*16 + rh*8 + (lane >> 2);
                sums[p*2 + wm] = v;
            }
        }
    __syncthreads();

    {
        int pq = pq0 + tid;
        if (pq < NPAIR) {
            float tot = sums[tid*2] + sums[tid*2 + 1] + __ldg(&bb[o]);
            out[(size_t)pq*NREL + o] = tot;
        }
    }
}

// ---------------- launcher ----------------
extern "C" void kernel_launch(void* const* d_in, const int* in_sizes, int n_in,
                              void* d_out, int out_size)
{
    const float* entity  = (const float*)d_in[0];
    const float* w_red   = (const float*)d_in[1];
    const float* w_sim3  = (const float*)d_in[2];
    const float* c1w     = (const float*)d_in[3];
    const float* c1b     = (const float*)d_in[4];
    const float* c2w     = (const float*)d_in[5];
    const float* c2b     = (const float*)d_in[6];
    const float* w_lin   = (const float*)d_in[7];
    const float* b_lin   = (const float*)d_in[8];
    const float* w_s     = (const float*)d_in[9];
    const float* w_o     = (const float*)d_in[10];
    const float* w_bil   = (const float*)d_in[11];
    const float* b_bil   = (const float*)d_in[12];
    float* out = (float*)d_out;

    cudaFuncSetAttribute(k_final_mma, cudaFuncAttributeMaxDynamicSharedMemorySize,
                         FB_SMEM);
    cudaFuncSetAttribute(k_c2g, cudaFuncAttributeMaxDynamicSharedMemorySize,
                         C2_SMEM);

    k_prep<<<(NE*EMBD*EMBD + 255)/256, 256>>>(c1w, c2w, w_sim3);
    k_wsplit<<<dim3(64, NREL), 256>>>(w_bil);

    k_gemm_E<<<dim3((EMBD+63)/64, (NROWS+63)/64), 256>>>(entity, w_red);
    k_norms<<<NROWS, 256>>>();

    k_gemm_T<<<dim3((NE*EMBD)/64, (NROWS+63)/64), 256>>>();

    k_sims<<<dim3(BATCH, NE), 256>>>();
    k_sim3b<<<NROWS, 256>>>();

    k_conv1<<<dim3(BATCH, NE), 256>>>(c1b);
    k_im2col<<<dim3(BATCH, NE, 8), 256>>>();
    k_c2g<<<dim3(56, 4), 256, C2_SMEM>>>(c2b);

    k_gemm_attn<<<dim3(EMBD/64, (NPAIR+63)/64), 256>>>(w_lin, b_lin);
    k_gemm_SO<<<dim3(EMBD/64, (NROWS+63)/64, 2), 256>>>(w_s, w_o);

    k_zszo<<<NPAIR_PAD, 256>>>();
    k_zot<<<dim3(NPAIR_PAD/32, EMBD/32), 256>>>();

    k_final_mma<<<dim3(NPAIR_PAD/FB_TILE, NREL), 256, FB_SMEM>>>(b_bil, out);
}

// round 11
// speedup vs baseline: 4.1138x; 1.1204x over previous
#include <cuda_runtime.h>
#include <cuda_fp16.h>
#include <cstdint>
#include <math.h>

#define NE    42
#define BATCH 4
#define EMBD  256
#define IN_D  768
#define NREL  97
#define NPIX  (NE*NE)          // 1764
#define NROWS (BATCH*NE)       // 168
#define NPAIR (BATCH*NPIX)     // 7056
#define FB_TILE 256
#define NPAIR_PAD (28*FB_TILE) // 7168
#define K2    2304             // conv2 GEMM K = 256*9

// ---------------- scratch (static device memory; no allocation) ----------------
__device__ float g_e   [NROWS*EMBD];
__device__ float g_norm[NROWS];
__device__ float g_W3  [NE*EMBD*EMBD];
__device__ float g_T   [NROWS*NE*EMBD];
__device__ float g_fm  [BATCH*3*NE*NE];
__device__ float g_w1t [27*EMBD];
__device__ float g_h1  [BATCH*EMBD*NE*NE];
__device__ float g_h2p [NPAIR_PAD*EMBD];           // conv2 out [pq][oc]
__device__ float g_attn[NPAIR*EMBD];
__device__ float g_S   [NROWS*EMBD];
__device__ float g_O   [NROWS*EMBD];
__device__ __half g_w2h[EMBD*K2];                  // conv2 weights fp16 hi
__device__ __half g_w2l[EMBD*K2];                  // conv2 weights fp16 lo
__device__ __half g_x2h[NPAIR_PAD*K2];             // im2col fp16 hi
__device__ __half g_x2l[NPAIR_PAD*K2];             // im2col fp16 lo
__device__ __half g_zs_h[NPAIR_PAD*EMBD];          // fp16 zs
__device__ float  g_zo  [NPAIR_PAD*EMBD];          // [pq][m] fp32 (transpose src)
__device__ __half g_zoT [EMBD*NPAIR_PAD];          // [m][pq] fp16
__device__ __half g_Wt_h[NREL*EMBD*EMBD];          // [o][m][n] = fp16(W_bil[o][n][m])

// ---------------- common helpers ----------------
__device__ __forceinline__ void ldm_x4(uint32_t* r, uint32_t addr) {
    asm volatile("ldmatrix.sync.aligned.m8n8.x4.shared.b16 {%0,%1,%2,%3}, [%4];"
                 : "=r"(r[0]), "=r"(r[1]), "=r"(r[2]), "=r"(r[3]) : "r"(addr));
}
__device__ __forceinline__ void mma_f16(float* c, const uint32_t* a, const uint32_t* b) {
    asm volatile("mma.sync.aligned.m16n8k16.row.col.f32.f16.f16.f32 "
                 "{%0,%1,%2,%3}, {%4,%5,%6,%7}, {%8,%9}, {%0,%1,%2,%3};"
                 : "+f"(c[0]), "+f"(c[1]), "+f"(c[2]), "+f"(c[3])
                 : "r"(a[0]), "r"(a[1]), "r"(a[2]), "r"(a[3]), "r"(b[0]), "r"(b[1]));
}
__device__ __forceinline__ uint32_t smem_u32(const void* p) {
    uint32_t a;
    asm("{ .reg .u64 t; cvta.to.shared.u64 t, %1; cvt.u32.u64 %0, t; }" : "=r"(a) : "l"(p));
    return a;
}
__device__ __forceinline__ void cp16(uint32_t dst, const void* src) {
    asm volatile("cp.async.cg.shared.global [%0], [%1], 16;" :: "r"(dst), "l"(src));
}
#define CP_COMMIT() asm volatile("cp.async.commit_group;" ::: "memory")
#define CP_WAIT0()  asm volatile("cp.async.wait_group 0;" ::: "memory")
#define CP_WAIT1()  asm volatile("cp.async.wait_group 1;" ::: "memory")

// ---------------- prep: conv1/sim3 permutes + conv2 fp16 split ----------------
__global__ void k_prep(const float* __restrict__ c1w,
                       const float* __restrict__ c2w,
                       const float* __restrict__ wsim3)
{
    int i = blockIdx.x * 256 + threadIdx.x;
    if (i < 27*EMBD) {
        int oc = i & 255, k = i >> 8;
        g_w1t[i] = c1w[oc*27 + k];
    }
    if (i < EMBD*K2) {                        // same layout, just split
        float v = c2w[i];
        __half hi = __float2half(v);
        g_w2h[i] = hi;
        g_w2l[i] = __float2half(v - __half2float(hi));
    }
    if (i < NE*EMBD*EMBD) {
        int n = i & 255;
        int c = i >> 8;
        int j = c >> 8, m = c & 255;
        g_W3[i] = wsim3[j*65536 + n*256 + m];
    }
}

// ---------------- prep: W_bil transpose -> fp16 (single precision pass) ---------
__global__ void __launch_bounds__(256) k_wsplit(const float* __restrict__ wbil)
{
    __shared__ float tile[32][33];
    int o = blockIdx.y;
    int t = blockIdx.x;
    int m0 = (t & 7) * 32, n0 = (t >> 3) * 32;
    int tx = threadIdx.x & 31, ty = threadIdx.x >> 5;
    for (int rr = ty; rr < 32; rr += 8)
        tile[rr][tx] = wbil[(size_t)o*65536 + (n0+rr)*256 + (m0+tx)];
    __syncthreads();
    for (int rr = ty; rr < 32; rr += 8) {
        float v = tile[tx][rr];                 // = w[o][n0+tx][m0+rr]
        size_t di = (size_t)o*65536 + (size_t)(m0+rr)*256 + (n0+tx);
        g_Wt_h[di] = __float2half(v);
    }
}

// ---------------- shared tiled SGEMM-NT:  C[M,N] = A[M,K] * W[N,K]^T (+bias) ------
__device__ __forceinline__ void gemm_nt_dev(
    const float* __restrict__ A, const float* __restrict__ W,
    float* __restrict__ C, const float* __restrict__ bias,
    int M, int N, int K)
{
    __shared__ float As[16][68];
    __shared__ float Bs[16][68];
    const int tid = threadIdx.x;
    const int tx = tid & 15, ty = tid >> 4;
    const int m0 = blockIdx.y * 64, n0 = blockIdx.x * 64;
    float acc[4][4];
#pragma unroll
    for (int i = 0; i < 4; i++)
#pragma unroll
        for (int j = 0; j < 4; j++) acc[i][j] = 0.f;

    for (int k0 = 0; k0 < K; k0 += 16) {
        for (int e = tid; e < 1024; e += 256) {
            int kk = e & 15, m = e >> 4;
            int gm = m0 + m;
            As[kk][m] = (gm < M) ? A[gm * K + k0 + kk] : 0.f;
        }
        for (int e = tid; e < 1024; e += 256) {
            int kk = e & 15, n = e >> 4;
            int gn = n0 + n;
            Bs[kk][n] = (gn < N) ? W[gn * K + k0 + kk] : 0.f;
        }
        __syncthreads();
#pragma unroll
        for (int kk = 0; kk < 16; kk++) {
            float a0 = As[kk][ty*4+0], a1 = As[kk][ty*4+1];
            float a2 = As[kk][ty*4+2], a3 = As[kk][ty*4+3];
            float b0 = Bs[kk][tx*4+0], b1 = Bs[kk][tx*4+1];
            float b2 = Bs[kk][tx*4+2], b3 = Bs[kk][tx*4+3];
            acc[0][0] += a0*b0; acc[0][1] += a0*b1; acc[0][2] += a0*b2; acc[0][3] += a0*b3;
            acc[1][0] += a1*b0; acc[1][1] += a1*b1; acc[1][2] += a1*b2; acc[1][3] += a1*b3;
            acc[2][0] += a2*b0; acc[2][1] += a2*b1; acc[2][2] += a2*b2; acc[2][3] += a2*b3;
            acc[3][0] += a3*b0; acc[3][1] += a3*b1; acc[3][2] += a3*b2; acc[3][3] += a3*b3;
        }
        __syncthreads();
    }
#pragma unroll
    for (int i = 0; i < 4; i++) {
        int gm = m0 + ty*4 + i;
        if (gm >= M) continue;
#pragma unroll
        for (int j = 0; j < 4; j++) {
            int gn = n0 + tx*4 + j;
            if (gn < N)
                C[gm * N + gn] = acc[i][j] + (bias ? bias[gn] : 0.f);
        }
    }
}

__global__ void __launch_bounds__(256) k_gemm_E(const float* __restrict__ ent,
                                                const float* __restrict__ wred)
{ gemm_nt_dev(ent, wred, g_e, nullptr, NROWS, EMBD, IN_D); }

__global__ void __launch_bounds__(256) k_gemm_T()
{ gemm_nt_dev(g_e, g_W3, g_T, nullptr, NROWS, NE*EMBD, EMBD); }

__global__ void __launch_bounds__(256) k_gemm_attn(const float* __restrict__ wlin,
                                                   const float* __restrict__ blin)
{ gemm_nt_dev(g_h2p, wlin, g_attn, blin, NPAIR, EMBD, EMBD); }

__global__ void __launch_bounds__(256) k_gemm_SO(const float* __restrict__ ws,
                                                 const float* __restrict__ wo)
{
    if (blockIdx.z == 0)
        gemm_nt_dev(g_e, ws, g_S, nullptr, NROWS, EMBD, EMBD);
    else
        gemm_nt_dev(g_e, wo, g_O, nullptr, NROWS, EMBD, EMBD);
}

// ---------------- norms ----------------
__global__ void k_norms()
{
    int bi = blockIdx.x;
    int tid = threadIdx.x;
    float v = g_e[bi*EMBD + tid];
    float s = v * v;
    __shared__ float red[8];
    for (int off = 16; off; off >>= 1) s += __shfl_down_sync(0xffffffffu, s, off);
    if ((tid & 31) == 0) red[tid >> 5] = s;
    __syncthreads();
    if (tid == 0) {
        float t = 0.f;
#pragma unroll
        for (int i = 0; i < 8; i++) t += red[i];
        g_norm[bi] = sqrtf(t);
    }
}

// ---------------- sim1/sim2 ----------------
__global__ void k_sims()
{
    int b = blockIdx.x, H = blockIdx.y;
    int tid = threadIdx.x, lane = tid & 31, wid = tid >> 5;
    __shared__ float eH[EMBD];
    eH[tid] = g_e[(b*NE + H)*EMBD + tid];
    __syncthreads();
    float nH = fmaxf(g_norm[b*NE + H], 1e-6f);
    for (int Wc = wid; Wc < NE; Wc += 8) {
        const float* eW = &g_e[(b*NE + Wc)*EMBD];
        float s = 0.f;
        for (int k = lane; k < EMBD; k += 32) s += eH[k] * eW[k];
        for (int off = 16; off; off >>= 1) s += __shfl_down_sync(0xffffffffu, s, off);
        if (lane == 0) {
            float nW = fmaxf(g_norm[b*NE + Wc], 1e-6f);
            g_fm[((b*3 + 0)*NE + H)*NE + Wc] = s;
            g_fm[((b*3 + 1)*NE + H)*NE + Wc] = s / (nH * nW);
        }
    }
}

// ---------------- sim3 epilogue ----------------
__global__ void k_sim3b()
{
    int bi = blockIdx.x;
    int tid = threadIdx.x, lane = tid & 31, wid = tid >> 5;
    __shared__ float ev[EMBD];
    ev[tid] = g_e[bi*EMBD + tid];
    __syncthreads();
    int b = bi / NE, r = bi - b*NE;
    for (int j = wid; j < NE; j += 8) {
        const float* Trow = &g_T[bi*(NE*EMBD) + j*EMBD];
        float s = 0.f;
        for (int k = lane; k < EMBD; k += 32) s += Trow[k] * ev[k];
        for (int off = 16; off; off >>= 1) s += __shfl_down_sync(0xffffffffu, s, off);
        if (lane == 0) g_fm[((b*3 + 2)*NE + j)*NE + r] = s;
    }
}

// ---------------- conv1 ----------------
__global__ void __launch_bounds__(256) k_conv1(const float* __restrict__ b1)
{
    int b = blockIdx.x, H = blockIdx.y;
    int oc = threadIdx.x;
    __shared__ float sm[3][3][44];
    for (int idx = threadIdx.x; idx < 396; idx += 256) {
        int ch = idx / 132, rem = idx - ch*132;
        int r = rem / 44, w = rem - r*44;
        int y = H + r - 1, x = w - 1;
        float v = 0.f;
        if (y >= 0 && y < NE && x >= 0 && x < NE)
            v = g_fm[((b*3 + ch)*NE + y)*NE + x];
        sm[ch][r][w] = v;
    }
    __syncthreads();
    float wreg[27];
#pragma unroll
    for (int k = 0; k < 27; k++) wreg[k] = g_w1t[k*EMBD + oc];
    float acc[NE];
    float bias = b1[oc];
#pragma unroll
    for (int W = 0; W < NE; W++) acc[W] = bias;
#pragma unroll
    for (int ch = 0; ch < 3; ch++)
#pragma unroll
    for (int ky = 0; ky < 3; ky++) {
        const float* row = sm[ch][ky];
        float w0 = wreg[(ch*3+ky)*3+0];
        float w1 = wreg[(ch*3+ky)*3+1];
        float w2 = wreg[(ch*3+ky)*3+2];
        float r0 = row[0], r1 = row[1];
#pragma unroll
        for (int W = 0; W < NE; W++) {
            float r2 = row[W + 2];
            acc[W] += w0*r0 + w1*r1 + w2*r2;
            r0 = r1; r1 = r2;
        }
    }
    int base = ((b*EMBD + oc)*NE + H)*NE;
#pragma unroll
    for (int W = 0; W < NE; W++) g_h1[base + W] = fmaxf(acc[W], 0.f);
}

// ---------------- im2col: X[pq][(ic)*9+k] = h1[b][ic][H+dy-1][W+dx-1] -------------
__global__ void __launch_bounds__(256) k_im2col()
{
    int b = blockIdx.x, H = blockIdx.y, icg = blockIdx.z;
    __shared__ float sm[32][3][44];
    for (int idx = threadIdx.x; idx < 4224; idx += 256) {
        int ic = idx / 132, rem = idx - ic*132;
        int r = rem / 44, w = rem - r*44;
        int y = H + r - 1, x = w - 1;
        float v = 0.f;
        if (y >= 0 && y < NE && x >= 0 && x < NE)
            v = g_h1[((b*EMBD + icg*32 + ic)*NE + y)*NE + x];
        sm[ic][r][w] = v;
    }
    __syncthreads();
    for (int idx = threadIdx.x; idx < 42*288; idx += 256) {
        int W = idx / 288, rem = idx - W*288;
        int ic = rem / 9, k = rem - ic*9;
        int dy = k / 3, dx = k - dy*3;
        float v = sm[ic][dy][W + dx];
        __half hi = __float2half(v);
        __half lo = __float2half(v - __half2float(hi));
        size_t di = (size_t)(b*NPIX + H*NE + W) * K2 + (size_t)(icg*32 + ic)*9 + k;
        g_x2h[di] = hi;
        g_x2l[di] = lo;
    }
}

// ---------------- conv2 GEMM: h2p[pq][oc] = X @ W2^T + b2 (3-pass fp16) ----------
#define C2_XH   0
#define C2_XL   18432              // 128 rows * 144 B
#define C2_WH   36864              // 64 rows * 144 B
#define C2_WL   46080
#define C2_BUF  55296
#define C2_SMEM (2*C2_BUF)         // 110592
#define C2_RSTR 144

__global__ void __launch_bounds__(256) k_c2g(const float* __restrict__ b2)
{
    extern __shared__ char smem[];
    const uint32_t sb = smem_u32(smem);
    const int tid  = threadIdx.x;
    const int lane = tid & 31;
    const int w    = tid >> 5;
    const int pgrp = w >> 1;             // 0..3 (32 pq each)
    const int wn   = w & 1;              // 0..1 (32 oc each)
    const int pq0  = blockIdx.x * 128;
    const int oc0  = blockIdx.y * 64;

    const int a_sub = (((lane >> 3) & 1) << 3) + (lane & 7);
    const int a_kh  = ((lane >> 4) & 1) << 3;
    const int b_sub = (((lane >> 4) & 1) << 3) + (lane & 7);
    const int b_kh  = ((lane >> 3) & 1) << 3;

    // prefetch chunk 0 into buffer 0
    {
        const uint32_t base = sb;
        for (int i = tid; i < 1024; i += 256) {
            int r = i >> 3, c = i & 7;
            uint32_t off = (uint32_t)r * C2_RSTR + (uint32_t)c * 16;
            size_t gsrc = ((size_t)(pq0 + r) * K2 + (size_t)c * 8) * 2;
            cp16(base + C2_XH + off, (const char*)g_x2h + gsrc);
            cp16(base + C2_XL + off, (const char*)g_x2l + gsrc);
        }
        for (int i = tid; i < 512; i += 256) {
            int r = i >> 3, c = i & 7;
            uint32_t off = (uint32_t)r * C2_RSTR + (uint32_t)c * 16;
            size_t gsrc = ((size_t)(oc0 + r) * K2 + (size_t)c * 8) * 2;
            cp16(base + C2_WH + off, (const char*)g_w2h + gsrc);
            cp16(base + C2_WL + off, (const char*)g_w2l + gsrc);
        }
        CP_COMMIT();
    }

    float acc[2][4][4];
#pragma unroll
    for (int pf = 0; pf < 2; pf++)
#pragma unroll
        for (int nf = 0; nf < 4; nf++)
#pragma unroll
            for (int q = 0; q < 4; q++) acc[pf][nf][q] = 0.f;

    for (int kc = 0; kc < 36; kc++) {
        const uint32_t cbase = sb + (kc & 1) * C2_BUF;

        if (kc < 35) {
            const uint32_t nbase = sb + ((kc + 1) & 1) * C2_BUF;
            int koff = (kc + 1) * 64;
            for (int i = tid; i < 1024; i += 256) {
                int r = i >> 3, c = i & 7;
                uint32_t off = (uint32_t)r * C2_RSTR + (uint32_t)c * 16;
                size_t gsrc = ((size_t)(pq0 + r) * K2 + koff + (size_t)c * 8) * 2;
                cp16(nbase + C2_XH + off, (const char*)g_x2h + gsrc);
                cp16(nbase + C2_XL + off, (const char*)g_x2l + gsrc);
            }
            for (int i = tid; i < 512; i += 256) {
                int r = i >> 3, c = i & 7;
                uint32_t off = (uint32_t)r * C2_RSTR + (uint32_t)c * 16;
                size_t gsrc = ((size_t)(oc0 + r) * K2 + koff + (size_t)c * 8) * 2;
                cp16(nbase + C2_WH + off, (const char*)g_w2h + gsrc);
                cp16(nbase + C2_WL + off, (const char*)g_w2l + gsrc);
            }
            CP_COMMIT();
            CP_WAIT1();            // chunk kc complete; kc+1 still in flight
        } else {
            CP_WAIT0();
        }
        __syncthreads();

#pragma unroll
        for (int k0 = 0; k0 < 64; k0 += 16) {
            uint32_t ah[2][4], al[2][4], bh[2][4], bl[2][4];
#pragma unroll
            for (int pf = 0; pf < 2; pf++) {
                uint32_t arow = (uint32_t)(pgrp*32 + pf*16 + a_sub);
                uint32_t aoff = arow * C2_RSTR + (uint32_t)(k0 + a_kh) * 2;
                ldm_x4(ah[pf], cbase + C2_XH + aoff);
                ldm_x4(al[pf], cbase + C2_XL + aoff);
            }
#pragma unroll
            for (int bn = 0; bn < 2; bn++) {
                uint32_t brow = (uint32_t)(wn*32 + bn*16 + b_sub);
                uint32_t boff = brow * C2_RSTR + (uint32_t)(k0 + b_kh) * 2;
                ldm_x4(bh[bn], cbase + C2_WH + boff);
                ldm_x4(bl[bn], cbase + C2_WL + boff);
            }
#pragma unroll
            for (int pf = 0; pf < 2; pf++)
#pragma unroll
                for (int bn = 0; bn < 2; bn++)
#pragma unroll
                    for (int j = 0; j < 2; j++) {
                        mma_f16(acc[pf][bn*2+j], ah[pf], bh[bn] + j*2);
                        mma_f16(acc[pf][bn*2+j], ah[pf], bl[bn] + j*2);
                        mma_f16(acc[pf][bn*2+j], al[pf], bh[bn] + j*2);
                    }
        }
        __syncthreads();
    }

    const int prow = lane >> 2;
#pragma unroll
    for (int pf = 0; pf < 2; pf++) {
        int p0 = pq0 + pgrp*32 + pf*16 + prow;
#pragma unroll
        for (int nf = 0; nf < 4; nf++) {
            int col = oc0 + wn*32 + nf*8 + (lane & 3)*2;
            float bias0 = __ldg(&b2[col]);
            float bias1 = __ldg(&b2[col + 1]);
            g_h2p[(size_t)p0*EMBD + col]       = acc[pf][nf][0] + bias0;
            g_h2p[(size_t)p0*EMBD + col + 1]   = acc[pf][nf][1] + bias1;
            g_h2p[(size_t)(p0+8)*EMBD + col]   = acc[pf][nf][2] + bias0;
            g_h2p[(size_t)(p0+8)*EMBD + col+1] = acc[pf][nf][3] + bias1;
        }
    }
}

// ---------------- zs/zo: tanh + fp16 zs (padded to 7168 rows) ----------
__global__ void k_zszo()
{
    int pq = blockIdx.x;
    int c  = threadIdx.x;
    float zs = 0.f, zo = 0.f;
    if (pq < NPAIR) {
        int b   = pq / NPIX;
        int rem = pq - b*NPIX;
        int a1  = rem / NE;
        int a2  = rem - a1*NE;
        float a = g_attn[pq*EMBD + c];
        zs = tanhf(g_S[(b*NE + a1)*EMBD + c] + a);
        zo = tanhf(g_O[(b*NE + a2)*EMBD + c] + a);
    }
    g_zs_h[pq*EMBD + c] = __float2half(zs);
    g_zo [pq*EMBD + c] = zo;
}

// ---------------- zo transpose: g_zoT[m][pq] = fp16(g_zo[pq][m]) ----------------
__global__ void __launch_bounds__(256) k_zot()
{
    __shared__ float tile[32][33];
    int pq0 = blockIdx.x * 32;
    int m0  = blockIdx.y * 32;
    int tx = threadIdx.x & 31, ty = threadIdx.x >> 5;
    for (int r = ty; r < 32; r += 8)
        tile[r][tx] = g_zo[(size_t)(pq0 + r)*EMBD + m0 + tx];
    __syncthreads();
    for (int r = ty; r < 32; r += 8)
        g_zoT[(size_t)(m0 + r)*NPAIR_PAD + pq0 + tx] = __float2half(tile[tx][r]);
}

// ======================= final bilinear via mma.sync fp16 ======================
// Single-pass fp16 W (error budget: zs, zo, W each 2^-11-class, fp32 accum).
#define FB_ZS      0                  // 256 rows * 528 B = 135168
#define FB_W       135168             // 2 bufs * 16896
#define FB_WBUF    16896
#define FB_ZO      168960             // 32 m * 528 B = 16896
#define FB_SUMS    185856             // 256 p * 2 * 4 = 2048
#define FB_SMEM    187904
#define FB_RSTR    528

__global__ void __launch_bounds__(256) k_final_mma(const float* __restrict__ bb,
                                                   float* __restrict__ out)
{
    extern __shared__ char smem[];
    const uint32_t sb = smem_u32(smem);
    const int tid  = threadIdx.x;
    const int lane = tid & 31;
    const int w    = tid >> 5;           // 8 warps
    const int pgrp = w >> 1;             // 0..3  (64 p each)
    const int wm   = w & 1;              // 0..1  (16 m each)
    const int pq0  = blockIdx.x * FB_TILE;
    const int o    = blockIdx.y;

    for (int i = tid; i < 256*32; i += 256) {
        int row = i >> 5, c = i & 31;
        uint32_t off = (uint32_t)row * FB_RSTR + (uint32_t)c * 16;
        size_t gsrc = ((size_t)(pq0 + row) * 256 + (size_t)c * 8) * 2;
        cp16(sb + FB_ZS + off, (const char*)g_zs_h + gsrc);
    }
    for (int i = tid; i < 1024; i += 256) {
        int r = i >> 5, c = i & 31;
        uint32_t off = (uint32_t)r * FB_RSTR + (uint32_t)c * 16;
        size_t gsrc = ((size_t)o * 65536 + (size_t)r * 256 + (size_t)c * 8) * 2;
        cp16(sb + FB_W + off, (const char*)g_Wt_h + gsrc);
    }
    CP_COMMIT();

    const int a_sub = (((lane >> 3) & 1) << 3) + (lane & 7);
    const int a_kh  = ((lane >> 4) & 1) << 3;
    const int b_sub = (((lane >> 4) & 1) << 3) + (lane & 7);
    const int b_kh  = ((lane >> 3) & 1) << 3;

    float psum[4][2];
#pragma unroll
    for (int pf = 0; pf < 4; pf++) { psum[pf][0] = 0.f; psum[pf][1] = 0.f; }
    const __half* zo_s = (const __half*)(smem + FB_ZO);

    for (int mc = 0; mc < 8; mc++) {
        const int cur = mc & 1, nxt = cur ^ 1;
        CP_WAIT0();
        __syncthreads();

        for (int i = tid; i < 1024; i += 256) {
            int m = i >> 5, c = i & 31;
            uint32_t off = (uint32_t)m * FB_RSTR + (uint32_t)c * 16;
            size_t gsrc = ((size_t)(mc*32 + m) * NPAIR_PAD + pq0) * 2 + (size_t)c * 16;
            cp16(sb + FB_ZO + off, (const char*)g_zoT + gsrc);
        }
        CP_COMMIT();

        if (mc < 7) {
            for (int i = tid; i < 1024; i += 256) {
                int r = i >> 5, c = i & 31;
                uint32_t off = (uint32_t)r * FB_RSTR + (uint32_t)c * 16;
                size_t gsrc = ((size_t)o * 65536 +
                               (size_t)((mc + 1) * 32 + r) * 256 + (size_t)c * 8) * 2;
                cp16(sb + FB_W + nxt*FB_WBUF + off, (const char*)g_Wt_h + gsrc);
            }
            CP_COMMIT();
        }

        float acc[4][2][4];
#pragma unroll
        for (int pf = 0; pf < 4; pf++)
#pragma unroll
            for (int mf = 0; mf < 2; mf++)
#pragma unroll
                for (int q = 0; q < 4; q++) acc[pf][mf][q] = 0.f;

        const uint32_t wbase = sb + FB_W + cur*FB_WBUF;
#pragma unroll 4
        for (int k0 = 0; k0 < 256; k0 += 16) {
            uint32_t av[4][4], bv[4];
#pragma unroll
            for (int pf = 0; pf < 4; pf++) {
                uint32_t arow = (uint32_t)(pgrp*64 + pf*16 + a_sub);
                uint32_t aoff = arow * FB_RSTR + (uint32_t)(k0 + a_kh) * 2;
                ldm_x4(av[pf], sb + FB_ZS + aoff);
            }
            {
                uint32_t brow = (uint32_t)(wm*16 + b_sub);
                uint32_t boff = brow * FB_RSTR + (uint32_t)(k0 + b_kh) * 2;
                ldm_x4(bv, wbase + boff);
            }
#pragma unroll
            for (int pf = 0; pf < 4; pf++)
#pragma unroll
                for (int mf = 0; mf < 2; mf++)
                    mma_f16(acc[pf][mf], av[pf], bv + mf*2);
        }

        if (mc < 7) { CP_WAIT1(); } else { CP_WAIT0(); }
        __syncthreads();

        const int mbase = wm*16 + (lane & 3)*2;
        const int prow  = (lane >> 2);
#pragma unroll
        for (int pf = 0; pf < 4; pf++) {
            int pl0 = pgrp*64 + pf*16 + prow;
#pragma unroll
            for (int mf = 0; mf < 2; mf++) {
                int ml = mbase + mf*8;
                float z0 = __half2float(zo_s[ml*264 + pl0]);
                float z1 = __half2float(zo_s[(ml+1)*264 + pl0]);
                float z2 = __half2float(zo_s[ml*264 + pl0 + 8]);
                float z3 = __half2float(zo_s[(ml+1)*264 + pl0 + 8]);
                psum[pf][0] += acc[pf][mf][0]*z0 + acc[pf][mf][1]*z1;
                psum[pf][1] += acc[pf][mf][2]*z2 + acc[pf][mf][3]*z3;
            }
        }
    }

    __syncthreads();
    float* sums = (float*)(smem + FB_SUMS);
#pragma unroll
    for (int pf = 0; pf < 4; pf++)
#pragma unroll
        for (int rh = 0; rh < 2; rh++) {
            float v = psum[pf][rh];
            v += __shfl_xor_sync(0xffffffffu, v, 1);
            v += __shfl_xor_sync(0xffffffffu, v, 2);
            if ((lane & 3) == 0) {
                int p = pgrp*64 + pf*16 + rh*8 + (lane >> 2);
                sums[p*2 + wm] = v;
            }
        }
    __syncthreads();

    {
        int pq = pq0 + tid;
        if (pq < NPAIR) {
            float tot = sums[tid*2] + sums[tid*2 + 1] + __ldg(&bb[o]);
            out[(size_t)pq*NREL + o] = tot;
        }
    }
}

// ---------------- launcher ----------------
extern "C" void kernel_launch(void* const* d_in, const int* in_sizes, int n_in,
                              void* d_out, int out_size)
{
    const float* entity  = (const float*)d_in[0];
    const float* w_red   = (const float*)d_in[1];
    const float* w_sim3  = (const float*)d_in[2];
    const float* c1w     = (const float*)d_in[3];
    const float* c1b     = (const float*)d_in[4];
    const float* c2w     = (const float*)d_in[5];
    const float* c2b     = (const float*)d_in[6];
    const float* w_lin   = (const float*)d_in[7];
    const float* b_lin   = (const float*)d_in[8];
    const float* w_s     = (const float*)d_in[9];
    const float* w_o     = (const float*)d_in[10];
    const float* w_bil   = (const float*)d_in[11];
    const float* b_bil   = (const float*)d_in[12];
    float* out = (float*)d_out;

    cudaFuncSetAttribute(k_final_mma, cudaFuncAttributeMaxDynamicSharedMemorySize,
                         FB_SMEM);
    cudaFuncSetAttribute(k_c2g, cudaFuncAttributeMaxDynamicSharedMemorySize,
                         C2_SMEM);

    k_prep<<<(NE*EMBD*EMBD + 255)/256, 256>>>(c1w, c2w, w_sim3);
    k_wsplit<<<dim3(64, NREL), 256>>>(w_bil);

    k_gemm_E<<<dim3((EMBD+63)/64, (NROWS+63)/64), 256>>>(entity, w_red);
    k_norms<<<NROWS, 256>>>();

    k_gemm_T<<<dim3((NE*EMBD)/64, (NROWS+63)/64), 256>>>();

    k_sims<<<dim3(BATCH, NE), 256>>>();
    k_sim3b<<<NROWS, 256>>>();

    k_conv1<<<dim3(BATCH, NE), 256>>>(c1b);
    k_im2col<<<dim3(BATCH, NE, 8), 256>>>();
    k_c2g<<<dim3(56, 4), 256, C2_SMEM>>>(c2b);

    k_gemm_attn<<<dim3(EMBD/64, (NPAIR+63)/64), 256>>>(w_lin, b_lin);
    k_gemm_SO<<<dim3(EMBD/64, (NROWS+63)/64, 2), 256>>>(w_s, w_o);

    k_zszo<<<NPAIR_PAD, 256>>>();
    k_zot<<<dim3(NPAIR_PAD/32, EMBD/32), 256>>>();

    k_final_mma<<<dim3(NPAIR_PAD/FB_TILE, NREL), 256, FB_SMEM>>>(b_bil, out);
}

// round 12
// speedup vs baseline: 4.6799x; 1.1376x over previous
#include <cuda_runtime.h>
#include <cuda_fp16.h>
#include <cstdint>
#include <math.h>

#define NE    42
#define BATCH 4
#define EMBD  256
#define IN_D  768
#define NREL  97
#define NPIX  (NE*NE)          // 1764
#define NROWS (BATCH*NE)       // 168
#define NPAIR (BATCH*NPIX)     // 7056
#define FB_TILE 256
#define NPAIR_PAD (28*FB_TILE) // 7168
#define K2    2304             // conv2 GEMM K = 256*9

// ---------------- scratch (static device memory; no allocation) ----------------
__device__ float g_e   [NROWS*EMBD];
__device__ float g_norm[NROWS];
__device__ float g_W3  [NE*EMBD*EMBD];
__device__ float g_T   [NROWS*NE*EMBD];
__device__ float g_fm  [BATCH*3*NE*NE];
__device__ float g_w1t [27*EMBD];
__device__ float g_h1  [BATCH*EMBD*NE*NE];
__device__ float g_h2p [NPAIR_PAD*EMBD];           // conv2 out [pq][oc]
__device__ float g_attn[NPAIR*EMBD];
__device__ float g_S   [NROWS*EMBD];
__device__ float g_O   [NROWS*EMBD];
__device__ __half g_w2h[EMBD*K2];                  // conv2 weights fp16 hi
__device__ __half g_w2l[EMBD*K2];                  // conv2 weights fp16 lo
__device__ __half g_x2h[NPAIR_PAD*K2];             // im2col fp16 hi
__device__ __half g_x2l[NPAIR_PAD*K2];             // im2col fp16 lo
__device__ __half g_zs_h[NPAIR_PAD*EMBD];          // fp16 zs
__device__ float  g_zo  [NPAIR_PAD*EMBD];          // [pq][m] fp32 (transpose src)
__device__ __half g_zoT [EMBD*NPAIR_PAD];          // [m][pq] fp16
__device__ __half g_Wt_h[NREL*EMBD*EMBD];          // [o][m][n] = fp16(W_bil[o][n][m])

// ---------------- common helpers ----------------
__device__ __forceinline__ void ldm_x4(uint32_t* r, uint32_t addr) {
    asm volatile("ldmatrix.sync.aligned.m8n8.x4.shared.b16 {%0,%1,%2,%3}, [%4];"
                 : "=r"(r[0]), "=r"(r[1]), "=r"(r[2]), "=r"(r[3]) : "r"(addr));
}
__device__ __forceinline__ void mma_f16(float* c, const uint32_t* a, const uint32_t* b) {
    asm volatile("mma.sync.aligned.m16n8k16.row.col.f32.f16.f16.f32 "
                 "{%0,%1,%2,%3}, {%4,%5,%6,%7}, {%8,%9}, {%0,%1,%2,%3};"
                 : "+f"(c[0]), "+f"(c[1]), "+f"(c[2]), "+f"(c[3])
                 : "r"(a[0]), "r"(a[1]), "r"(a[2]), "r"(a[3]), "r"(b[0]), "r"(b[1]));
}
__device__ __forceinline__ uint32_t smem_u32(const void* p) {
    uint32_t a;
    asm("{ .reg .u64 t; cvta.to.shared.u64 t, %1; cvt.u32.u64 %0, t; }" : "=r"(a) : "l"(p));
    return a;
}
__device__ __forceinline__ void cp16(uint32_t dst, const void* src) {
    asm volatile("cp.async.cg.shared.global [%0], [%1], 16;" :: "r"(dst), "l"(src));
}
#define CP_COMMIT() asm volatile("cp.async.commit_group;" ::: "memory")
#define CP_WAIT0()  asm volatile("cp.async.wait_group 0;" ::: "memory")
#define CP_WAIT1()  asm volatile("cp.async.wait_group 1;" ::: "memory")

// ---------------- prep: conv1/sim3 permutes + conv2 fp16 split ----------------
__global__ void k_prep(const float* __restrict__ c1w,
                       const float* __restrict__ c2w,
                       const float* __restrict__ wsim3)
{
    int i = blockIdx.x * 256 + threadIdx.x;
    if (i < 27*EMBD) {
        int oc = i & 255, k = i >> 8;
        g_w1t[i] = c1w[oc*27 + k];
    }
    if (i < EMBD*K2) {
        float v = c2w[i];
        __half hi = __float2half(v);
        g_w2h[i] = hi;
        g_w2l[i] = __float2half(v - __half2float(hi));
    }
    if (i < NE*EMBD*EMBD) {
        int n = i & 255;
        int c = i >> 8;
        int j = c >> 8, m = c & 255;
        g_W3[i] = wsim3[j*65536 + n*256 + m];
    }
}

// ---------------- prep: W_bil transpose -> fp16 ----------------
__global__ void __launch_bounds__(256) k_wsplit(const float* __restrict__ wbil)
{
    __shared__ float tile[32][33];
    int o = blockIdx.y;
    int t = blockIdx.x;
    int m0 = (t & 7) * 32, n0 = (t >> 3) * 32;
    int tx = threadIdx.x & 31, ty = threadIdx.x >> 5;
    for (int rr = ty; rr < 32; rr += 8)
        tile[rr][tx] = wbil[(size_t)o*65536 + (n0+rr)*256 + (m0+tx)];
    __syncthreads();
    for (int rr = ty; rr < 32; rr += 8) {
        float v = tile[tx][rr];                 // = w[o][n0+tx][m0+rr]
        size_t di = (size_t)o*65536 + (size_t)(m0+rr)*256 + (n0+tx);
        g_Wt_h[di] = __float2half(v);
    }
}

// ---------------- shared tiled SGEMM-NT:  C[M,N] = A[M,K] * W[N,K]^T (+bias) ------
__device__ __forceinline__ void gemm_nt_dev(
    const float* __restrict__ A, const float* __restrict__ W,
    float* __restrict__ C, const float* __restrict__ bias,
    int M, int N, int K)
{
    __shared__ float As[16][68];
    __shared__ float Bs[16][68];
    const int tid = threadIdx.x;
    const int tx = tid & 15, ty = tid >> 4;
    const int m0 = blockIdx.y * 64, n0 = blockIdx.x * 64;
    float acc[4][4];
#pragma unroll
    for (int i = 0; i < 4; i++)
#pragma unroll
        for (int j = 0; j < 4; j++) acc[i][j] = 0.f;

    for (int k0 = 0; k0 < K; k0 += 16) {
        for (int e = tid; e < 1024; e += 256) {
            int kk = e & 15, m = e >> 4;
            int gm = m0 + m;
            As[kk][m] = (gm < M) ? A[gm * K + k0 + kk] : 0.f;
        }
        for (int e = tid; e < 1024; e += 256) {
            int kk = e & 15, n = e >> 4;
            int gn = n0 + n;
            Bs[kk][n] = (gn < N) ? W[gn * K + k0 + kk] : 0.f;
        }
        __syncthreads();
#pragma unroll
        for (int kk = 0; kk < 16; kk++) {
            float a0 = As[kk][ty*4+0], a1 = As[kk][ty*4+1];
            float a2 = As[kk][ty*4+2], a3 = As[kk][ty*4+3];
            float b0 = Bs[kk][tx*4+0], b1 = Bs[kk][tx*4+1];
            float b2 = Bs[kk][tx*4+2], b3 = Bs[kk][tx*4+3];
            acc[0][0] += a0*b0; acc[0][1] += a0*b1; acc[0][2] += a0*b2; acc[0][3] += a0*b3;
            acc[1][0] += a1*b0; acc[1][1] += a1*b1; acc[1][2] += a1*b2; acc[1][3] += a1*b3;
            acc[2][0] += a2*b0; acc[2][1] += a2*b1; acc[2][2] += a2*b2; acc[2][3] += a2*b3;
            acc[3][0] += a3*b0; acc[3][1] += a3*b1; acc[3][2] += a3*b2; acc[3][3] += a3*b3;
        }
        __syncthreads();
    }
#pragma unroll
    for (int i = 0; i < 4; i++) {
        int gm = m0 + ty*4 + i;
        if (gm >= M) continue;
#pragma unroll
        for (int j = 0; j < 4; j++) {
            int gn = n0 + tx*4 + j;
            if (gn < N)
                C[gm * N + gn] = acc[i][j] + (bias ? bias[gn] : 0.f);
        }
    }
}

__global__ void __launch_bounds__(256) k_gemm_E(const float* __restrict__ ent,
                                                const float* __restrict__ wred)
{ gemm_nt_dev(ent, wred, g_e, nullptr, NROWS, EMBD, IN_D); }

__global__ void __launch_bounds__(256) k_gemm_T()
{ gemm_nt_dev(g_e, g_W3, g_T, nullptr, NROWS, NE*EMBD, EMBD); }

__global__ void __launch_bounds__(256) k_gemm_attn(const float* __restrict__ wlin,
                                                   const float* __restrict__ blin)
{ gemm_nt_dev(g_h2p, wlin, g_attn, blin, NPAIR, EMBD, EMBD); }

__global__ void __launch_bounds__(256) k_gemm_SO(const float* __restrict__ ws,
                                                 const float* __restrict__ wo)
{
    if (blockIdx.z == 0)
        gemm_nt_dev(g_e, ws, g_S, nullptr, NROWS, EMBD, EMBD);
    else
        gemm_nt_dev(g_e, wo, g_O, nullptr, NROWS, EMBD, EMBD);
}

// ---------------- norms ----------------
__global__ void k_norms()
{
    int bi = blockIdx.x;
    int tid = threadIdx.x;
    float v = g_e[bi*EMBD + tid];
    float s = v * v;
    __shared__ float red[8];
    for (int off = 16; off; off >>= 1) s += __shfl_down_sync(0xffffffffu, s, off);
    if ((tid & 31) == 0) red[tid >> 5] = s;
    __syncthreads();
    if (tid == 0) {
        float t = 0.f;
#pragma unroll
        for (int i = 0; i < 8; i++) t += red[i];
        g_norm[bi] = sqrtf(t);
    }
}

// ---------------- sim1/sim2 ----------------
__global__ void k_sims()
{
    int b = blockIdx.x, H = blockIdx.y;
    int tid = threadIdx.x, lane = tid & 31, wid = tid >> 5;
    __shared__ float eH[EMBD];
    eH[tid] = g_e[(b*NE + H)*EMBD + tid];
    __syncthreads();
    float nH = fmaxf(g_norm[b*NE + H], 1e-6f);
    for (int Wc = wid; Wc < NE; Wc += 8) {
        const float* eW = &g_e[(b*NE + Wc)*EMBD];
        float s = 0.f;
        for (int k = lane; k < EMBD; k += 32) s += eH[k] * eW[k];
        for (int off = 16; off; off >>= 1) s += __shfl_down_sync(0xffffffffu, s, off);
        if (lane == 0) {
            float nW = fmaxf(g_norm[b*NE + Wc], 1e-6f);
            g_fm[((b*3 + 0)*NE + H)*NE + Wc] = s;
            g_fm[((b*3 + 1)*NE + H)*NE + Wc] = s / (nH * nW);
        }
    }
}

// ---------------- sim3 epilogue ----------------
__global__ void k_sim3b()
{
    int bi = blockIdx.x;
    int tid = threadIdx.x, lane = tid & 31, wid = tid >> 5;
    __shared__ float ev[EMBD];
    ev[tid] = g_e[bi*EMBD + tid];
    __syncthreads();
    int b = bi / NE, r = bi - b*NE;
    for (int j = wid; j < NE; j += 8) {
        const float* Trow = &g_T[bi*(NE*EMBD) + j*EMBD];
        float s = 0.f;
        for (int k = lane; k < EMBD; k += 32) s += Trow[k] * ev[k];
        for (int off = 16; off; off >>= 1) s += __shfl_down_sync(0xffffffffu, s, off);
        if (lane == 0) g_fm[((b*3 + 2)*NE + j)*NE + r] = s;
    }
}

// ---------------- conv1 ----------------
__global__ void __launch_bounds__(256) k_conv1(const float* __restrict__ b1)
{
    int b = blockIdx.x, H = blockIdx.y;
    int oc = threadIdx.x;
    __shared__ float sm[3][3][44];
    for (int idx = threadIdx.x; idx < 396; idx += 256) {
        int ch = idx / 132, rem = idx - ch*132;
        int r = rem / 44, w = rem - r*44;
        int y = H + r - 1, x = w - 1;
        float v = 0.f;
        if (y >= 0 && y < NE && x >= 0 && x < NE)
            v = g_fm[((b*3 + ch)*NE + y)*NE + x];
        sm[ch][r][w] = v;
    }
    __syncthreads();
    float wreg[27];
#pragma unroll
    for (int k = 0; k < 27; k++) wreg[k] = g_w1t[k*EMBD + oc];
    float acc[NE];
    float bias = b1[oc];
#pragma unroll
    for (int W = 0; W < NE; W++) acc[W] = bias;
#pragma unroll
    for (int ch = 0; ch < 3; ch++)
#pragma unroll
    for (int ky = 0; ky < 3; ky++) {
        const float* row = sm[ch][ky];
        float w0 = wreg[(ch*3+ky)*3+0];
        float w1 = wreg[(ch*3+ky)*3+1];
        float w2 = wreg[(ch*3+ky)*3+2];
        float r0 = row[0], r1 = row[1];
#pragma unroll
        for (int W = 0; W < NE; W++) {
            float r2 = row[W + 2];
            acc[W] += w0*r0 + w1*r1 + w2*r2;
            r0 = r1; r1 = r2;
        }
    }
    int base = ((b*EMBD + oc)*NE + H)*NE;
#pragma unroll
    for (int W = 0; W < NE; W++) g_h1[base + W] = fmaxf(acc[W], 0.f);
}

// ---------------- im2col: X[pq][(ic)*9+k] = h1[b][ic][H+dy-1][W+dx-1] -------------
__global__ void __launch_bounds__(256) k_im2col()
{
    int b = blockIdx.x, H = blockIdx.y, icg = blockIdx.z;
    __shared__ float sm[32][3][44];
    for (int idx = threadIdx.x; idx < 4224; idx += 256) {
        int ic = idx / 132, rem = idx - ic*132;
        int r = rem / 44, w = rem - r*44;
        int y = H + r - 1, x = w - 1;
        float v = 0.f;
        if (y >= 0 && y < NE && x >= 0 && x < NE)
            v = g_h1[((b*EMBD + icg*32 + ic)*NE + y)*NE + x];
        sm[ic][r][w] = v;
    }
    __syncthreads();
    for (int idx = threadIdx.x; idx < 42*288; idx += 256) {
        int W = idx / 288, rem = idx - W*288;
        int ic = rem / 9, k = rem - ic*9;
        int dy = k / 3, dx = k - dy*3;
        float v = sm[ic][dy][W + dx];
        __half hi = __float2half(v);
        __half lo = __float2half(v - __half2float(hi));
        size_t di = (size_t)(b*NPIX + H*NE + W) * K2 + (size_t)(icg*32 + ic)*9 + k;
        g_x2h[di] = hi;
        g_x2l[di] = lo;
    }
}

// ---------------- conv2 GEMM: h2p[pq][oc] = X @ W2^T + b2 (3-pass fp16) ----------
#define C2_XH   0
#define C2_XL   18432              // 128 rows * 144 B
#define C2_WH   36864              // 64 rows * 144 B
#define C2_WL   46080
#define C2_BUF  55296
#define C2_SMEM (2*C2_BUF)         // 110592
#define C2_RSTR 144

__global__ void __launch_bounds__(256) k_c2g(const float* __restrict__ b2)
{
    extern __shared__ char smem[];
    const uint32_t sb = smem_u32(smem);
    const int tid  = threadIdx.x;
    const int lane = tid & 31;
    const int w    = tid >> 5;
    const int pgrp = w >> 1;             // 0..3 (32 pq each)
    const int wn   = w & 1;              // 0..1 (32 oc each)
    const int pq0  = blockIdx.x * 128;
    const int oc0  = blockIdx.y * 64;

    const int a_sub = (((lane >> 3) & 1) << 3) + (lane & 7);
    const int a_kh  = ((lane >> 4) & 1) << 3;
    const int b_sub = (((lane >> 4) & 1) << 3) + (lane & 7);
    const int b_kh  = ((lane >> 3) & 1) << 3;

    // prefetch chunk 0 into buffer 0
    {
        const uint32_t base = sb;
        for (int i = tid; i < 1024; i += 256) {
            int r = i >> 3, c = i & 7;
            uint32_t off = (uint32_t)r * C2_RSTR + (uint32_t)c * 16;
            size_t gsrc = ((size_t)(pq0 + r) * K2 + (size_t)c * 8) * 2;
            cp16(base + C2_XH + off, (const char*)g_x2h + gsrc);
            cp16(base + C2_XL + off, (const char*)g_x2l + gsrc);
        }
        for (int i = tid; i < 512; i += 256) {
            int r = i >> 3, c = i & 7;
            uint32_t off = (uint32_t)r * C2_RSTR + (uint32_t)c * 16;
            size_t gsrc = ((size_t)(oc0 + r) * K2 + (size_t)c * 8) * 2;
            cp16(base + C2_WH + off, (const char*)g_w2h + gsrc);
            cp16(base + C2_WL + off, (const char*)g_w2l + gsrc);
        }
        CP_COMMIT();
    }

    float acc[2][4][4];
#pragma unroll
    for (int pf = 0; pf < 2; pf++)
#pragma unroll
        for (int nf = 0; nf < 4; nf++)
#pragma unroll
            for (int q = 0; q < 4; q++) acc[pf][nf][q] = 0.f;

    for (int kc = 0; kc < 36; kc++) {
        const uint32_t cbase = sb + (kc & 1) * C2_BUF;

        if (kc < 35) {
            const uint32_t nbase = sb + ((kc + 1) & 1) * C2_BUF;
            int koff = (kc + 1) * 64;
            for (int i = tid; i < 1024; i += 256) {
                int r = i >> 3, c = i & 7;
                uint32_t off = (uint32_t)r * C2_RSTR + (uint32_t)c * 16;
                size_t gsrc = ((size_t)(pq0 + r) * K2 + koff + (size_t)c * 8) * 2;
                cp16(nbase + C2_XH + off, (const char*)g_x2h + gsrc);
                cp16(nbase + C2_XL + off, (const char*)g_x2l + gsrc);
            }
            for (int i = tid; i < 512; i += 256) {
                int r = i >> 3, c = i & 7;
                uint32_t off = (uint32_t)r * C2_RSTR + (uint32_t)c * 16;
                size_t gsrc = ((size_t)(oc0 + r) * K2 + koff + (size_t)c * 8) * 2;
                cp16(nbase + C2_WH + off, (const char*)g_w2h + gsrc);
                cp16(nbase + C2_WL + off, (const char*)g_w2l + gsrc);
            }
            CP_COMMIT();
            CP_WAIT1();
        } else {
            CP_WAIT0();
        }
        __syncthreads();

#pragma unroll
        for (int k0 = 0; k0 < 64; k0 += 16) {
            uint32_t ah[2][4], al[2][4], bh[2][4], bl[2][4];
#pragma unroll
            for (int pf = 0; pf < 2; pf++) {
                uint32_t arow = (uint32_t)(pgrp*32 + pf*16 + a_sub);
                uint32_t aoff = arow * C2_RSTR + (uint32_t)(k0 + a_kh) * 2;
                ldm_x4(ah[pf], cbase + C2_XH + aoff);
                ldm_x4(al[pf], cbase + C2_XL + aoff);
            }
#pragma unroll
            for (int bn = 0; bn < 2; bn++) {
                uint32_t brow = (uint32_t)(wn*32 + bn*16 + b_sub);
                uint32_t boff = brow * C2_RSTR + (uint32_t)(k0 + b_kh) * 2;
                ldm_x4(bh[bn], cbase + C2_WH + boff);
                ldm_x4(bl[bn], cbase + C2_WL + boff);
            }
#pragma unroll
            for (int pf = 0; pf < 2; pf++)
#pragma unroll
                for (int bn = 0; bn < 2; bn++)
#pragma unroll
                    for (int j = 0; j < 2; j++) {
                        mma_f16(acc[pf][bn*2+j], ah[pf], bh[bn] + j*2);
                        mma_f16(acc[pf][bn*2+j], ah[pf], bl[bn] + j*2);
                        mma_f16(acc[pf][bn*2+j], al[pf], bh[bn] + j*2);
                    }
        }
        __syncthreads();
    }

    const int prow = lane >> 2;
#pragma unroll
    for (int pf = 0; pf < 2; pf++) {
        int p0 = pq0 + pgrp*32 + pf*16 + prow;
#pragma unroll
        for (int nf = 0; nf < 4; nf++) {
            int col = oc0 + wn*32 + nf*8 + (lane & 3)*2;
            float bias0 = __ldg(&b2[col]);
            float bias1 = __ldg(&b2[col + 1]);
            g_h2p[(size_t)p0*EMBD + col]       = acc[pf][nf][0] + bias0;
            g_h2p[(size_t)p0*EMBD + col + 1]   = acc[pf][nf][1] + bias1;
            g_h2p[(size_t)(p0+8)*EMBD + col]   = acc[pf][nf][2] + bias0;
            g_h2p[(size_t)(p0+8)*EMBD + col+1] = acc[pf][nf][3] + bias1;
        }
    }
}

// ---------------- zs/zo: tanh + fp16 zs (padded to 7168 rows) ----------
__global__ void k_zszo()
{
    int pq = blockIdx.x;
    int c  = threadIdx.x;
    float zs = 0.f, zo = 0.f;
    if (pq < NPAIR) {
        int b   = pq / NPIX;
        int rem = pq - b*NPIX;
        int a1  = rem / NE;
        int a2  = rem - a1*NE;
        float a = g_attn[pq*EMBD + c];
        zs = tanhf(g_S[(b*NE + a1)*EMBD + c] + a);
        zo = tanhf(g_O[(b*NE + a2)*EMBD + c] + a);
    }
    g_zs_h[pq*EMBD + c] = __float2half(zs);
    g_zo [pq*EMBD + c] = zo;
}

// ---------------- zo transpose: g_zoT[m][pq] = fp16(g_zo[pq][m]) ----------------
__global__ void __launch_bounds__(256) k_zot()
{
    __shared__ float tile[32][33];
    int pq0 = blockIdx.x * 32;
    int m0  = blockIdx.y * 32;
    int tx = threadIdx.x & 31, ty = threadIdx.x >> 5;
    for (int r = ty; r < 32; r += 8)
        tile[r][tx] = g_zo[(size_t)(pq0 + r)*EMBD + m0 + tx];
    __syncthreads();
    for (int r = ty; r < 32; r += 8)
        g_zoT[(size_t)(m0 + r)*NPAIR_PAD + pq0 + tx] = __float2half(tile[tx][r]);
}

// ======================= final bilinear via mma.sync fp16 ======================
// 64-m chunks (4), 64p x 32m warp tiles, XOR-swizzled zs/W (512B rows, no pad).
// SMEM: zs 131072 | W 2x32768 | zo 33792 (sums overlaid) = 230400 B.
#define FB_ZS      0
#define FB_W       131072
#define FB_WBUF    32768
#define FB_ZO      196608
#define FB_SUMS    196608             // overlays zo (used only after final sync)
#define FB_SMEM    230400
// swizzled offset within a 512B row: 16B unit c (0..31), unit' = c ^ (row&7)
#define SWZ(row, c) ((uint32_t)(row) * 512u + (uint32_t)(((c) ^ ((row) & 7)) * 16))

__global__ void __launch_bounds__(256) k_final_mma(const float* __restrict__ bb,
                                                   float* __restrict__ out)
{
    extern __shared__ char smem[];
    const uint32_t sb = smem_u32(smem);
    const int tid  = threadIdx.x;
    const int lane = tid & 31;
    const int w    = tid >> 5;           // 8 warps
    const int pgrp = w >> 1;             // 0..3  (64 p each)
    const int wm   = w & 1;              // 0..1  (32 m each within 64-m chunk)
    const int pq0  = blockIdx.x * FB_TILE;
    const int o    = blockIdx.y;

    // ---- stage zs (256x256 fp16, swizzled) + W chunk 0 (64 m, swizzled) ----
    for (int i = tid; i < 256*32; i += 256) {
        int row = i >> 5, c = i & 31;
        size_t gsrc = ((size_t)(pq0 + row) * 256 + (size_t)c * 8) * 2;
        cp16(sb + FB_ZS + SWZ(row, c), (const char*)g_zs_h + gsrc);
    }
    for (int i = tid; i < 64*32; i += 256) {
        int r = i >> 5, c = i & 31;
        size_t gsrc = ((size_t)o * 65536 + (size_t)r * 256 + (size_t)c * 8) * 2;
        cp16(sb + FB_W + SWZ(r, c), (const char*)g_Wt_h + gsrc);
    }
    CP_COMMIT();

    const int a_sub = (((lane >> 3) & 1) << 3) + (lane & 7);
    const int a_ku  = (lane >> 4) & 1;                  // k-half in 16B units
    const int b_sub = (((lane >> 4) & 1) << 3) + (lane & 7);
    const int b_ku  = (lane >> 3) & 1;

    float psum[4][2];
#pragma unroll
    for (int pf = 0; pf < 4; pf++) { psum[pf][0] = 0.f; psum[pf][1] = 0.f; }
    const __half* zo_s = (const __half*)(smem + FB_ZO);

    for (int mc = 0; mc < 4; mc++) {
        const int cur = mc & 1, nxt = cur ^ 1;
        CP_WAIT0();
        __syncthreads();            // W[mc] (and zs on mc==0) visible; zo buf free

        // group A: zo chunk [64 m x 256 pq] fp16 (rows padded to 528 B)
        for (int i = tid; i < 64*32; i += 256) {
            int m = i >> 5, c = i & 31;
            uint32_t off = (uint32_t)m * 528 + (uint32_t)c * 16;
            size_t gsrc = ((size_t)(mc*64 + m) * NPAIR_PAD + pq0) * 2 + (size_t)c * 16;
            cp16(sb + FB_ZO + off, (const char*)g_zoT + gsrc);
        }
        CP_COMMIT();

        // group B: prefetch W[mc+1] (in flight through mainloop AND epilogue)
        if (mc < 3) {
            for (int i = tid; i < 64*32; i += 256) {
                int r = i >> 5, c = i & 31;
                size_t gsrc = ((size_t)o * 65536 +
                               (size_t)((mc + 1) * 64 + r) * 256 + (size_t)c * 8) * 2;
                cp16(sb + FB_W + nxt*FB_WBUF + SWZ(r, c), (const char*)g_Wt_h + gsrc);
            }
            CP_COMMIT();
        }

        // ---- mainloop: warp tile 64p x 32m, 6 LDSM : 16 HMMA per k-step ----
        float acc[4][4][4];
#pragma unroll
        for (int pf = 0; pf < 4; pf++)
#pragma unroll
            for (int mf = 0; mf < 4; mf++)
#pragma unroll
                for (int q = 0; q < 4; q++) acc[pf][mf][q] = 0.f;

        const uint32_t wbase = sb + FB_W + cur*FB_WBUF;
#pragma unroll 4
        for (int k0 = 0; k0 < 256; k0 += 16) {
            uint32_t av[4][4], bv[2][4];
            const int ku = k0 >> 3;   // 16B-unit index of k0
#pragma unroll
            for (int pf = 0; pf < 4; pf++) {
                int arow = pgrp*64 + pf*16 + a_sub;
                ldm_x4(av[pf], sb + FB_ZS + SWZ(arow, ku + a_ku));
            }
#pragma unroll
            for (int bn = 0; bn < 2; bn++) {
                int brow = wm*32 + bn*16 + b_sub;
                ldm_x4(bv[bn], wbase + SWZ(brow, ku + b_ku));
            }
#pragma unroll
            for (int pf = 0; pf < 4; pf++)
#pragma unroll
                for (int bn = 0; bn < 2; bn++)
#pragma unroll
                    for (int j = 0; j < 2; j++)
                        mma_f16(acc[pf][bn*2+j], av[pf], bv[bn] + j*2);
        }

        // ---- wait for zo (group A); W group B may stay in flight ----
        if (mc < 3) { CP_WAIT1(); } else { CP_WAIT0(); }
        __syncthreads();

        // ---- epilogue: dot with zo ----
        const int mbase = wm*32 + (lane & 3)*2;
        const int prow  = (lane >> 2);
#pragma unroll
        for (int pf = 0; pf < 4; pf++) {
            int pl0 = pgrp*64 + pf*16 + prow;
#pragma unroll
            for (int mf = 0; mf < 4; mf++) {
                int ml = mbase + mf*8;
                float z0 = __half2float(zo_s[ml*264 + pl0]);
                float z1 = __half2float(zo_s[(ml+1)*264 + pl0]);
                float z2 = __half2float(zo_s[ml*264 + pl0 + 8]);
                float z3 = __half2float(zo_s[(ml+1)*264 + pl0 + 8]);
                psum[pf][0] += acc[pf][mf][0]*z0 + acc[pf][mf][1]*z1;
                psum[pf][1] += acc[pf][mf][2]*z2 + acc[pf][mf][3]*z3;
            }
        }
    }

    // ---- reduce across the 4 lanes of each quad (different m) ----
    __syncthreads();
    float* sums = (float*)(smem + FB_SUMS);
#pragma unroll
    for (int pf = 0; pf < 4; pf++)
#pragma unroll
        for (int rh = 0; rh < 2; rh++) {
            float v = psum[pf][rh];
            v += __shfl_xor_sync(0xffffffffu, v, 1);
            v += __shfl_xor_sync(0xffffffffu, v, 2);
            if ((lane & 3) == 0) {
                int p = pgrp*64 + pf*16 + rh*8 + (lane >> 2);
                sums[p*2 + wm] = v;
            }
        }
    __syncthreads();

    {
        int pq = pq0 + tid;
        if (pq < NPAIR) {
            float tot = sums[tid*2] + sums[tid*2 + 1] + __ldg(&bb[o]);
            out[(size_t)pq*NREL + o] = tot;
        }
    }
}

// ---------------- launcher ----------------
extern "C" void kernel_launch(void* const* d_in, const int* in_sizes, int n_in,
                              void* d_out, int out_size)
{
    const float* entity  = (const float*)d_in[0];
    const float* w_red   = (const float*)d_in[1];
    const float* w_sim3  = (const float*)d_in[2];
    const float* c1w     = (const float*)d_in[3];
    const float* c1b     = (const float*)d_in[4];
    const float* c2w     = (const float*)d_in[5];
    const float* c2b     = (const float*)d_in[6];
    const float* w_lin   = (const float*)d_in[7];
    const float* b_lin   = (const float*)d_in[8];
    const float* w_s     = (const float*)d_in[9];
    const float* w_o     = (const float*)d_in[10];
    const float* w_bil   = (const float*)d_in[11];
    const float* b_bil   = (const float*)d_in[12];
    float* out = (float*)d_out;

    cudaFuncSetAttribute(k_final_mma, cudaFuncAttributeMaxDynamicSharedMemorySize,
                         FB_SMEM);
    cudaFuncSetAttribute(k_c2g, cudaFuncAttributeMaxDynamicSharedMemorySize,
                         C2_SMEM);

    k_prep<<<(NE*EMBD*EMBD + 255)/256, 256>>>(c1w, c2w, w_sim3);
    k_wsplit<<<dim3(64, NREL), 256>>>(w_bil);

    k_gemm_E<<<dim3((EMBD+63)/64, (NROWS+63)/64), 256>>>(entity, w_red);
    k_norms<<<NROWS, 256>>>();

    k_gemm_T<<<dim3((NE*EMBD)/64, (NROWS+63)/64), 256>>>();

    k_sims<<<dim3(BATCH, NE), 256>>>();
    k_sim3b<<<NROWS, 256>>>();

    k_conv1<<<dim3(BATCH, NE), 256>>>(c1b);
    k_im2col<<<dim3(BATCH, NE, 8), 256>>>();
    k_c2g<<<dim3(56, 4), 256, C2_SMEM>>>(c2b);

    k_gemm_attn<<<dim3(EMBD/64, (NPAIR+63)/64), 256>>>(w_lin, b_lin);
    k_gemm_SO<<<dim3(EMBD/64, (NROWS+63)/64, 2), 256>>>(w_s, w_o);

    k_zszo<<<NPAIR_PAD, 256>>>();
    k_zot<<<dim3(NPAIR_PAD/32, EMBD/32), 256>>>();

    k_final_mma<<<dim3(NPAIR_PAD/FB_TILE, NREL), 256, FB_SMEM>>>(b_bil, out);
}

// round 15
// speedup vs baseline: 5.0299x; 1.0748x over previous
#include <cuda_runtime.h>
#include <cuda_fp16.h>
#include <cstdint>
#include <math.h>

#define NE    42
#define BATCH 4
#define EMBD  256
#define IN_D  768
#define NREL  97
#define NPIX  (NE*NE)          // 1764
#define NROWS (BATCH*NE)       // 168
#define NPAIR (BATCH*NPIX)     // 7056
#define FB_TILE 256
#define NPAIR_PAD (28*FB_TILE) // 7168
#define K2    2304             // conv2 GEMM K = 256*9
#define NT    (NE*EMBD)        // 10752

// ---------------- scratch (static device memory; no allocation) ----------------
__device__ float g_e   [NROWS*EMBD];
__device__ __half g_e_h[NROWS*EMBD];
__device__ __half g_e_l[NROWS*EMBD];
__device__ float g_norm[NROWS];
__device__ __half g_W3h[NE*EMBD*EMBD];             // sim3 weight permuted, fp16 hi
__device__ __half g_W3l[NE*EMBD*EMBD];             // fp16 lo
__device__ float g_T   [NROWS*NT];
__device__ float g_fm  [BATCH*3*NE*NE];
__device__ float g_w1t [27*EMBD];
__device__ float g_h1  [BATCH*EMBD*NE*NE];
__device__ float g_h2p [NPAIR_PAD*EMBD];           // conv2 out [pq][oc] fp32
__device__ __half g_h2hx[NPAIR_PAD*EMBD];          // h2 fp16 hi
__device__ __half g_h2lx[NPAIR_PAD*EMBD];          // h2 fp16 lo
__device__ __half g_wlh[EMBD*EMBD];                // W_lin fp16 hi
__device__ __half g_wll[EMBD*EMBD];                // W_lin fp16 lo
__device__ float g_attn[NPAIR_PAD*EMBD];
__device__ float g_S   [NROWS*EMBD];
__device__ float g_O   [NROWS*EMBD];
__device__ __half g_w2h[EMBD*K2];                  // conv2 weights fp16 hi
__device__ __half g_w2l[EMBD*K2];                  // conv2 weights fp16 lo
__device__ __half g_x2h[NPAIR_PAD*K2];             // im2col fp16 hi
__device__ __half g_x2l[NPAIR_PAD*K2];             // im2col fp16 lo
__device__ __half g_zs_h[NPAIR_PAD*EMBD];          // fp16 zs
__device__ float  g_zo  [NPAIR_PAD*EMBD];          // [pq][m] fp32 (transpose src)
__device__ __half g_zoT [EMBD*NPAIR_PAD];          // [m][pq] fp16
__device__ __half g_Wt_h[NREL*EMBD*EMBD];          // [o][m][n] = fp16(W_bil[o][n][m])

// ---------------- common helpers ----------------
__device__ __forceinline__ void ldm_x4(uint32_t* r, uint32_t addr) {
    asm volatile("ldmatrix.sync.aligned.m8n8.x4.shared.b16 {%0,%1,%2,%3}, [%4];"
                 : "=r"(r[0]), "=r"(r[1]), "=r"(r[2]), "=r"(r[3]) : "r"(addr));
}
__device__ __forceinline__ void mma_f16(float* c, const uint32_t* a, const uint32_t* b) {
    asm volatile("mma.sync.aligned.m16n8k16.row.col.f32.f16.f16.f32 "
                 "{%0,%1,%2,%3}, {%4,%5,%6,%7}, {%8,%9}, {%0,%1,%2,%3};"
                 : "+f"(c[0]), "+f"(c[1]), "+f"(c[2]), "+f"(c[3])
                 : "r"(a[0]), "r"(a[1]), "r"(a[2]), "r"(a[3]), "r"(b[0]), "r"(b[1]));
}
__device__ __forceinline__ uint32_t smem_u32(const void* p) {
    uint32_t a;
    asm("{ .reg .u64 t; cvta.to.shared.u64 t, %1; cvt.u32.u64 %0, t; }" : "=r"(a) : "l"(p));
    return a;
}
__device__ __forceinline__ void cp16(uint32_t dst, const void* src) {
    asm volatile("cp.async.cg.shared.global [%0], [%1], 16;" :: "r"(dst), "l"(src));
}
#define CP_COMMIT() asm volatile("cp.async.commit_group;" ::: "memory")
#define CP_WAIT0()  asm volatile("cp.async.wait_group 0;" ::: "memory")
#define CP_WAIT1()  asm volatile("cp.async.wait_group 1;" ::: "memory")
// swizzled offset within a 512B row: 16B unit c (0..31), unit' = c ^ (row&7)
#define SWZ(row, c) ((uint32_t)(row) * 512u + (uint32_t)(((c) ^ ((row) & 7)) * 16))

// ---------------- prep: conv1 permute + fp16 splits (conv2, W3, W_lin) ----------
__global__ void k_prep(const float* __restrict__ c1w,
                       const float* __restrict__ c2w,
                       const float* __restrict__ wsim3,
                       const float* __restrict__ wlin)
{
    int i = blockIdx.x * 256 + threadIdx.x;
    if (i < 27*EMBD) {
        int oc = i & 255, k = i >> 8;
        g_w1t[i] = c1w[oc*27 + k];
    }
    if (i < EMBD*EMBD) {
        float v = wlin[i];
        __half hi = __float2half(v);
        g_wlh[i] = hi;
        g_wll[i] = __float2half(v - __half2float(hi));
    }
    if (i < EMBD*K2) {
        float v = c2w[i];
        __half hi = __float2half(v);
        g_w2h[i] = hi;
        g_w2l[i] = __float2half(v - __half2float(hi));
    }
    if (i < NE*EMBD*EMBD) {
        int n = i & 255;
        int c = i >> 8;
        int j = c >> 8, m = c & 255;
        float v = wsim3[j*65536 + n*256 + m];
        __half hi = __float2half(v);
        g_W3h[i] = hi;
        g_W3l[i] = __float2half(v - __half2float(hi));
    }
}

// ---------------- prep: W_bil transpose -> fp16 ----------------
__global__ void __launch_bounds__(256) k_wsplit(const float* __restrict__ wbil)
{
    __shared__ float tile[32][33];
    int o = blockIdx.y;
    int t = blockIdx.x;
    int m0 = (t & 7) * 32, n0 = (t >> 3) * 32;
    int tx = threadIdx.x & 31, ty = threadIdx.x >> 5;
    for (int rr = ty; rr < 32; rr += 8)
        tile[rr][tx] = wbil[(size_t)o*65536 + (n0+rr)*256 + (m0+tx)];
    __syncthreads();
    for (int rr = ty; rr < 32; rr += 8) {
        float v = tile[tx][rr];                 // = w[o][n0+tx][m0+rr]
        size_t di = (size_t)o*65536 + (size_t)(m0+rr)*256 + (n0+tx);
        g_Wt_h[di] = __float2half(v);
    }
}

// ---------------- shared tiled SGEMM-NT (small cases: E, S, O) ----------------
__device__ __forceinline__ void gemm_nt_dev(
    const float* __restrict__ A, const float* __restrict__ W,
    float* __restrict__ C, const float* __restrict__ bias,
    int M, int N, int K)
{
    __shared__ float As[16][68];
    __shared__ float Bs[16][68];
    const int tid = threadIdx.x;
    const int tx = tid & 15, ty = tid >> 4;
    const int m0 = blockIdx.y * 64, n0 = blockIdx.x * 64;
    float acc[4][4];
#pragma unroll
    for (int i = 0; i < 4; i++)
#pragma unroll
        for (int j = 0; j < 4; j++) acc[i][j] = 0.f;

    for (int k0 = 0; k0 < K; k0 += 16) {
        for (int e = tid; e < 1024; e += 256) {
            int kk = e & 15, m = e >> 4;
            int gm = m0 + m;
            As[kk][m] = (gm < M) ? A[gm * K + k0 + kk] : 0.f;
        }
        for (int e = tid; e < 1024; e += 256) {
            int kk = e & 15, n = e >> 4;
            int gn = n0 + n;
            Bs[kk][n] = (gn < N) ? W[gn * K + k0 + kk] : 0.f;
        }
        __syncthreads();
#pragma unroll
        for (int kk = 0; kk < 16; kk++) {
            float a0 = As[kk][ty*4+0], a1 = As[kk][ty*4+1];
            float a2 = As[kk][ty*4+2], a3 = As[kk][ty*4+3];
            float b0 = Bs[kk][tx*4+0], b1 = Bs[kk][tx*4+1];
            float b2 = Bs[kk][tx*4+2], b3 = Bs[kk][tx*4+3];
            acc[0][0] += a0*b0; acc[0][1] += a0*b1; acc[0][2] += a0*b2; acc[0][3] += a0*b3;
            acc[1][0] += a1*b0; acc[1][1] += a1*b1; acc[1][2] += a1*b2; acc[1][3] += a1*b3;
            acc[2][0] += a2*b0; acc[2][1] += a2*b1; acc[2][2] += a2*b2; acc[2][3] += a2*b3;
            acc[3][0] += a3*b0; acc[3][1] += a3*b1; acc[3][2] += a3*b2; acc[3][3] += a3*b3;
        }
        __syncthreads();
    }
#pragma unroll
    for (int i = 0; i < 4; i++) {
        int gm = m0 + ty*4 + i;
        if (gm >= M) continue;
#pragma unroll
        for (int j = 0; j < 4; j++) {
            int gn = n0 + tx*4 + j;
            if (gn < N)
                C[gm * N + gn] = acc[i][j] + (bias ? bias[gn] : 0.f);
        }
    }
}

__global__ void __launch_bounds__(256) k_gemm_E(const float* __restrict__ ent,
                                                const float* __restrict__ wred)
{ gemm_nt_dev(ent, wred, g_e, nullptr, NROWS, EMBD, IN_D); }

__global__ void __launch_bounds__(256) k_gemm_SO(const float* __restrict__ ws,
                                                 const float* __restrict__ wo)
{
    if (blockIdx.z == 0)
        gemm_nt_dev(g_e, ws, g_S, nullptr, NROWS, EMBD, EMBD);
    else
        gemm_nt_dev(g_e, wo, g_O, nullptr, NROWS, EMBD, EMBD);
}

// ---------------- norms + e fp16 split ----------------
__global__ void k_norms()
{
    int bi = blockIdx.x;
    int tid = threadIdx.x;
    float v = g_e[bi*EMBD + tid];
    __half hi = __float2half(v);
    g_e_h[bi*EMBD + tid] = hi;
    g_e_l[bi*EMBD + tid] = __float2half(v - __half2float(hi));
    float s = v * v;
    __shared__ float red[8];
    for (int off = 16; off; off >>= 1) s += __shfl_down_sync(0xffffffffu, s, off);
    if ((tid & 31) == 0) red[tid >> 5] = s;
    __syncthreads();
    if (tid == 0) {
        float t = 0.f;
#pragma unroll
        for (int i = 0; i < 8; i++) t += red[i];
        g_norm[bi] = sqrtf(t);
    }
}

// ---------------- sim1/sim2 ----------------
__global__ void k_sims()
{
    int b = blockIdx.x, H = blockIdx.y;
    int tid = threadIdx.x, lane = tid & 31, wid = tid >> 5;
    __shared__ float eH[EMBD];
    eH[tid] = g_e[(b*NE + H)*EMBD + tid];
    __syncthreads();
    float nH = fmaxf(g_norm[b*NE + H], 1e-6f);
    for (int Wc = wid; Wc < NE; Wc += 8) {
        const float* eW = &g_e[(b*NE + Wc)*EMBD];
        float s = 0.f;
        for (int k = lane; k < EMBD; k += 32) s += eH[k] * eW[k];
        for (int off = 16; off; off >>= 1) s += __shfl_down_sync(0xffffffffu, s, off);
        if (lane == 0) {
            float nW = fmaxf(g_norm[b*NE + Wc], 1e-6f);
            g_fm[((b*3 + 0)*NE + H)*NE + Wc] = s;
            g_fm[((b*3 + 1)*NE + H)*NE + Wc] = s / (nH * nW);
        }
    }
}

// ---------------- sim3 epilogue ----------------
__global__ void k_sim3b()
{
    int bi = blockIdx.x;
    int tid = threadIdx.x, lane = tid & 31, wid = tid >> 5;
    __shared__ float ev[EMBD];
    ev[tid] = g_e[bi*EMBD + tid];
    __syncthreads();
    int b = bi / NE, r = bi - b*NE;
    for (int j = wid; j < NE; j += 8) {
        const float* Trow = &g_T[bi*NT + j*EMBD];
        float s = 0.f;
        for (int k = lane; k < EMBD; k += 32) s += Trow[k] * ev[k];
        for (int off = 16; off; off >>= 1) s += __shfl_down_sync(0xffffffffu, s, off);
        if (lane == 0) g_fm[((b*3 + 2)*NE + j)*NE + r] = s;
    }
}

// ---------------- conv1 ----------------
__global__ void __launch_bounds__(256) k_conv1(const float* __restrict__ b1)
{
    int b = blockIdx.x, H = blockIdx.y;
    int oc = threadIdx.x;
    __shared__ float sm[3][3][44];
    for (int idx = threadIdx.x; idx < 396; idx += 256) {
        int ch = idx / 132, rem = idx - ch*132;
        int r = rem / 44, w = rem - r*44;
        int y = H + r - 1, x = w - 1;
        float v = 0.f;
        if (y >= 0 && y < NE && x >= 0 && x < NE)
            v = g_fm[((b*3 + ch)*NE + y)*NE + x];
        sm[ch][r][w] = v;
    }
    __syncthreads();
    float wreg[27];
#pragma unroll
    for (int k = 0; k < 27; k++) wreg[k] = g_w1t[k*EMBD + oc];
    float acc[NE];
    float bias = b1[oc];
#pragma unroll
    for (int W = 0; W < NE; W++) acc[W] = bias;
#pragma unroll
    for (int ch = 0; ch < 3; ch++)
#pragma unroll
    for (int ky = 0; ky < 3; ky++) {
        const float* row = sm[ch][ky];
        float w0 = wreg[(ch*3+ky)*3+0];
        float w1 = wreg[(ch*3+ky)*3+1];
        float w2 = wreg[(ch*3+ky)*3+2];
        float r0 = row[0], r1 = row[1];
#pragma unroll
        for (int W = 0; W < NE; W++) {
            float r2 = row[W + 2];
            acc[W] += w0*r0 + w1*r1 + w2*r2;
            r0 = r1; r1 = r2;
        }
    }
    int base = ((b*EMBD + oc)*NE + H)*NE;
#pragma unroll
    for (int W = 0; W < NE; W++) g_h1[base + W] = fmaxf(acc[W], 0.f);
}

// ---------------- im2col ----------------
__global__ void __launch_bounds__(256) k_im2col()
{
    int b = blockIdx.x, H = blockIdx.y, icg = blockIdx.z;
    __shared__ float sm[32][3][44];
    for (int idx = threadIdx.x; idx < 4224; idx += 256) {
        int ic = idx / 132, rem = idx - ic*132;
        int r = rem / 44, w = rem - r*44;
        int y = H + r - 1, x = w - 1;
        float v = 0.f;
        if (y >= 0 && y < NE && x >= 0 && x < NE)
            v = g_h1[((b*EMBD + icg*32 + ic)*NE + y)*NE + x];
        sm[ic][r][w] = v;
    }
    __syncthreads();
    for (int idx = threadIdx.x; idx < 42*288; idx += 256) {
        int W = idx / 288, rem = idx - W*288;
        int ic = rem / 9, k = rem - ic*9;
        int dy = k / 3, dx = k - dy*3;
        float v = sm[ic][dy][W + dx];
        __half hi = __float2half(v);
        __half lo = __float2half(v - __half2float(hi));
        size_t di = (size_t)(b*NPIX + H*NE + W) * K2 + (size_t)(icg*32 + ic)*9 + k;
        g_x2h[di] = hi;
        g_x2l[di] = lo;
    }
}

// ---------------- conv2 GEMM: h2p[pq][oc] = X @ W2^T + b2 (3-pass fp16) ----------
#define C2_XH   0
#define C2_XL   18432              // 128 rows * 144 B
#define C2_WH   36864              // 64 rows * 144 B
#define C2_WL   46080
#define C2_BUF  55296
#define C2_SMEM (2*C2_BUF)         // 110592
#define C2_RSTR 144

__global__ void __launch_bounds__(256) k_c2g(const float* __restrict__ b2)
{
    extern __shared__ char smem[];
    const uint32_t sb = smem_u32(smem);
    const int tid  = threadIdx.x;
    const int lane = tid & 31;
    const int w    = tid >> 5;
    const int pgrp = w >> 1;
    const int wn   = w & 1;
    const int pq0  = blockIdx.x * 128;
    const int oc0  = blockIdx.y * 64;

    const int a_sub = (((lane >> 3) & 1) << 3) + (lane & 7);
    const int a_kh  = ((lane >> 4) & 1) << 3;
    const int b_sub = (((lane >> 4) & 1) << 3) + (lane & 7);
    const int b_kh  = ((lane >> 3) & 1) << 3;

    {
        const uint32_t base = sb;
        for (int i = tid; i < 1024; i += 256) {
            int r = i >> 3, c = i & 7;
            uint32_t off = (uint32_t)r * C2_RSTR + (uint32_t)c * 16;
            size_t gsrc = ((size_t)(pq0 + r) * K2 + (size_t)c * 8) * 2;
            cp16(base + C2_XH + off, (const char*)g_x2h + gsrc);
            cp16(base + C2_XL + off, (const char*)g_x2l + gsrc);
        }
        for (int i = tid; i < 512; i += 256) {
            int r = i >> 3, c = i & 7;
            uint32_t off = (uint32_t)r * C2_RSTR + (uint32_t)c * 16;
            size_t gsrc = ((size_t)(oc0 + r) * K2 + (size_t)c * 8) * 2;
            cp16(base + C2_WH + off, (const char*)g_w2h + gsrc);
            cp16(base + C2_WL + off, (const char*)g_w2l + gsrc);
        }
        CP_COMMIT();
    }

    float acc[2][4][4];
#pragma unroll
    for (int pf = 0; pf < 2; pf++)
#pragma unroll
        for (int nf = 0; nf < 4; nf++)
#pragma unroll
            for (int q = 0; q < 4; q++) acc[pf][nf][q] = 0.f;

    for (int kc = 0; kc < 36; kc++) {
        const uint32_t cbase = sb + (kc & 1) * C2_BUF;

        if (kc < 35) {
            const uint32_t nbase = sb + ((kc + 1) & 1) * C2_BUF;
            int koff = (kc + 1) * 64;
            for (int i = tid; i < 1024; i += 256) {
                int r = i >> 3, c = i & 7;
                uint32_t off = (uint32_t)r * C2_RSTR + (uint32_t)c * 16;
                size_t gsrc = ((size_t)(pq0 + r) * K2 + koff + (size_t)c * 8) * 2;
                cp16(nbase + C2_XH + off, (const char*)g_x2h + gsrc);
                cp16(nbase + C2_XL + off, (const char*)g_x2l + gsrc);
            }
            for (int i = tid; i < 512; i += 256) {
                int r = i >> 3, c = i & 7;
                uint32_t off = (uint32_t)r * C2_RSTR + (uint32_t)c * 16;
                size_t gsrc = ((size_t)(oc0 + r) * K2 + koff + (size_t)c * 8) * 2;
                cp16(nbase + C2_WH + off, (const char*)g_w2h + gsrc);
                cp16(nbase + C2_WL + off, (const char*)g_w2l + gsrc);
            }
            CP_COMMIT();
            CP_WAIT1();
        } else {
            CP_WAIT0();
        }
        __syncthreads();

#pragma unroll
        for (int k0 = 0; k0 < 64; k0 += 16) {
            uint32_t ah[2][4], al[2][4], bh[2][4], bl[2][4];
#pragma unroll
            for (int pf = 0; pf < 2; pf++) {
                uint32_t arow = (uint32_t)(pgrp*32 + pf*16 + a_sub);
                uint32_t aoff = arow * C2_RSTR + (uint32_t)(k0 + a_kh) * 2;
                ldm_x4(ah[pf], cbase + C2_XH + aoff);
                ldm_x4(al[pf], cbase + C2_XL + aoff);
            }
#pragma unroll
            for (int bn = 0; bn < 2; bn++) {
                uint32_t brow = (uint32_t)(wn*32 + bn*16 + b_sub);
                uint32_t boff = brow * C2_RSTR + (uint32_t)(k0 + b_kh) * 2;
                ldm_x4(bh[bn], cbase + C2_WH + boff);
                ldm_x4(bl[bn], cbase + C2_WL + boff);
            }
#pragma unroll
            for (int pf = 0; pf < 2; pf++)
#pragma unroll
                for (int bn = 0; bn < 2; bn++)
#pragma unroll
                    for (int j = 0; j < 2; j++) {
                        mma_f16(acc[pf][bn*2+j], ah[pf], bh[bn] + j*2);
                        mma_f16(acc[pf][bn*2+j], ah[pf], bl[bn] + j*2);
                        mma_f16(acc[pf][bn*2+j], al[pf], bh[bn] + j*2);
                    }
        }
        __syncthreads();
    }

    const int prow = lane >> 2;
#pragma unroll
    for (int pf = 0; pf < 2; pf++) {
        int p0 = pq0 + pgrp*32 + pf*16 + prow;
#pragma unroll
        for (int nf = 0; nf < 4; nf++) {
            int col = oc0 + wn*32 + nf*8 + (lane & 3)*2;
            float bias0 = __ldg(&b2[col]);
            float bias1 = __ldg(&b2[col + 1]);
            g_h2p[(size_t)p0*EMBD + col]       = acc[pf][nf][0] + bias0;
            g_h2p[(size_t)p0*EMBD + col + 1]   = acc[pf][nf][1] + bias1;
            g_h2p[(size_t)(p0+8)*EMBD + col]   = acc[pf][nf][2] + bias0;
            g_h2p[(size_t)(p0+8)*EMBD + col+1] = acc[pf][nf][3] + bias1;
        }
    }
}

// ---------------- h2 fp16 split ----------------
__global__ void k_h2split()
{
    size_t i = (size_t)blockIdx.x * 256 + threadIdx.x;
    float v = g_h2p[i];
    __half hi = __float2half(v);
    g_h2hx[i] = hi;
    g_h2lx[i] = __float2half(v - __half2float(hi));
}

// ------- attn GEMM (k_c2g clone, K=256 in 4 chunks): attn = h2 @ Wlin^T + b -----
__global__ void __launch_bounds__(256) k_attn_g(const float* __restrict__ blin)
{
    extern __shared__ char smem[];
    const uint32_t sb = smem_u32(smem);
    const int tid  = threadIdx.x;
    const int lane = tid & 31;
    const int w    = tid >> 5;
    const int pgrp = w >> 1;
    const int wn   = w & 1;
    const int pq0  = blockIdx.x * 128;
    const int oc0  = blockIdx.y * 64;

    const int a_sub = (((lane >> 3) & 1) << 3) + (lane & 7);
    const int a_kh  = ((lane >> 4) & 1) << 3;
    const int b_sub = (((lane >> 4) & 1) << 3) + (lane & 7);
    const int b_kh  = ((lane >> 3) & 1) << 3;

    {
        const uint32_t base = sb;
        for (int i = tid; i < 1024; i += 256) {
            int r = i >> 3, c = i & 7;
            uint32_t off = (uint32_t)r * C2_RSTR + (uint32_t)c * 16;
            size_t gsrc = ((size_t)(pq0 + r) * EMBD + (size_t)c * 8) * 2;
            cp16(base + C2_XH + off, (const char*)g_h2hx + gsrc);
            cp16(base + C2_XL + off, (const char*)g_h2lx + gsrc);
        }
        for (int i = tid; i < 512; i += 256) {
            int r = i >> 3, c = i & 7;
            uint32_t off = (uint32_t)r * C2_RSTR + (uint32_t)c * 16;
            size_t gsrc = ((size_t)(oc0 + r) * EMBD + (size_t)c * 8) * 2;
            cp16(base + C2_WH + off, (const char*)g_wlh + gsrc);
            cp16(base + C2_WL + off, (const char*)g_wll + gsrc);
        }
        CP_COMMIT();
    }

    float acc[2][4][4];
#pragma unroll
    for (int pf = 0; pf < 2; pf++)
#pragma unroll
        for (int nf = 0; nf < 4; nf++)
#pragma unroll
            for (int q = 0; q < 4; q++) acc[pf][nf][q] = 0.f;

    for (int kc = 0; kc < 4; kc++) {
        const uint32_t cbase = sb + (kc & 1) * C2_BUF;

        if (kc < 3) {
            const uint32_t nbase = sb + ((kc + 1) & 1) * C2_BUF;
            int koff = (kc + 1) * 64;
            for (int i = tid; i < 1024; i += 256) {
                int r = i >> 3, c = i & 7;
                uint32_t off = (uint32_t)r * C2_RSTR + (uint32_t)c * 16;
                size_t gsrc = ((size_t)(pq0 + r) * EMBD + koff + (size_t)c * 8) * 2;
                cp16(nbase + C2_XH + off, (const char*)g_h2hx + gsrc);
                cp16(nbase + C2_XL + off, (const char*)g_h2lx + gsrc);
            }
            for (int i = tid; i < 512; i += 256) {
                int r = i >> 3, c = i & 7;
                uint32_t off = (uint32_t)r * C2_RSTR + (uint32_t)c * 16;
                size_t gsrc = ((size_t)(oc0 + r) * EMBD + koff + (size_t)c * 8) * 2;
                cp16(nbase + C2_WH + off, (const char*)g_wlh + gsrc);
                cp16(nbase + C2_WL + off, (const char*)g_wll + gsrc);
            }
            CP_COMMIT();
            CP_WAIT1();
        } else {
            CP_WAIT0();
        }
        __syncthreads();

#pragma unroll
        for (int k0 = 0; k0 < 64; k0 += 16) {
            uint32_t ah[2][4], al[2][4], bh[2][4], bl[2][4];
#pragma unroll
            for (int pf = 0; pf < 2; pf++) {
                uint32_t arow = (uint32_t)(pgrp*32 + pf*16 + a_sub);
                uint32_t aoff = arow * C2_RSTR + (uint32_t)(k0 + a_kh) * 2;
                ldm_x4(ah[pf], cbase + C2_XH + aoff);
                ldm_x4(al[pf], cbase + C2_XL + aoff);
            }
#pragma unroll
            for (int bn = 0; bn < 2; bn++) {
                uint32_t brow = (uint32_t)(wn*32 + bn*16 + b_sub);
                uint32_t boff = brow * C2_RSTR + (uint32_t)(k0 + b_kh) * 2;
                ldm_x4(bh[bn], cbase + C2_WH + boff);
                ldm_x4(bl[bn], cbase + C2_WL + boff);
            }
#pragma unroll
            for (int pf = 0; pf < 2; pf++)
#pragma unroll
                for (int bn = 0; bn < 2; bn++)
#pragma unroll
                    for (int j = 0; j < 2; j++) {
                        mma_f16(acc[pf][bn*2+j], ah[pf], bh[bn] + j*2);
                        mma_f16(acc[pf][bn*2+j], ah[pf], bl[bn] + j*2);
                        mma_f16(acc[pf][bn*2+j], al[pf], bh[bn] + j*2);
                    }
        }
        __syncthreads();
    }

    const int prow = lane >> 2;
#pragma unroll
    for (int pf = 0; pf < 2; pf++) {
        int p0 = pq0 + pgrp*32 + pf*16 + prow;
#pragma unroll
        for (int nf = 0; nf < 4; nf++) {
            int col = oc0 + wn*32 + nf*8 + (lane & 3)*2;
            float bias0 = __ldg(&blin[col]);
            float bias1 = __ldg(&blin[col + 1]);
            g_attn[(size_t)p0*EMBD + col]       = acc[pf][nf][0] + bias0;
            g_attn[(size_t)p0*EMBD + col + 1]   = acc[pf][nf][1] + bias1;
            g_attn[(size_t)(p0+8)*EMBD + col]   = acc[pf][nf][2] + bias0;
            g_attn[(size_t)(p0+8)*EMBD + col+1] = acc[pf][nf][3] + bias1;
        }
    }
}

// ------- sim3 GEMM (k_c2g clone, K=256 in 4 chunks): T = e @ W3^T ---------------
__global__ void __launch_bounds__(256) k_t_g()
{
    extern __shared__ char smem[];
    const uint32_t sb = smem_u32(smem);
    const int tid  = threadIdx.x;
    const int lane = tid & 31;
    const int w    = tid >> 5;
    const int pgrp = w >> 1;
    const int wn   = w & 1;
    const int pq0  = blockIdx.x * 128;       // rows of e (0 or 128)
    const int oc0  = blockIdx.y * 64;        // cols of T (0..10688)

    const int a_sub = (((lane >> 3) & 1) << 3) + (lane & 7);
    const int a_kh  = ((lane >> 4) & 1) << 3;
    const int b_sub = (((lane >> 4) & 1) << 3) + (lane & 7);
    const int b_kh  = ((lane >> 3) & 1) << 3;

    {
        const uint32_t base = sb;
        for (int i = tid; i < 1024; i += 256) {
            int r = i >> 3, c = i & 7;
            int gm = pq0 + r; if (gm > NROWS-1) gm = NROWS-1;
            uint32_t off = (uint32_t)r * C2_RSTR + (uint32_t)c * 16;
            size_t gsrc = ((size_t)gm * EMBD + (size_t)c * 8) * 2;
            cp16(base + C2_XH + off, (const char*)g_e_h + gsrc);
            cp16(base + C2_XL + off, (const char*)g_e_l + gsrc);
        }
        for (int i = tid; i < 512; i += 256) {
            int r = i >> 3, c = i & 7;
            uint32_t off = (uint32_t)r * C2_RSTR + (uint32_t)c * 16;
            size_t gsrc = ((size_t)(oc0 + r) * EMBD + (size_t)c * 8) * 2;
            cp16(base + C2_WH + off, (const char*)g_W3h + gsrc);
            cp16(base + C2_WL + off, (const char*)g_W3l + gsrc);
        }
        CP_COMMIT();
    }

    float acc[2][4][4];
#pragma unroll
    for (int pf = 0; pf < 2; pf++)
#pragma unroll
        for (int nf = 0; nf < 4; nf++)
#pragma unroll
            for (int q = 0; q < 4; q++) acc[pf][nf][q] = 0.f;

    for (int kc = 0; kc < 4; kc++) {
        const uint32_t cbase = sb + (kc & 1) * C2_BUF;

        if (kc < 3) {
            const uint32_t nbase = sb + ((kc + 1) & 1) * C2_BUF;
            int koff = (kc + 1) * 64;
            for (int i = tid; i < 1024; i += 256) {
                int r = i >> 3, c = i & 7;
                int gm = pq0 + r; if (gm > NROWS-1) gm = NROWS-1;
                uint32_t off = (uint32_t)r * C2_RSTR + (uint32_t)c * 16;
                size_t gsrc = ((size_t)gm * EMBD + koff + (size_t)c * 8) * 2;
                cp16(nbase + C2_XH + off, (const char*)g_e_h + gsrc);
                cp16(nbase + C2_XL + off, (const char*)g_e_l + gsrc);
            }
            for (int i = tid; i < 512; i += 256) {
                int r = i >> 3, c = i & 7;
                uint32_t off = (uint32_t)r * C2_RSTR + (uint32_t)c * 16;
                size_t gsrc = ((size_t)(oc0 + r) * EMBD + koff + (size_t)c * 8) * 2;
                cp16(nbase + C2_WH + off, (const char*)g_W3h + gsrc);
                cp16(nbase + C2_WL + off, (const char*)g_W3l + gsrc);
            }
            CP_COMMIT();
            CP_WAIT1();
        } else {
            CP_WAIT0();
        }
        __syncthreads();

#pragma unroll
        for (int k0 = 0; k0 < 64; k0 += 16) {
            uint32_t ah[2][4], al[2][4], bh[2][4], bl[2][4];
#pragma unroll
            for (int pf = 0; pf < 2; pf++) {
                uint32_t arow = (uint32_t)(pgrp*32 + pf*16 + a_sub);
                uint32_t aoff = arow * C2_RSTR + (uint32_t)(k0 + a_kh) * 2;
                ldm_x4(ah[pf], cbase + C2_XH + aoff);
                ldm_x4(al[pf], cbase + C2_XL + aoff);
            }
#pragma unroll
            for (int bn = 0; bn < 2; bn++) {
                uint32_t brow = (uint32_t)(wn*32 + bn*16 + b_sub);
                uint32_t boff = brow * C2_RSTR + (uint32_t)(k0 + b_kh) * 2;
                ldm_x4(bh[bn], cbase + C2_WH + boff);
                ldm_x4(bl[bn], cbase + C2_WL + boff);
            }
#pragma unroll
            for (int pf = 0; pf < 2; pf++)
#pragma unroll
                for (int bn = 0; bn < 2; bn++)
#pragma unroll
                    for (int j = 0; j < 2; j++) {
                        mma_f16(acc[pf][bn*2+j], ah[pf], bh[bn] + j*2);
                        mma_f16(acc[pf][bn*2+j], ah[pf], bl[bn] + j*2);
                        mma_f16(acc[pf][bn*2+j], al[pf], bh[bn] + j*2);
                    }
        }
        __syncthreads();
    }

    const int prow = lane >> 2;
#pragma unroll
    for (int pf = 0; pf < 2; pf++) {
        int p0 = pq0 + pgrp*32 + pf*16 + prow;
#pragma unroll
        for (int nf = 0; nf < 4; nf++) {
            int col = oc0 + wn*32 + nf*8 + (lane & 3)*2;
            if (p0 < NROWS) {
                g_T[(size_t)p0*NT + col]     = acc[pf][nf][0];
                g_T[(size_t)p0*NT + col + 1] = acc[pf][nf][1];
            }
            if (p0 + 8 < NROWS) {
                g_T[(size_t)(p0+8)*NT + col]     = acc[pf][nf][2];
                g_T[(size_t)(p0+8)*NT + col + 1] = acc[pf][nf][3];
            }
        }
    }
}

// ---------------- zs/zo: tanh + fp16 zs (padded to 7168 rows) ----------
__global__ void k_zszo()
{
    int pq = blockIdx.x;
    int c  = threadIdx.x;
    float zs = 0.f, zo = 0.f;
    if (pq < NPAIR) {
        int b   = pq / NPIX;
        int rem = pq - b*NPIX;
        int a1  = rem / NE;
        int a2  = rem - a1*NE;
        float a = g_attn[pq*EMBD + c];
        zs = tanhf(g_S[(b*NE + a1)*EMBD + c] + a);
        zo = tanhf(g_O[(b*NE + a2)*EMBD + c] + a);
    }
    g_zs_h[pq*EMBD + c] = __float2half(zs);
    g_zo [pq*EMBD + c] = zo;
}

// ---------------- zo transpose: g_zoT[m][pq] = fp16(g_zo[pq][m]) ----------------
__global__ void __launch_bounds__(256) k_zot()
{
    __shared__ float tile[32][33];
    int pq0 = blockIdx.x * 32;
    int m0  = blockIdx.y * 32;
    int tx = threadIdx.x & 31, ty = threadIdx.x >> 5;
    for (int r = ty; r < 32; r += 8)
        tile[r][tx] = g_zo[(size_t)(pq0 + r)*EMBD + m0 + tx];
    __syncthreads();
    for (int r = ty; r < 32; r += 8)
        g_zoT[(size_t)(m0 + r)*NPAIR_PAD + pq0 + tx] = __float2half(tile[tx][r]);
}

// ======================= final bilinear via mma.sync fp16 ======================
#define FB_ZS      0
#define FB_W       131072
#define FB_WBUF    32768
#define FB_ZO      196608
#define FB_SUMS    196608             // overlays zo (used only after final sync)
#define FB_SMEM    230400

__global__ void __launch_bounds__(256) k_final_mma(const float* __restrict__ bb,
                                                   float* __restrict__ out)
{
    extern __shared__ char smem[];
    const uint32_t sb = smem_u32(smem);
    const int tid  = threadIdx.x;
    const int lane = tid & 31;
    const int w    = tid >> 5;
    const int pgrp = w >> 1;             // 0..3  (64 p each)
    const int wm   = w & 1;              // 0..1  (32 m each within 64-m chunk)
    const int pq0  = blockIdx.x * FB_TILE;
    const int o    = blockIdx.y;

    for (int i = tid; i < 256*32; i += 256) {
        int row = i >> 5, c = i & 31;
        size_t gsrc = ((size_t)(pq0 + row) * 256 + (size_t)c * 8) * 2;
        cp16(sb + FB_ZS + SWZ(row, c), (const char*)g_zs_h + gsrc);
    }
    for (int i = tid; i < 64*32; i += 256) {
        int r = i >> 5, c = i & 31;
        size_t gsrc = ((size_t)o * 65536 + (size_t)r * 256 + (size_t)c * 8) * 2;
        cp16(sb + FB_W + SWZ(r, c), (const char*)g_Wt_h + gsrc);
    }
    CP_COMMIT();

    const int a_sub = (((lane >> 3) & 1) << 3) + (lane & 7);
    const int a_ku  = (lane >> 4) & 1;
    const int b_sub = (((lane >> 4) & 1) << 3) + (lane & 7);
    const int b_ku  = (lane >> 3) & 1;

    float psum[4][2];
#pragma unroll
    for (int pf = 0; pf < 4; pf++) { psum[pf][0] = 0.f; psum[pf][1] = 0.f; }
    const __half* zo_s = (const __half*)(smem + FB_ZO);

    for (int mc = 0; mc < 4; mc++) {
        const int cur = mc & 1, nxt = cur ^ 1;
        CP_WAIT0();
        __syncthreads();

        for (int i = tid; i < 64*32; i += 256) {
            int m = i >> 5, c = i & 31;
            uint32_t off = (uint32_t)m * 528 + (uint32_t)c * 16;
            size_t gsrc = ((size_t)(mc*64 + m) * NPAIR_PAD + pq0) * 2 + (size_t)c * 16;
            cp16(sb + FB_ZO + off, (const char*)g_zoT + gsrc);
        }
        CP_COMMIT();

        if (mc < 3) {
            for (int i = tid; i < 64*32; i += 256) {
                int r = i >> 5, c = i & 31;
                size_t gsrc = ((size_t)o * 65536 +
                               (size_t)((mc + 1) * 64 + r) * 256 + (size_t)c * 8) * 2;
                cp16(sb + FB_W + nxt*FB_WBUF + SWZ(r, c), (const char*)g_Wt_h + gsrc);
            }
            CP_COMMIT();
        }

        float acc[4][4][4];
#pragma unroll
        for (int pf = 0; pf < 4; pf++)
#pragma unroll
            for (int mf = 0; mf < 4; mf++)
#pragma unroll
                for (int q = 0; q < 4; q++) acc[pf][mf][q] = 0.f;

        const uint32_t wbase = sb + FB_W + cur*FB_WBUF;
#pragma unroll 4
        for (int k0 = 0; k0 < 256; k0 += 16) {
            uint32_t av[4][4], bv[2][4];
            const int ku = k0 >> 3;
#pragma unroll
            for (int pf = 0; pf < 4; pf++) {
                int arow = pgrp*64 + pf*16 + a_sub;
                ldm_x4(av[pf], sb + FB_ZS + SWZ(arow, ku + a_ku));
            }
#pragma unroll
            for (int bn = 0; bn < 2; bn++) {
                int brow = wm*32 + bn*16 + b_sub;
                ldm_x4(bv[bn], wbase + SWZ(brow, ku + b_ku));
            }
#pragma unroll
            for (int pf = 0; pf < 4; pf++)
#pragma unroll
                for (int bn = 0; bn < 2; bn++)
#pragma unroll
                    for (int j = 0; j < 2; j++)
                        mma_f16(acc[pf][bn*2+j], av[pf], bv[bn] + j*2);
        }

        if (mc < 3) { CP_WAIT1(); } else { CP_WAIT0(); }
        __syncthreads();

        const int mbase = wm*32 + (lane & 3)*2;
        const int prow  = (lane >> 2);
#pragma unroll
        for (int pf = 0; pf < 4; pf++) {
            int pl0 = pgrp*64 + pf*16 + prow;
#pragma unroll
            for (int mf = 0; mf < 4; mf++) {
                int ml = mbase + mf*8;
                float z0 = __half2float(zo_s[ml*264 + pl0]);
                float z1 = __half2float(zo_s[(ml+1)*264 + pl0]);
                float z2 = __half2float(zo_s[ml*264 + pl0 + 8]);
                float z3 = __half2float(zo_s[(ml+1)*264 + pl0 + 8]);
                psum[pf][0] += acc[pf][mf][0]*z0 + acc[pf][mf][1]*z1;
                psum[pf][1] += acc[pf][mf][2]*z2 + acc[pf][mf][3]*z3;
            }
        }
    }

    __syncthreads();
    float* sums = (float*)(smem + FB_SUMS);
#pragma unroll
    for (int pf = 0; pf < 4; pf++)
#pragma unroll
        for (int rh = 0; rh < 2; rh++) {
            float v = psum[pf][rh];
            v += __shfl_xor_sync(0xffffffffu, v, 1);
            v += __shfl_xor_sync(0xffffffffu, v, 2);
            if ((lane & 3) == 0) {
                int p = pgrp*64 + pf*16 + rh*8 + (lane >> 2);
                sums[p*2 + wm] = v;
            }
        }
    __syncthreads();

    {
        int pq = pq0 + tid;
        if (pq < NPAIR) {
            float tot = sums[tid*2] + sums[tid*2 + 1] + __ldg(&bb[o]);
            out[(size_t)pq*NREL + o] = tot;
        }
    }
}

// ---------------- launcher ----------------
extern "C" void kernel_launch(void* const* d_in, const int* in_sizes, int n_in,
                              void* d_out, int out_size)
{
    const float* entity  = (const float*)d_in[0];
    const float* w_red   = (const float*)d_in[1];
    const float* w_sim3  = (const float*)d_in[2];
    const float* c1w     = (const float*)d_in[3];
    const float* c1b     = (const float*)d_in[4];
    const float* c2w     = (const float*)d_in[5];
    const float* c2b     = (const float*)d_in[6];
    const float* w_lin   = (const float*)d_in[7];
    const float* b_lin   = (const float*)d_in[8];
    const float* w_s     = (const float*)d_in[9];
    const float* w_o     = (const float*)d_in[10];
    const float* w_bil   = (const float*)d_in[11];
    const float* b_bil   = (const float*)d_in[12];
    float* out = (float*)d_out;

    cudaFuncSetAttribute(k_final_mma, cudaFuncAttributeMaxDynamicSharedMemorySize,
                         FB_SMEM);
    cudaFuncSetAttribute(k_c2g, cudaFuncAttributeMaxDynamicSharedMemorySize,
                         C2_SMEM);
    cudaFuncSetAttribute(k_attn_g, cudaFuncAttributeMaxDynamicSharedMemorySize,
                         C2_SMEM);
    cudaFuncSetAttribute(k_t_g, cudaFuncAttributeMaxDynamicSharedMemorySize,
                         C2_SMEM);

    k_prep<<<(NE*EMBD*EMBD + 255)/256, 256>>>(c1w, c2w, w_sim3, w_lin);
    k_wsplit<<<dim3(64, NREL), 256>>>(w_bil);

    k_gemm_E<<<dim3((EMBD+63)/64, (NROWS+63)/64), 256>>>(entity, w_red);
    k_norms<<<NROWS, 256>>>();

    // sim3 GEMM: T[168, 10752] = e @ W3^T (fp16 3-pass, k_c2g-clone)
    k_t_g<<<dim3(2, NT/64), 256, C2_SMEM>>>();

    k_sims<<<dim3(BATCH, NE), 256>>>();
    k_sim3b<<<NROWS, 256>>>();

    k_conv1<<<dim3(BATCH, NE), 256>>>(c1b);
    k_im2col<<<dim3(BATCH, NE, 8), 256>>>();
    k_c2g<<<dim3(56, 4), 256, C2_SMEM>>>(c2b);
    k_h2split<<<NPAIR_PAD, 256>>>();

    // attn[7168, 256] = h2 @ W_lin^T + b_lin (fp16 3-pass, k_c2g-clone)
    k_attn_g<<<dim3(56, 4), 256, C2_SMEM>>>(b_lin);

    k_gemm_SO<<<dim3(EMBD/64, (NROWS+63)/64, 2), 256>>>(w_s, w_o);

    k_zszo<<<NPAIR_PAD, 256>>>();
    k_zot<<<dim3(NPAIR_PAD/32, EMBD/32), 256>>>();

    k_final_mma<<<dim3(NPAIR_PAD/FB_TILE, NREL), 256, FB_SMEM>>>(b_bil, out);
}

// round 16
// speedup vs baseline: 5.2307x; 1.0399x over previous
#include <cuda_runtime.h>
#include <cuda_fp16.h>
#include <cstdint>
#include <math.h>

#define NE    42
#define BATCH 4
#define EMBD  256
#define IN_D  768
#define NREL  97
#define NPIX  (NE*NE)          // 1764
#define NROWS (BATCH*NE)       // 168
#define NPAIR (BATCH*NPIX)     // 7056
#define FB_TILE 256
#define NPAIR_PAD (28*FB_TILE) // 7168
#define K2    2304             // conv2 GEMM K = 256*9
#define NT    (NE*EMBD)        // 10752

// ---------------- scratch (static device memory; no allocation) ----------------
__device__ float g_e   [NROWS*EMBD];
__device__ __half g_e_h[NROWS*EMBD];
__device__ __half g_e_l[NROWS*EMBD];
__device__ float g_norm[NROWS];
__device__ __half g_W3h[NE*EMBD*EMBD];             // sim3 weight permuted, fp16 hi
__device__ __half g_W3l[NE*EMBD*EMBD];             // fp16 lo
__device__ float g_T   [NROWS*NT];
__device__ float g_fm  [BATCH*3*NE*NE];
__device__ float g_w1t [27*EMBD];
__device__ float g_h1  [BATCH*EMBD*NE*NE];
__device__ float g_h2p [NPAIR_PAD*EMBD];           // conv2 out [pq][oc] fp32
__device__ __half g_h2hx[NPAIR_PAD*EMBD];          // h2 fp16 hi
__device__ __half g_h2lx[NPAIR_PAD*EMBD];          // h2 fp16 lo
__device__ __half g_wlh[EMBD*EMBD];                // W_lin fp16 hi
__device__ __half g_wll[EMBD*EMBD];                // W_lin fp16 lo
__device__ float g_attn[NPAIR_PAD*EMBD];
__device__ float g_S   [NROWS*EMBD];
__device__ float g_O   [NROWS*EMBD];
__device__ __half g_w2h[EMBD*K2];                  // conv2 weights fp16 hi
__device__ __half g_w2l[EMBD*K2];                  // conv2 weights fp16 lo
__device__ __half g_x2h[NPAIR_PAD*K2];             // im2col fp16 (hi only, 2-pass)
__device__ __half g_zs_h[NPAIR_PAD*EMBD];          // fp16 zs
__device__ float  g_zo  [NPAIR_PAD*EMBD];          // [pq][m] fp32 (transpose src)
__device__ __half g_zoT [EMBD*NPAIR_PAD];          // [m][pq] fp16
__device__ __half g_Wt_h[NREL*EMBD*EMBD];          // [o][m][n] = fp16(W_bil[o][n][m])

// ---------------- common helpers ----------------
__device__ __forceinline__ void ldm_x4(uint32_t* r, uint32_t addr) {
    asm volatile("ldmatrix.sync.aligned.m8n8.x4.shared.b16 {%0,%1,%2,%3}, [%4];"
                 : "=r"(r[0]), "=r"(r[1]), "=r"(r[2]), "=r"(r[3]) : "r"(addr));
}
__device__ __forceinline__ void mma_f16(float* c, const uint32_t* a, const uint32_t* b) {
    asm volatile("mma.sync.aligned.m16n8k16.row.col.f32.f16.f16.f32 "
                 "{%0,%1,%2,%3}, {%4,%5,%6,%7}, {%8,%9}, {%0,%1,%2,%3};"
                 : "+f"(c[0]), "+f"(c[1]), "+f"(c[2]), "+f"(c[3])
                 : "r"(a[0]), "r"(a[1]), "r"(a[2]), "r"(a[3]), "r"(b[0]), "r"(b[1]));
}
__device__ __forceinline__ uint32_t smem_u32(const void* p) {
    uint32_t a;
    asm("{ .reg .u64 t; cvta.to.shared.u64 t, %1; cvt.u32.u64 %0, t; }" : "=r"(a) : "l"(p));
    return a;
}
__device__ __forceinline__ void cp16(uint32_t dst, const void* src) {
    asm volatile("cp.async.cg.shared.global [%0], [%1], 16;" :: "r"(dst), "l"(src));
}
#define CP_COMMIT() asm volatile("cp.async.commit_group;" ::: "memory")
#define CP_WAIT0()  asm volatile("cp.async.wait_group 0;" ::: "memory")
#define CP_WAIT1()  asm volatile("cp.async.wait_group 1;" ::: "memory")
// swizzled offset within a 512B row: 16B unit c (0..31), unit' = c ^ (row&7)
#define SWZ(row, c) ((uint32_t)(row) * 512u + (uint32_t)(((c) ^ ((row) & 7)) * 16))

// ---------------- prep: conv1 permute + fp16 splits (conv2, W_lin) -------------
__global__ void k_prep(const float* __restrict__ c1w,
                       const float* __restrict__ c2w,
                       const float* __restrict__ wlin)
{
    int i = blockIdx.x * 256 + threadIdx.x;
    if (i < 27*EMBD) {
        int oc = i & 255, k = i >> 8;
        g_w1t[i] = c1w[oc*27 + k];
    }
    if (i < EMBD*EMBD) {
        float v = wlin[i];
        __half hi = __float2half(v);
        g_wlh[i] = hi;
        g_wll[i] = __float2half(v - __half2float(hi));
    }
    if (i < EMBD*K2) {
        float v = c2w[i];
        __half hi = __float2half(v);
        g_w2h[i] = hi;
        g_w2l[i] = __float2half(v - __half2float(hi));
    }
}

// ---------------- prep: W3 transpose -> fp16 hi/lo (coalesced, tiled) ----------
// dst[(j*256+m)*256+n] = wsim3[j][n][m]
__global__ void __launch_bounds__(256) k_w3split(const float* __restrict__ wsim3)
{
    __shared__ float tile[32][33];
    int j = blockIdx.y;
    int t = blockIdx.x;
    int m0 = (t & 7) * 32, n0 = (t >> 3) * 32;
    int tx = threadIdx.x & 31, ty = threadIdx.x >> 5;
    for (int rr = ty; rr < 32; rr += 8)
        tile[rr][tx] = wsim3[(size_t)j*65536 + (n0+rr)*256 + (m0+tx)];
    __syncthreads();
    for (int rr = ty; rr < 32; rr += 8) {
        float v = tile[tx][rr];                 // = wsim3[j][n0+tx][m0+rr]
        size_t di = (size_t)j*65536 + (size_t)(m0+rr)*256 + (n0+tx);
        __half hi = __float2half(v);
        g_W3h[di] = hi;
        g_W3l[di] = __float2half(v - __half2float(hi));
    }
}

// ---------------- prep: W_bil transpose -> fp16 ----------------
__global__ void __launch_bounds__(256) k_wsplit(const float* __restrict__ wbil)
{
    __shared__ float tile[32][33];
    int o = blockIdx.y;
    int t = blockIdx.x;
    int m0 = (t & 7) * 32, n0 = (t >> 3) * 32;
    int tx = threadIdx.x & 31, ty = threadIdx.x >> 5;
    for (int rr = ty; rr < 32; rr += 8)
        tile[rr][tx] = wbil[(size_t)o*65536 + (n0+rr)*256 + (m0+tx)];
    __syncthreads();
    for (int rr = ty; rr < 32; rr += 8) {
        float v = tile[tx][rr];                 // = w[o][n0+tx][m0+rr]
        size_t di = (size_t)o*65536 + (size_t)(m0+rr)*256 + (n0+tx);
        g_Wt_h[di] = __float2half(v);
    }
}

// ---------------- shared tiled SGEMM-NT (small cases: E, S, O) ----------------
__device__ __forceinline__ void gemm_nt_dev(
    const float* __restrict__ A, const float* __restrict__ W,
    float* __restrict__ C, const float* __restrict__ bias,
    int M, int N, int K)
{
    __shared__ float As[16][68];
    __shared__ float Bs[16][68];
    const int tid = threadIdx.x;
    const int tx = tid & 15, ty = tid >> 4;
    const int m0 = blockIdx.y * 64, n0 = blockIdx.x * 64;
    float acc[4][4];
#pragma unroll
    for (int i = 0; i < 4; i++)
#pragma unroll
        for (int j = 0; j < 4; j++) acc[i][j] = 0.f;

    for (int k0 = 0; k0 < K; k0 += 16) {
        for (int e = tid; e < 1024; e += 256) {
            int kk = e & 15, m = e >> 4;
            int gm = m0 + m;
            As[kk][m] = (gm < M) ? A[gm * K + k0 + kk] : 0.f;
        }
        for (int e = tid; e < 1024; e += 256) {
            int kk = e & 15, n = e >> 4;
            int gn = n0 + n;
            Bs[kk][n] = (gn < N) ? W[gn * K + k0 + kk] : 0.f;
        }
        __syncthreads();
#pragma unroll
        for (int kk = 0; kk < 16; kk++) {
            float a0 = As[kk][ty*4+0], a1 = As[kk][ty*4+1];
            float a2 = As[kk][ty*4+2], a3 = As[kk][ty*4+3];
            float b0 = Bs[kk][tx*4+0], b1 = Bs[kk][tx*4+1];
            float b2 = Bs[kk][tx*4+2], b3 = Bs[kk][tx*4+3];
            acc[0][0] += a0*b0; acc[0][1] += a0*b1; acc[0][2] += a0*b2; acc[0][3] += a0*b3;
            acc[1][0] += a1*b0; acc[1][1] += a1*b1; acc[1][2] += a1*b2; acc[1][3] += a1*b3;
            acc[2][0] += a2*b0; acc[2][1] += a2*b1; acc[2][2] += a2*b2; acc[2][3] += a2*b3;
            acc[3][0] += a3*b0; acc[3][1] += a3*b1; acc[3][2] += a3*b2; acc[3][3] += a3*b3;
        }
        __syncthreads();
    }
#pragma unroll
    for (int i = 0; i < 4; i++) {
        int gm = m0 + ty*4 + i;
        if (gm >= M) continue;
#pragma unroll
        for (int j = 0; j < 4; j++) {
            int gn = n0 + tx*4 + j;
            if (gn < N)
                C[gm * N + gn] = acc[i][j] + (bias ? bias[gn] : 0.f);
        }
    }
}

__global__ void __launch_bounds__(256) k_gemm_E(const float* __restrict__ ent,
                                                const float* __restrict__ wred)
{ gemm_nt_dev(ent, wred, g_e, nullptr, NROWS, EMBD, IN_D); }

__global__ void __launch_bounds__(256) k_gemm_SO(const float* __restrict__ ws,
                                                 const float* __restrict__ wo)
{
    if (blockIdx.z == 0)
        gemm_nt_dev(g_e, ws, g_S, nullptr, NROWS, EMBD, EMBD);
    else
        gemm_nt_dev(g_e, wo, g_O, nullptr, NROWS, EMBD, EMBD);
}

// ---------------- norms + e fp16 split ----------------
__global__ void k_norms()
{
    int bi = blockIdx.x;
    int tid = threadIdx.x;
    float v = g_e[bi*EMBD + tid];
    __half hi = __float2half(v);
    g_e_h[bi*EMBD + tid] = hi;
    g_e_l[bi*EMBD + tid] = __float2half(v - __half2float(hi));
    float s = v * v;
    __shared__ float red[8];
    for (int off = 16; off; off >>= 1) s += __shfl_down_sync(0xffffffffu, s, off);
    if ((tid & 31) == 0) red[tid >> 5] = s;
    __syncthreads();
    if (tid == 0) {
        float t = 0.f;
#pragma unroll
        for (int i = 0; i < 8; i++) t += red[i];
        g_norm[bi] = sqrtf(t);
    }
}

// ---------------- sim1/sim2 ----------------
__global__ void k_sims()
{
    int b = blockIdx.x, H = blockIdx.y;
    int tid = threadIdx.x, lane = tid & 31, wid = tid >> 5;
    __shared__ float eH[EMBD];
    eH[tid] = g_e[(b*NE + H)*EMBD + tid];
    __syncthreads();
    float nH = fmaxf(g_norm[b*NE + H], 1e-6f);
    for (int Wc = wid; Wc < NE; Wc += 8) {
        const float* eW = &g_e[(b*NE + Wc)*EMBD];
        float s = 0.f;
        for (int k = lane; k < EMBD; k += 32) s += eH[k] * eW[k];
        for (int off = 16; off; off >>= 1) s += __shfl_down_sync(0xffffffffu, s, off);
        if (lane == 0) {
            float nW = fmaxf(g_norm[b*NE + Wc], 1e-6f);
            g_fm[((b*3 + 0)*NE + H)*NE + Wc] = s;
            g_fm[((b*3 + 1)*NE + H)*NE + Wc] = s / (nH * nW);
        }
    }
}

// ---------------- sim3 epilogue ----------------
__global__ void k_sim3b()
{
    int bi = blockIdx.x;
    int tid = threadIdx.x, lane = tid & 31, wid = tid >> 5;
    __shared__ float ev[EMBD];
    ev[tid] = g_e[bi*EMBD + tid];
    __syncthreads();
    int b = bi / NE, r = bi - b*NE;
    for (int j = wid; j < NE; j += 8) {
        const float* Trow = &g_T[bi*NT + j*EMBD];
        float s = 0.f;
        for (int k = lane; k < EMBD; k += 32) s += Trow[k] * ev[k];
        for (int off = 16; off; off >>= 1) s += __shfl_down_sync(0xffffffffu, s, off);
        if (lane == 0) g_fm[((b*3 + 2)*NE + j)*NE + r] = s;
    }
}

// ---------------- conv1 ----------------
__global__ void __launch_bounds__(256) k_conv1(const float* __restrict__ b1)
{
    int b = blockIdx.x, H = blockIdx.y;
    int oc = threadIdx.x;
    __shared__ float sm[3][3][44];
    for (int idx = threadIdx.x; idx < 396; idx += 256) {
        int ch = idx / 132, rem = idx - ch*132;
        int r = rem / 44, w = rem - r*44;
        int y = H + r - 1, x = w - 1;
        float v = 0.f;
        if (y >= 0 && y < NE && x >= 0 && x < NE)
            v = g_fm[((b*3 + ch)*NE + y)*NE + x];
        sm[ch][r][w] = v;
    }
    __syncthreads();
    float wreg[27];
#pragma unroll
    for (int k = 0; k < 27; k++) wreg[k] = g_w1t[k*EMBD + oc];
    float acc[NE];
    float bias = b1[oc];
#pragma unroll
    for (int W = 0; W < NE; W++) acc[W] = bias;
#pragma unroll
    for (int ch = 0; ch < 3; ch++)
#pragma unroll
    for (int ky = 0; ky < 3; ky++) {
        const float* row = sm[ch][ky];
        float w0 = wreg[(ch*3+ky)*3+0];
        float w1 = wreg[(ch*3+ky)*3+1];
        float w2 = wreg[(ch*3+ky)*3+2];
        float r0 = row[0], r1 = row[1];
#pragma unroll
        for (int W = 0; W < NE; W++) {
            float r2 = row[W + 2];
            acc[W] += w0*r0 + w1*r1 + w2*r2;
            r0 = r1; r1 = r2;
        }
    }
    int base = ((b*EMBD + oc)*NE + H)*NE;
#pragma unroll
    for (int W = 0; W < NE; W++) g_h1[base + W] = fmaxf(acc[W], 0.f);
}

// ---------------- im2col (fp16 hi only; conv2 is 2-pass) ----------------
__global__ void __launch_bounds__(256) k_im2col()
{
    int b = blockIdx.x, H = blockIdx.y, icg = blockIdx.z;
    __shared__ float sm[32][3][44];
    for (int idx = threadIdx.x; idx < 4224; idx += 256) {
        int ic = idx / 132, rem = idx - ic*132;
        int r = rem / 44, w = rem - r*44;
        int y = H + r - 1, x = w - 1;
        float v = 0.f;
        if (y >= 0 && y < NE && x >= 0 && x < NE)
            v = g_h1[((b*EMBD + icg*32 + ic)*NE + y)*NE + x];
        sm[ic][r][w] = v;
    }
    __syncthreads();
    for (int idx = threadIdx.x; idx < 42*288; idx += 256) {
        int W = idx / 288, rem = idx - W*288;
        int ic = rem / 9, k = rem - ic*9;
        int dy = k / 3, dx = k - dy*3;
        float v = sm[ic][dy][W + dx];
        size_t di = (size_t)(b*NPIX + H*NE + W) * K2 + (size_t)(icg*32 + ic)*9 + k;
        g_x2h[di] = __float2half(v);
    }
}

// ---------------- conv2 GEMM: h2p = Xh @ (W2h+W2l)^T + b2 (2-pass fp16) --------
#define C2_XH   0
#define C2_WH   18432              // 128 rows * 144 B
#define C2_WL   27648              // + 64 rows * 144 B
#define C2_BUF  36864
#define C2_SMEM (2*C2_BUF)         // 73728 -> 2 CTAs/SM possible
#define C2_RSTR 144

__global__ void __launch_bounds__(256) k_c2g(const float* __restrict__ b2)
{
    extern __shared__ char smem[];
    const uint32_t sb = smem_u32(smem);
    const int tid  = threadIdx.x;
    const int lane = tid & 31;
    const int w    = tid >> 5;
    const int pgrp = w >> 1;
    const int wn   = w & 1;
    const int pq0  = blockIdx.x * 128;
    const int oc0  = blockIdx.y * 64;

    const int a_sub = (((lane >> 3) & 1) << 3) + (lane & 7);
    const int a_kh  = ((lane >> 4) & 1) << 3;
    const int b_sub = (((lane >> 4) & 1) << 3) + (lane & 7);
    const int b_kh  = ((lane >> 3) & 1) << 3;

    {
        const uint32_t base = sb;
        for (int i = tid; i < 1024; i += 256) {
            int r = i >> 3, c = i & 7;
            uint32_t off = (uint32_t)r * C2_RSTR + (uint32_t)c * 16;
            size_t gsrc = ((size_t)(pq0 + r) * K2 + (size_t)c * 8) * 2;
            cp16(base + C2_XH + off, (const char*)g_x2h + gsrc);
        }
        for (int i = tid; i < 512; i += 256) {
            int r = i >> 3, c = i & 7;
            uint32_t off = (uint32_t)r * C2_RSTR + (uint32_t)c * 16;
            size_t gsrc = ((size_t)(oc0 + r) * K2 + (size_t)c * 8) * 2;
            cp16(base + C2_WH + off, (const char*)g_w2h + gsrc);
            cp16(base + C2_WL + off, (const char*)g_w2l + gsrc);
        }
        CP_COMMIT();
    }

    float acc[2][4][4];
#pragma unroll
    for (int pf = 0; pf < 2; pf++)
#pragma unroll
        for (int nf = 0; nf < 4; nf++)
#pragma unroll
            for (int q = 0; q < 4; q++) acc[pf][nf][q] = 0.f;

    for (int kc = 0; kc < 36; kc++) {
        const uint32_t cbase = sb + (kc & 1) * C2_BUF;

        if (kc < 35) {
            const uint32_t nbase = sb + ((kc + 1) & 1) * C2_BUF;
            int koff = (kc + 1) * 64;
            for (int i = tid; i < 1024; i += 256) {
                int r = i >> 3, c = i & 7;
                uint32_t off = (uint32_t)r * C2_RSTR + (uint32_t)c * 16;
                size_t gsrc = ((size_t)(pq0 + r) * K2 + koff + (size_t)c * 8) * 2;
                cp16(nbase + C2_XH + off, (const char*)g_x2h + gsrc);
            }
            for (int i = tid; i < 512; i += 256) {
                int r = i >> 3, c = i & 7;
                uint32_t off = (uint32_t)r * C2_RSTR + (uint32_t)c * 16;
                size_t gsrc = ((size_t)(oc0 + r) * K2 + koff + (size_t)c * 8) * 2;
                cp16(nbase + C2_WH + off, (const char*)g_w2h + gsrc);
                cp16(nbase + C2_WL + off, (const char*)g_w2l + gsrc);
            }
            CP_COMMIT();
            CP_WAIT1();
        } else {
            CP_WAIT0();
        }
        __syncthreads();

#pragma unroll
        for (int k0 = 0; k0 < 64; k0 += 16) {
            uint32_t ah[2][4], bh[2][4], bl[2][4];
#pragma unroll
            for (int pf = 0; pf < 2; pf++) {
                uint32_t arow = (uint32_t)(pgrp*32 + pf*16 + a_sub);
                uint32_t aoff = arow * C2_RSTR + (uint32_t)(k0 + a_kh) * 2;
                ldm_x4(ah[pf], cbase + C2_XH + aoff);
            }
#pragma unroll
            for (int bn = 0; bn < 2; bn++) {
                uint32_t brow = (uint32_t)(wn*32 + bn*16 + b_sub);
                uint32_t boff = brow * C2_RSTR + (uint32_t)(k0 + b_kh) * 2;
                ldm_x4(bh[bn], cbase + C2_WH + boff);
                ldm_x4(bl[bn], cbase + C2_WL + boff);
            }
#pragma unroll
            for (int pf = 0; pf < 2; pf++)
#pragma unroll
                for (int bn = 0; bn < 2; bn++)
#pragma unroll
                    for (int j = 0; j < 2; j++) {
                        mma_f16(acc[pf][bn*2+j], ah[pf], bh[bn] + j*2);
                        mma_f16(acc[pf][bn*2+j], ah[pf], bl[bn] + j*2);
                    }
        }
        __syncthreads();
    }

    const int prow = lane >> 2;
#pragma unroll
    for (int pf = 0; pf < 2; pf++) {
        int p0 = pq0 + pgrp*32 + pf*16 + prow;
#pragma unroll
        for (int nf = 0; nf < 4; nf++) {
            int col = oc0 + wn*32 + nf*8 + (lane & 3)*2;
            float bias0 = __ldg(&b2[col]);
            float bias1 = __ldg(&b2[col + 1]);
            g_h2p[(size_t)p0*EMBD + col]       = acc[pf][nf][0] + bias0;
            g_h2p[(size_t)p0*EMBD + col + 1]   = acc[pf][nf][1] + bias1;
            g_h2p[(size_t)(p0+8)*EMBD + col]   = acc[pf][nf][2] + bias0;
            g_h2p[(size_t)(p0+8)*EMBD + col+1] = acc[pf][nf][3] + bias1;
        }
    }
}

// ---------------- h2 fp16 split ----------------
__global__ void k_h2split()
{
    size_t i = (size_t)blockIdx.x * 256 + threadIdx.x;
    float v = g_h2p[i];
    __half hi = __float2half(v);
    g_h2hx[i] = hi;
    g_h2lx[i] = __float2half(v - __half2float(hi));
}

// ------- attn GEMM (k_c2g clone, K=256 in 4 chunks, 3-pass): attn = h2 @ Wlin^T -
#define A2_XH   0
#define A2_XL   18432
#define A2_WH   36864
#define A2_WL   46080
#define A2_BUF  55296
#define A2_SMEM (2*A2_BUF)         // 110592

__global__ void __launch_bounds__(256) k_attn_g(const float* __restrict__ blin)
{
    extern __shared__ char smem[];
    const uint32_t sb = smem_u32(smem);
    const int tid  = threadIdx.x;
    const int lane = tid & 31;
    const int w    = tid >> 5;
    const int pgrp = w >> 1;
    const int wn   = w & 1;
    const int pq0  = blockIdx.x * 128;
    const int oc0  = blockIdx.y * 64;

    const int a_sub = (((lane >> 3) & 1) << 3) + (lane & 7);
    const int a_kh  = ((lane >> 4) & 1) << 3;
    const int b_sub = (((lane >> 4) & 1) << 3) + (lane & 7);
    const int b_kh  = ((lane >> 3) & 1) << 3;

    {
        const uint32_t base = sb;
        for (int i = tid; i < 1024; i += 256) {
            int r = i >> 3, c = i & 7;
            uint32_t off = (uint32_t)r * C2_RSTR + (uint32_t)c * 16;
            size_t gsrc = ((size_t)(pq0 + r) * EMBD + (size_t)c * 8) * 2;
            cp16(base + A2_XH + off, (const char*)g_h2hx + gsrc);
            cp16(base + A2_XL + off, (const char*)g_h2lx + gsrc);
        }
        for (int i = tid; i < 512; i += 256) {
            int r = i >> 3, c = i & 7;
            uint32_t off = (uint32_t)r * C2_RSTR + (uint32_t)c * 16;
            size_t gsrc = ((size_t)(oc0 + r) * EMBD + (size_t)c * 8) * 2;
            cp16(base + A2_WH + off, (const char*)g_wlh + gsrc);
            cp16(base + A2_WL + off, (const char*)g_wll + gsrc);
        }
        CP_COMMIT();
    }

    float acc[2][4][4];
#pragma unroll
    for (int pf = 0; pf < 2; pf++)
#pragma unroll
        for (int nf = 0; nf < 4; nf++)
#pragma unroll
            for (int q = 0; q < 4; q++) acc[pf][nf][q] = 0.f;

    for (int kc = 0; kc < 4; kc++) {
        const uint32_t cbase = sb + (kc & 1) * A2_BUF;

        if (kc < 3) {
            const uint32_t nbase = sb + ((kc + 1) & 1) * A2_BUF;
            int koff = (kc + 1) * 64;
            for (int i = tid; i < 1024; i += 256) {
                int r = i >> 3, c = i & 7;
                uint32_t off = (uint32_t)r * C2_RSTR + (uint32_t)c * 16;
                size_t gsrc = ((size_t)(pq0 + r) * EMBD + koff + (size_t)c * 8) * 2;
                cp16(nbase + A2_XH + off, (const char*)g_h2hx + gsrc);
                cp16(nbase + A2_XL + off, (const char*)g_h2lx + gsrc);
            }
            for (int i = tid; i < 512; i += 256) {
                int r = i >> 3, c = i & 7;
                uint32_t off = (uint32_t)r * C2_RSTR + (uint32_t)c * 16;
                size_t gsrc = ((size_t)(oc0 + r) * EMBD + koff + (size_t)c * 8) * 2;
                cp16(nbase + A2_WH + off, (const char*)g_wlh + gsrc);
                cp16(nbase + A2_WL + off, (const char*)g_wll + gsrc);
            }
            CP_COMMIT();
            CP_WAIT1();
        } else {
            CP_WAIT0();
        }
        __syncthreads();

#pragma unroll
        for (int k0 = 0; k0 < 64; k0 += 16) {
            uint32_t ah[2][4], al[2][4], bh[2][4], bl[2][4];
#pragma unroll
            for (int pf = 0; pf < 2; pf++) {
                uint32_t arow = (uint32_t)(pgrp*32 + pf*16 + a_sub);
                uint32_t aoff = arow * C2_RSTR + (uint32_t)(k0 + a_kh) * 2;
                ldm_x4(ah[pf], cbase + A2_XH + aoff);
                ldm_x4(al[pf], cbase + A2_XL + aoff);
            }
#pragma unroll
            for (int bn = 0; bn < 2; bn++) {
                uint32_t brow = (uint32_t)(wn*32 + bn*16 + b_sub);
                uint32_t boff = brow * C2_RSTR + (uint32_t)(k0 + b_kh) * 2;
                ldm_x4(bh[bn], cbase + A2_WH + boff);
                ldm_x4(bl[bn], cbase + A2_WL + boff);
            }
#pragma unroll
            for (int pf = 0; pf < 2; pf++)
#pragma unroll
                for (int bn = 0; bn < 2; bn++)
#pragma unroll
                    for (int j = 0; j < 2; j++) {
                        mma_f16(acc[pf][bn*2+j], ah[pf], bh[bn] + j*2);
                        mma_f16(acc[pf][bn*2+j], ah[pf], bl[bn] + j*2);
                        mma_f16(acc[pf][bn*2+j], al[pf], bh[bn] + j*2);
                    }
        }
        __syncthreads();
    }

    const int prow = lane >> 2;
#pragma unroll
    for (int pf = 0; pf < 2; pf++) {
        int p0 = pq0 + pgrp*32 + pf*16 + prow;
#pragma unroll
        for (int nf = 0; nf < 4; nf++) {
            int col = oc0 + wn*32 + nf*8 + (lane & 3)*2;
            float bias0 = __ldg(&blin[col]);
            float bias1 = __ldg(&blin[col + 1]);
            g_attn[(size_t)p0*EMBD + col]       = acc[pf][nf][0] + bias0;
            g_attn[(size_t)p0*EMBD + col + 1]   = acc[pf][nf][1] + bias1;
            g_attn[(size_t)(p0+8)*EMBD + col]   = acc[pf][nf][2] + bias0;
            g_attn[(size_t)(p0+8)*EMBD + col+1] = acc[pf][nf][3] + bias1;
        }
    }
}

// ------- sim3 GEMM (k_c2g clone, K=256 in 4 chunks, 3-pass): T = e @ W3^T -------
__global__ void __launch_bounds__(256) k_t_g()
{
    extern __shared__ char smem[];
    const uint32_t sb = smem_u32(smem);
    const int tid  = threadIdx.x;
    const int lane = tid & 31;
    const int w    = tid >> 5;
    const int pgrp = w >> 1;
    const int wn   = w & 1;
    const int pq0  = blockIdx.x * 128;       // rows of e (0 or 128)
    const int oc0  = blockIdx.y * 64;        // cols of T (0..10688)

    const int a_sub = (((lane >> 3) & 1) << 3) + (lane & 7);
    const int a_kh  = ((lane >> 4) & 1) << 3;
    const int b_sub = (((lane >> 4) & 1) << 3) + (lane & 7);
    const int b_kh  = ((lane >> 3) & 1) << 3;

    {
        const uint32_t base = sb;
        for (int i = tid; i < 1024; i += 256) {
            int r = i >> 3, c = i & 7;
            int gm = pq0 + r; if (gm > NROWS-1) gm = NROWS-1;
            uint32_t off = (uint32_t)r * C2_RSTR + (uint32_t)c * 16;
            size_t gsrc = ((size_t)gm * EMBD + (size_t)c * 8) * 2;
            cp16(base + A2_XH + off, (const char*)g_e_h + gsrc);
            cp16(base + A2_XL + off, (const char*)g_e_l + gsrc);
        }
        for (int i = tid; i < 512; i += 256) {
            int r = i >> 3, c = i & 7;
            uint32_t off = (uint32_t)r * C2_RSTR + (uint32_t)c * 16;
            size_t gsrc = ((size_t)(oc0 + r) * EMBD + (size_t)c * 8) * 2;
            cp16(base + A2_WH + off, (const char*)g_W3h + gsrc);
            cp16(base + A2_WL + off, (const char*)g_W3l + gsrc);
        }
        CP_COMMIT();
    }

    float acc[2][4][4];
#pragma unroll
    for (int pf = 0; pf < 2; pf++)
#pragma unroll
        for (int nf = 0; nf < 4; nf++)
#pragma unroll
            for (int q = 0; q < 4; q++) acc[pf][nf][q] = 0.f;

    for (int kc = 0; kc < 4; kc++) {
        const uint32_t cbase = sb + (kc & 1) * A2_BUF;

        if (kc < 3) {
            const uint32_t nbase = sb + ((kc + 1) & 1) * A2_BUF;
            int koff = (kc + 1) * 64;
            for (int i = tid; i < 1024; i += 256) {
                int r = i >> 3, c = i & 7;
                int gm = pq0 + r; if (gm > NROWS-1) gm = NROWS-1;
                uint32_t off = (uint32_t)r * C2_RSTR + (uint32_t)c * 16;
                size_t gsrc = ((size_t)gm * EMBD + koff + (size_t)c * 8) * 2;
                cp16(nbase + A2_XH + off, (const char*)g_e_h + gsrc);
                cp16(nbase + A2_XL + off, (const char*)g_e_l + gsrc);
            }
            for (int i = tid; i < 512; i += 256) {
                int r = i >> 3, c = i & 7;
                uint32_t off = (uint32_t)r * C2_RSTR + (uint32_t)c * 16;
                size_t gsrc = ((size_t)(oc0 + r) * EMBD + koff + (size_t)c * 8) * 2;
                cp16(nbase + A2_WH + off, (const char*)g_W3h + gsrc);
                cp16(nbase + A2_WL + off, (const char*)g_W3l + gsrc);
            }
            CP_COMMIT();
            CP_WAIT1();
        } else {
            CP_WAIT0();
        }
        __syncthreads();

#pragma unroll
        for (int k0 = 0; k0 < 64; k0 += 16) {
            uint32_t ah[2][4], al[2][4], bh[2][4], bl[2][4];
#pragma unroll
            for (int pf = 0; pf < 2; pf++) {
                uint32_t arow = (uint32_t)(pgrp*32 + pf*16 + a_sub);
                uint32_t aoff = arow * C2_RSTR + (uint32_t)(k0 + a_kh) * 2;
                ldm_x4(ah[pf], cbase + A2_XH + aoff);
                ldm_x4(al[pf], cbase + A2_XL + aoff);
            }
#pragma unroll
            for (int bn = 0; bn < 2; bn++) {
                uint32_t brow = (uint32_t)(wn*32 + bn*16 + b_sub);
                uint32_t boff = brow * C2_RSTR + (uint32_t)(k0 + b_kh) * 2;
                ldm_x4(bh[bn], cbase + A2_WH + boff);
                ldm_x4(bl[bn], cbase + A2_WL + boff);
            }
#pragma unroll
            for (int pf = 0; pf < 2; pf++)
#pragma unroll
                for (int bn = 0; bn < 2; bn++)
#pragma unroll
                    for (int j = 0; j < 2; j++) {
                        mma_f16(acc[pf][bn*2+j], ah[pf], bh[bn] + j*2);
                        mma_f16(acc[pf][bn*2+j], ah[pf], bl[bn] + j*2);
                        mma_f16(acc[pf][bn*2+j], al[pf], bh[bn] + j*2);
                    }
        }
        __syncthreads();
    }

    const int prow = lane >> 2;
#pragma unroll
    for (int pf = 0; pf < 2; pf++) {
        int p0 = pq0 + pgrp*32 + pf*16 + prow;
#pragma unroll
        for (int nf = 0; nf < 4; nf++) {
            int col = oc0 + wn*32 + nf*8 + (lane & 3)*2;
            if (p0 < NROWS) {
                g_T[(size_t)p0*NT + col]     = acc[pf][nf][0];
                g_T[(size_t)p0*NT + col + 1] = acc[pf][nf][1];
            }
            if (p0 + 8 < NROWS) {
                g_T[(size_t)(p0+8)*NT + col]     = acc[pf][nf][2];
                g_T[(size_t)(p0+8)*NT + col + 1] = acc[pf][nf][3];
            }
        }
    }
}

// ---------------- zs/zo: tanh + fp16 zs (padded to 7168 rows) ----------
__global__ void k_zszo()
{
    int pq = blockIdx.x;
    int c  = threadIdx.x;
    float zs = 0.f, zo = 0.f;
    if (pq < NPAIR) {
        int b   = pq / NPIX;
        int rem = pq - b*NPIX;
        int a1  = rem / NE;
        int a2  = rem - a1*NE;
        float a = g_attn[pq*EMBD + c];
        zs = tanhf(g_S[(b*NE + a1)*EMBD + c] + a);
        zo = tanhf(g_O[(b*NE + a2)*EMBD + c] + a);
    }
    g_zs_h[pq*EMBD + c] = __float2half(zs);
    g_zo [pq*EMBD + c] = zo;
}

// ---------------- zo transpose: g_zoT[m][pq] = fp16(g_zo[pq][m]) ----------------
__global__ void __launch_bounds__(256) k_zot()
{
    __shared__ float tile[32][33];
    int pq0 = blockIdx.x * 32;
    int m0  = blockIdx.y * 32;
    int tx = threadIdx.x & 31, ty = threadIdx.x >> 5;
    for (int r = ty; r < 32; r += 8)
        tile[r][tx] = g_zo[(size_t)(pq0 + r)*EMBD + m0 + tx];
    __syncthreads();
    for (int r = ty; r < 32; r += 8)
        g_zoT[(size_t)(m0 + r)*NPAIR_PAD + pq0 + tx] = __float2half(tile[tx][r]);
}

// ======================= final bilinear via mma.sync fp16 ======================
#define FB_ZS      0
#define FB_W       131072
#define FB_WBUF    32768
#define FB_ZO      196608
#define FB_SUMS    196608             // overlays zo (used only after final sync)
#define FB_SMEM    230400

__global__ void __launch_bounds__(256) k_final_mma(const float* __restrict__ bb,
                                                   float* __restrict__ out)
{
    extern __shared__ char smem[];
    const uint32_t sb = smem_u32(smem);
    const int tid  = threadIdx.x;
    const int lane = tid & 31;
    const int w    = tid >> 5;
    const int pgrp = w >> 1;             // 0..3  (64 p each)
    const int wm   = w & 1;              // 0..1  (32 m each within 64-m chunk)
    const int pq0  = blockIdx.x * FB_TILE;
    const int o    = blockIdx.y;

    for (int i = tid; i < 256*32; i += 256) {
        int row = i >> 5, c = i & 31;
        size_t gsrc = ((size_t)(pq0 + row) * 256 + (size_t)c * 8) * 2;
        cp16(sb + FB_ZS + SWZ(row, c), (const char*)g_zs_h + gsrc);
    }
    for (int i = tid; i < 64*32; i += 256) {
        int r = i >> 5, c = i & 31;
        size_t gsrc = ((size_t)o * 65536 + (size_t)r * 256 + (size_t)c * 8) * 2;
        cp16(sb + FB_W + SWZ(r, c), (const char*)g_Wt_h + gsrc);
    }
    CP_COMMIT();

    const int a_sub = (((lane >> 3) & 1) << 3) + (lane & 7);
    const int a_ku  = (lane >> 4) & 1;
    const int b_sub = (((lane >> 4) & 1) << 3) + (lane & 7);
    const int b_ku  = (lane >> 3) & 1;

    float psum[4][2];
#pragma unroll
    for (int pf = 0; pf < 4; pf++) { psum[pf][0] = 0.f; psum[pf][1] = 0.f; }
    const __half* zo_s = (const __half*)(smem + FB_ZO);

    for (int mc = 0; mc < 4; mc++) {
        const int cur = mc & 1, nxt = cur ^ 1;
        CP_WAIT0();
        __syncthreads();

        for (int i = tid; i < 64*32; i += 256) {
            int m = i >> 5, c = i & 31;
            uint32_t off = (uint32_t)m * 528 + (uint32_t)c * 16;
            size_t gsrc = ((size_t)(mc*64 + m) * NPAIR_PAD + pq0) * 2 + (size_t)c * 16;
            cp16(sb + FB_ZO + off, (const char*)g_zoT + gsrc);
        }
        CP_COMMIT();

        if (mc < 3) {
            for (int i = tid; i < 64*32; i += 256) {
                int r = i >> 5, c = i & 31;
                size_t gsrc = ((size_t)o * 65536 +
                               (size_t)((mc + 1) * 64 + r) * 256 + (size_t)c * 8) * 2;
                cp16(sb + FB_W + nxt*FB_WBUF + SWZ(r, c), (const char*)g_Wt_h + gsrc);
            }
            CP_COMMIT();
        }

        float acc[4][4][4];
#pragma unroll
        for (int pf = 0; pf < 4; pf++)
#pragma unroll
            for (int mf = 0; mf < 4; mf++)
#pragma unroll
                for (int q = 0; q < 4; q++) acc[pf][mf][q] = 0.f;

        const uint32_t wbase = sb + FB_W + cur*FB_WBUF;
#pragma unroll 4
        for (int k0 = 0; k0 < 256; k0 += 16) {
            uint32_t av[4][4], bv[2][4];
            const int ku = k0 >> 3;
#pragma unroll
            for (int pf = 0; pf < 4; pf++) {
                int arow = pgrp*64 + pf*16 + a_sub;
                ldm_x4(av[pf], sb + FB_ZS + SWZ(arow, ku + a_ku));
            }
#pragma unroll
            for (int bn = 0; bn < 2; bn++) {
                int brow = wm*32 + bn*16 + b_sub;
                ldm_x4(bv[bn], wbase + SWZ(brow, ku + b_ku));
            }
#pragma unroll
            for (int pf = 0; pf < 4; pf++)
#pragma unroll
                for (int bn = 0; bn < 2; bn++)
#pragma unroll
                    for (int j = 0; j < 2; j++)
                        mma_f16(acc[pf][bn*2+j], av[pf], bv[bn] + j*2);
        }

        if (mc < 3) { CP_WAIT1(); } else { CP_WAIT0(); }
        __syncthreads();

        const int mbase = wm*32 + (lane & 3)*2;
        const int prow  = (lane >> 2);
#pragma unroll
        for (int pf = 0; pf < 4; pf++) {
            int pl0 = pgrp*64 + pf*16 + prow;
#pragma unroll
            for (int mf = 0; mf < 4; mf++) {
                int ml = mbase + mf*8;
                float z0 = __half2float(zo_s[ml*264 + pl0]);
                float z1 = __half2float(zo_s[(ml+1)*264 + pl0]);
                float z2 = __half2float(zo_s[ml*264 + pl0 + 8]);
                float z3 = __half2float(zo_s[(ml+1)*264 + pl0 + 8]);
                psum[pf][0] += acc[pf][mf][0]*z0 + acc[pf][mf][1]*z1;
                psum[pf][1] += acc[pf][mf][2]*z2 + acc[pf][mf][3]*z3;
            }
        }
    }

    __syncthreads();
    float* sums = (float*)(smem + FB_SUMS);
#pragma unroll
    for (int pf = 0; pf < 4; pf++)
#pragma unroll
        for (int rh = 0; rh < 2; rh++) {
            float v = psum[pf][rh];
            v += __shfl_xor_sync(0xffffffffu, v, 1);
            v += __shfl_xor_sync(0xffffffffu, v, 2);
            if ((lane & 3) == 0) {
                int p = pgrp*64 + pf*16 + rh*8 + (lane >> 2);
                sums[p*2 + wm] = v;
            }
        }
    __syncthreads();

    {
        int pq = pq0 + tid;
        if (pq < NPAIR) {
            float tot = sums[tid*2] + sums[tid*2 + 1] + __ldg(&bb[o]);
            out[(size_t)pq*NREL + o] = tot;
        }
    }
}

// ---------------- launcher ----------------
extern "C" void kernel_launch(void* const* d_in, const int* in_sizes, int n_in,
                              void* d_out, int out_size)
{
    const float* entity  = (const float*)d_in[0];
    const float* w_red   = (const float*)d_in[1];
    const float* w_sim3  = (const float*)d_in[2];
    const float* c1w     = (const float*)d_in[3];
    const float* c1b     = (const float*)d_in[4];
    const float* c2w     = (const float*)d_in[5];
    const float* c2b     = (const float*)d_in[6];
    const float* w_lin   = (const float*)d_in[7];
    const float* b_lin   = (const float*)d_in[8];
    const float* w_s     = (const float*)d_in[9];
    const float* w_o     = (const float*)d_in[10];
    const float* w_bil   = (const float*)d_in[11];
    const float* b_bil   = (const float*)d_in[12];
    float* out = (float*)d_out;

    cudaFuncSetAttribute(k_final_mma, cudaFuncAttributeMaxDynamicSharedMemorySize,
                         FB_SMEM);
    cudaFuncSetAttribute(k_c2g, cudaFuncAttributeMaxDynamicSharedMemorySize,
                         C2_SMEM);
    cudaFuncSetAttribute(k_attn_g, cudaFuncAttributeMaxDynamicSharedMemorySize,
                         A2_SMEM);
    cudaFuncSetAttribute(k_t_g, cudaFuncAttributeMaxDynamicSharedMemorySize,
                         A2_SMEM);

    k_prep<<<(EMBD*K2 + 255)/256, 256>>>(c1w, c2w, w_lin);
    k_w3split<<<dim3(64, NE), 256>>>(w_sim3);
    k_wsplit<<<dim3(64, NREL), 256>>>(w_bil);

    k_gemm_E<<<dim3((EMBD+63)/64, (NROWS+63)/64), 256>>>(entity, w_red);
    k_norms<<<NROWS, 256>>>();

    // sim3 GEMM: T[168, 10752] = e @ W3^T (fp16 3-pass, k_c2g-clone)
    k_t_g<<<dim3(2, NT/64), 256, A2_SMEM>>>();

    k_sims<<<dim3(BATCH, NE), 256>>>();
    k_sim3b<<<NROWS, 256>>>();

    k_conv1<<<dim3(BATCH, NE), 256>>>(c1b);
    k_im2col<<<dim3(BATCH, NE, 8), 256>>>();
    k_c2g<<<dim3(56, 4), 256, C2_SMEM>>>(c2b);
    k_h2split<<<NPAIR_PAD, 256>>>();

    // attn[7168, 256] = h2 @ W_lin^T + b_lin (fp16 3-pass, k_c2g-clone)
    k_attn_g<<<dim3(56, 4), 256, A2_SMEM>>>(b_lin);

    k_gemm_SO<<<dim3(EMBD/64, (NROWS+63)/64, 2), 256>>>(w_s, w_o);

    k_zszo<<<NPAIR_PAD, 256>>>();
    k_zot<<<dim3(NPAIR_PAD/32, EMBD/32), 256>>>();

    k_final_mma<<<dim3(NPAIR_PAD/FB_TILE, NREL), 256, FB_SMEM>>>(b_bil, out);
}

// round 17
// speedup vs baseline: 6.6304x; 1.2676x over previous
#include <cuda_runtime.h>
#include <cuda_fp16.h>
#include <cstdint>
#include <math.h>

#define NE    42
#define BATCH 4
#define EMBD  256
#define IN_D  768
#define NREL  97
#define NPIX  (NE*NE)          // 1764
#define NROWS (BATCH*NE)       // 168
#define NPAIR (BATCH*NPIX)     // 7056
#define FB_TILE 256
#define NPAIR_PAD (28*FB_TILE) // 7168
#define K2    2304             // conv2 GEMM K = 256*9
#define NT    (NE*EMBD)        // 10752
#define NEL   (NROWS*EMBD)     // 43008

// ---------------- scratch (static device memory; no allocation) ----------------
__device__ float g_pE  [6*NEL];                    // split-K partials for e
__device__ float g_pS  [4*NEL];
__device__ float g_pO  [4*NEL];
__device__ float g_e   [NEL];
__device__ __half g_e_h[NEL];
__device__ __half g_e_l[NEL];
__device__ float g_norm[NROWS];
__device__ __half g_W3h[NE*EMBD*EMBD];             // sim3 weight permuted, fp16 hi
__device__ __half g_W3l[NE*EMBD*EMBD];             // fp16 lo
__device__ float g_T   [NROWS*NT];
__device__ float g_fm  [BATCH*3*NE*NE];
__device__ float g_w1t [27*EMBD];
__device__ float g_h1  [BATCH*EMBD*NE*NE];
__device__ float g_h2p [NPAIR_PAD*EMBD];           // conv2 out [pq][oc] fp32
__device__ __half g_h2hx[NPAIR_PAD*EMBD];          // h2 fp16 hi
__device__ __half g_h2lx[NPAIR_PAD*EMBD];          // h2 fp16 lo
__device__ __half g_wlh[EMBD*EMBD];                // W_lin fp16 hi
__device__ __half g_wll[EMBD*EMBD];                // W_lin fp16 lo
__device__ float g_attn[NPAIR_PAD*EMBD];
__device__ float g_S   [NEL];
__device__ float g_O   [NEL];
__device__ __half g_w2h[EMBD*K2];                  // conv2 weights fp16 hi
__device__ __half g_w2l[EMBD*K2];                  // conv2 weights fp16 lo
__device__ __half g_x2h[NPAIR_PAD*K2];             // im2col fp16 (hi only, 2-pass)
__device__ __half g_zs_h[NPAIR_PAD*EMBD];          // fp16 zs
__device__ float  g_zo  [NPAIR_PAD*EMBD];          // [pq][m] fp32 (transpose src)
__device__ __half g_zoT [EMBD*NPAIR_PAD];          // [m][pq] fp16
__device__ __half g_Wt_h[NREL*EMBD*EMBD];          // [o][m][n] = fp16(W_bil[o][n][m])

// ---------------- common helpers ----------------
__device__ __forceinline__ void ldm_x4(uint32_t* r, uint32_t addr) {
    asm volatile("ldmatrix.sync.aligned.m8n8.x4.shared.b16 {%0,%1,%2,%3}, [%4];"
                 : "=r"(r[0]), "=r"(r[1]), "=r"(r[2]), "=r"(r[3]) : "r"(addr));
}
__device__ __forceinline__ void mma_f16(float* c, const uint32_t* a, const uint32_t* b) {
    asm volatile("mma.sync.aligned.m16n8k16.row.col.f32.f16.f16.f32 "
                 "{%0,%1,%2,%3}, {%4,%5,%6,%7}, {%8,%9}, {%0,%1,%2,%3};"
                 : "+f"(c[0]), "+f"(c[1]), "+f"(c[2]), "+f"(c[3])
                 : "r"(a[0]), "r"(a[1]), "r"(a[2]), "r"(a[3]), "r"(b[0]), "r"(b[1]));
}
__device__ __forceinline__ uint32_t smem_u32(const void* p) {
    uint32_t a;
    asm("{ .reg .u64 t; cvta.to.shared.u64 t, %1; cvt.u32.u64 %0, t; }" : "=r"(a) : "l"(p));
    return a;
}
__device__ __forceinline__ void cp16(uint32_t dst, const void* src) {
    asm volatile("cp.async.cg.shared.global [%0], [%1], 16;" :: "r"(dst), "l"(src));
}
#define CP_COMMIT() asm volatile("cp.async.commit_group;" ::: "memory")
#define CP_WAIT0()  asm volatile("cp.async.wait_group 0;" ::: "memory")
#define CP_WAIT1()  asm volatile("cp.async.wait_group 1;" ::: "memory")
// swizzled offset within a 512B row: 16B unit c (0..31), unit' = c ^ (row&7)
#define SWZ(row, c) ((uint32_t)(row) * 512u + (uint32_t)(((c) ^ ((row) & 7)) * 16))

// ---------------- prep: conv1 permute + fp16 splits (conv2, W_lin) -------------
__global__ void k_prep(const float* __restrict__ c1w,
                       const float* __restrict__ c2w,
                       const float* __restrict__ wlin)
{
    int i = blockIdx.x * 256 + threadIdx.x;
    if (i < 27*EMBD) {
        int oc = i & 255, k = i >> 8;
        g_w1t[i] = c1w[oc*27 + k];
    }
    if (i < EMBD*EMBD) {
        float v = wlin[i];
        __half hi = __float2half(v);
        g_wlh[i] = hi;
        g_wll[i] = __float2half(v - __half2float(hi));
    }
    if (i < EMBD*K2) {
        float v = c2w[i];
        __half hi = __float2half(v);
        g_w2h[i] = hi;
        g_w2l[i] = __float2half(v - __half2float(hi));
    }
}

// ---------------- prep: W3 transpose -> fp16 hi/lo (coalesced, tiled) ----------
__global__ void __launch_bounds__(256) k_w3split(const float* __restrict__ wsim3)
{
    __shared__ float tile[32][33];
    int j = blockIdx.y;
    int t = blockIdx.x;
    int m0 = (t & 7) * 32, n0 = (t >> 3) * 32;
    int tx = threadIdx.x & 31, ty = threadIdx.x >> 5;
    for (int rr = ty; rr < 32; rr += 8)
        tile[rr][tx] = wsim3[(size_t)j*65536 + (n0+rr)*256 + (m0+tx)];
    __syncthreads();
    for (int rr = ty; rr < 32; rr += 8) {
        float v = tile[tx][rr];                 // = wsim3[j][n0+tx][m0+rr]
        size_t di = (size_t)j*65536 + (size_t)(m0+rr)*256 + (n0+tx);
        __half hi = __float2half(v);
        g_W3h[di] = hi;
        g_W3l[di] = __float2half(v - __half2float(hi));
    }
}

// ---------------- prep: W_bil transpose -> fp16 ----------------
__global__ void __launch_bounds__(256) k_wsplit(const float* __restrict__ wbil)
{
    __shared__ float tile[32][33];
    int o = blockIdx.y;
    int t = blockIdx.x;
    int m0 = (t & 7) * 32, n0 = (t >> 3) * 32;
    int tx = threadIdx.x & 31, ty = threadIdx.x >> 5;
    for (int rr = ty; rr < 32; rr += 8)
        tile[rr][tx] = wbil[(size_t)o*65536 + (n0+rr)*256 + (m0+tx)];
    __syncthreads();
    for (int rr = ty; rr < 32; rr += 8) {
        float v = tile[tx][rr];                 // = w[o][n0+tx][m0+rr]
        size_t di = (size_t)o*65536 + (size_t)(m0+rr)*256 + (n0+tx);
        g_Wt_h[di] = __float2half(v);
    }
}

// ---------------- split-K tiled SGEMM-NT partial: C = A[,kbeg:kend] * W^T -------
__device__ __forceinline__ void gemm_nt_part(
    const float* __restrict__ A, const float* __restrict__ W,
    float* __restrict__ C, int M, int N, int K, int kbeg, int kend)
{
    __shared__ float As[16][68];
    __shared__ float Bs[16][68];
    const int tid = threadIdx.x;
    const int tx = tid & 15, ty = tid >> 4;
    const int m0 = blockIdx.y * 64, n0 = blockIdx.x * 64;
    float acc[4][4];
#pragma unroll
    for (int i = 0; i < 4; i++)
#pragma unroll
        for (int j = 0; j < 4; j++) acc[i][j] = 0.f;

    for (int k0 = kbeg; k0 < kend; k0 += 16) {
        for (int e = tid; e < 1024; e += 256) {
            int kk = e & 15, m = e >> 4;
            int gm = m0 + m;
            As[kk][m] = (gm < M) ? A[gm * K + k0 + kk] : 0.f;
        }
        for (int e = tid; e < 1024; e += 256) {
            int kk = e & 15, n = e >> 4;
            int gn = n0 + n;
            Bs[kk][n] = (gn < N) ? W[gn * K + k0 + kk] : 0.f;
        }
        __syncthreads();
#pragma unroll
        for (int kk = 0; kk < 16; kk++) {
            float a0 = As[kk][ty*4+0], a1 = As[kk][ty*4+1];
            float a2 = As[kk][ty*4+2], a3 = As[kk][ty*4+3];
            float b0 = Bs[kk][tx*4+0], b1 = Bs[kk][tx*4+1];
            float b2 = Bs[kk][tx*4+2], b3 = Bs[kk][tx*4+3];
            acc[0][0] += a0*b0; acc[0][1] += a0*b1; acc[0][2] += a0*b2; acc[0][3] += a0*b3;
            acc[1][0] += a1*b0; acc[1][1] += a1*b1; acc[1][2] += a1*b2; acc[1][3] += a1*b3;
            acc[2][0] += a2*b0; acc[2][1] += a2*b1; acc[2][2] += a2*b2; acc[2][3] += a2*b3;
            acc[3][0] += a3*b0; acc[3][1] += a3*b1; acc[3][2] += a3*b2; acc[3][3] += a3*b3;
        }
        __syncthreads();
    }
#pragma unroll
    for (int i = 0; i < 4; i++) {
        int gm = m0 + ty*4 + i;
        if (gm >= M) continue;
#pragma unroll
        for (int j = 0; j < 4; j++) {
            int gn = n0 + tx*4 + j;
            if (gn < N)
                C[gm * N + gn] = acc[i][j];
        }
    }
}

// split-K=6 (chunks of 128) entity reduce: partials into g_pE[z]
__global__ void __launch_bounds__(256) k_gemm_E(const float* __restrict__ ent,
                                                const float* __restrict__ wred)
{
    int z = blockIdx.z;
    gemm_nt_part(ent, wred, g_pE + (size_t)z*NEL, NROWS, EMBD, IN_D,
                 z*128, (z+1)*128);
}

// split-K=4 (chunks of 64) S/O projections: z<4 -> S, z>=4 -> O
__global__ void __launch_bounds__(256) k_gemm_SO(const float* __restrict__ ws,
                                                 const float* __restrict__ wo)
{
    int z = blockIdx.z;
    if (z < 4)
        gemm_nt_part(g_e, ws, g_pS + (size_t)z*NEL, NROWS, EMBD, EMBD,
                     z*64, (z+1)*64);
    else
        gemm_nt_part(g_e, wo, g_pO + (size_t)(z-4)*NEL, NROWS, EMBD, EMBD,
                     (z-4)*64, (z-3)*64);
}

// ---------------- S/O partial combine ----------------
__global__ void k_socomb()
{
    int i = blockIdx.x * 256 + threadIdx.x;
    float s = 0.f, o = 0.f;
#pragma unroll
    for (int z = 0; z < 4; z++) {
        s += g_pS[(size_t)z*NEL + i];
        o += g_pO[(size_t)z*NEL + i];
    }
    g_S[i] = s;
    g_O[i] = o;
}

// ---------------- norms + e combine + fp16 split ----------------
__global__ void k_norms()
{
    int bi = blockIdx.x;
    int tid = threadIdx.x;
    int idx = bi*EMBD + tid;
    float v = 0.f;
#pragma unroll
    for (int z = 0; z < 6; z++) v += g_pE[(size_t)z*NEL + idx];
    g_e[idx] = v;
    __half hi = __float2half(v);
    g_e_h[idx] = hi;
    g_e_l[idx] = __float2half(v - __half2float(hi));
    float s = v * v;
    __shared__ float red[8];
    for (int off = 16; off; off >>= 1) s += __shfl_down_sync(0xffffffffu, s, off);
    if ((tid & 31) == 0) red[tid >> 5] = s;
    __syncthreads();
    if (tid == 0) {
        float t = 0.f;
#pragma unroll
        for (int i = 0; i < 8; i++) t += red[i];
        g_norm[bi] = sqrtf(t);
    }
}

// ---------------- sim1/sim2 ----------------
__global__ void k_sims()
{
    int b = blockIdx.x, H = blockIdx.y;
    int tid = threadIdx.x, lane = tid & 31, wid = tid >> 5;
    __shared__ float eH[EMBD];
    eH[tid] = g_e[(b*NE + H)*EMBD + tid];
    __syncthreads();
    float nH = fmaxf(g_norm[b*NE + H], 1e-6f);
    for (int Wc = wid; Wc < NE; Wc += 8) {
        const float* eW = &g_e[(b*NE + Wc)*EMBD];
        float s = 0.f;
        for (int k = lane; k < EMBD; k += 32) s += eH[k] * eW[k];
        for (int off = 16; off; off >>= 1) s += __shfl_down_sync(0xffffffffu, s, off);
        if (lane == 0) {
            float nW = fmaxf(g_norm[b*NE + Wc], 1e-6f);
            g_fm[((b*3 + 0)*NE + H)*NE + Wc] = s;
            g_fm[((b*3 + 1)*NE + H)*NE + Wc] = s / (nH * nW);
        }
    }
}

// ---------------- sim3 epilogue ----------------
__global__ void k_sim3b()
{
    int bi = blockIdx.x;
    int tid = threadIdx.x, lane = tid & 31, wid = tid >> 5;
    __shared__ float ev[EMBD];
    ev[tid] = g_e[bi*EMBD + tid];
    __syncthreads();
    int b = bi / NE, r = bi - b*NE;
    for (int j = wid; j < NE; j += 8) {
        const float* Trow = &g_T[bi*NT + j*EMBD];
        float s = 0.f;
        for (int k = lane; k < EMBD; k += 32) s += Trow[k] * ev[k];
        for (int off = 16; off; off >>= 1) s += __shfl_down_sync(0xffffffffu, s, off);
        if (lane == 0) g_fm[((b*3 + 2)*NE + j)*NE + r] = s;
    }
}

// ---------------- conv1 ----------------
__global__ void __launch_bounds__(256) k_conv1(const float* __restrict__ b1)
{
    int b = blockIdx.x, H = blockIdx.y;
    int oc = threadIdx.x;
    __shared__ float sm[3][3][44];
    for (int idx = threadIdx.x; idx < 396; idx += 256) {
        int ch = idx / 132, rem = idx - ch*132;
        int r = rem / 44, w = rem - r*44;
        int y = H + r - 1, x = w - 1;
        float v = 0.f;
        if (y >= 0 && y < NE && x >= 0 && x < NE)
            v = g_fm[((b*3 + ch)*NE + y)*NE + x];
        sm[ch][r][w] = v;
    }
    __syncthreads();
    float wreg[27];
#pragma unroll
    for (int k = 0; k < 27; k++) wreg[k] = g_w1t[k*EMBD + oc];
    float acc[NE];
    float bias = b1[oc];
#pragma unroll
    for (int W = 0; W < NE; W++) acc[W] = bias;
#pragma unroll
    for (int ch = 0; ch < 3; ch++)
#pragma unroll
    for (int ky = 0; ky < 3; ky++) {
        const float* row = sm[ch][ky];
        float w0 = wreg[(ch*3+ky)*3+0];
        float w1 = wreg[(ch*3+ky)*3+1];
        float w2 = wreg[(ch*3+ky)*3+2];
        float r0 = row[0], r1 = row[1];
#pragma unroll
        for (int W = 0; W < NE; W++) {
            float r2 = row[W + 2];
            acc[W] += w0*r0 + w1*r1 + w2*r2;
            r0 = r1; r1 = r2;
        }
    }
    int base = ((b*EMBD + oc)*NE + H)*NE;
#pragma unroll
    for (int W = 0; W < NE; W++) g_h1[base + W] = fmaxf(acc[W], 0.f);
}

// ---------------- im2col (fp16 hi only; conv2 is 2-pass) ----------------
__global__ void __launch_bounds__(256) k_im2col()
{
    int b = blockIdx.x, H = blockIdx.y, icg = blockIdx.z;
    __shared__ float sm[32][3][44];
    for (int idx = threadIdx.x; idx < 4224; idx += 256) {
        int ic = idx / 132, rem = idx - ic*132;
        int r = rem / 44, w = rem - r*44;
        int y = H + r - 1, x = w - 1;
        float v = 0.f;
        if (y >= 0 && y < NE && x >= 0 && x < NE)
            v = g_h1[((b*EMBD + icg*32 + ic)*NE + y)*NE + x];
        sm[ic][r][w] = v;
    }
    __syncthreads();
    for (int idx = threadIdx.x; idx < 42*288; idx += 256) {
        int W = idx / 288, rem = idx - W*288;
        int ic = rem / 9, k = rem - ic*9;
        int dy = k / 3, dx = k - dy*3;
        float v = sm[ic][dy][W + dx];
        size_t di = (size_t)(b*NPIX + H*NE + W) * K2 + (size_t)(icg*32 + ic)*9 + k;
        g_x2h[di] = __float2half(v);
    }
}

// ---------------- conv2 GEMM: h2p = Xh @ (W2h+W2l)^T + b2 (2-pass fp16) --------
#define C2_XH   0
#define C2_WH   18432              // 128 rows * 144 B
#define C2_WL   27648              // + 64 rows * 144 B
#define C2_BUF  36864
#define C2_SMEM (2*C2_BUF)         // 73728 -> 2 CTAs/SM possible
#define C2_RSTR 144

__global__ void __launch_bounds__(256) k_c2g(const float* __restrict__ b2)
{
    extern __shared__ char smem[];
    const uint32_t sb = smem_u32(smem);
    const int tid  = threadIdx.x;
    const int lane = tid & 31;
    const int w    = tid >> 5;
    const int pgrp = w >> 1;
    const int wn   = w & 1;
    const int pq0  = blockIdx.x * 128;
    const int oc0  = blockIdx.y * 64;

    const int a_sub = (((lane >> 3) & 1) << 3) + (lane & 7);
    const int a_kh  = ((lane >> 4) & 1) << 3;
    const int b_sub = (((lane >> 4) & 1) << 3) + (lane & 7);
    const int b_kh  = ((lane >> 3) & 1) << 3;

    {
        const uint32_t base = sb;
        for (int i = tid; i < 1024; i += 256) {
            int r = i >> 3, c = i & 7;
            uint32_t off = (uint32_t)r * C2_RSTR + (uint32_t)c * 16;
            size_t gsrc = ((size_t)(pq0 + r) * K2 + (size_t)c * 8) * 2;
            cp16(base + C2_XH + off, (const char*)g_x2h + gsrc);
        }
        for (int i = tid; i < 512; i += 256) {
            int r = i >> 3, c = i & 7;
            uint32_t off = (uint32_t)r * C2_RSTR + (uint32_t)c * 16;
            size_t gsrc = ((size_t)(oc0 + r) * K2 + (size_t)c * 8) * 2;
            cp16(base + C2_WH + off, (const char*)g_w2h + gsrc);
            cp16(base + C2_WL + off, (const char*)g_w2l + gsrc);
        }
        CP_COMMIT();
    }

    float acc[2][4][4];
#pragma unroll
    for (int pf = 0; pf < 2; pf++)
#pragma unroll
        for (int nf = 0; nf < 4; nf++)
#pragma unroll
            for (int q = 0; q < 4; q++) acc[pf][nf][q] = 0.f;

    for (int kc = 0; kc < 36; kc++) {
        const uint32_t cbase = sb + (kc & 1) * C2_BUF;

        if (kc < 35) {
            const uint32_t nbase = sb + ((kc + 1) & 1) * C2_BUF;
            int koff = (kc + 1) * 64;
            for (int i = tid; i < 1024; i += 256) {
                int r = i >> 3, c = i & 7;
                uint32_t off = (uint32_t)r * C2_RSTR + (uint32_t)c * 16;
                size_t gsrc = ((size_t)(pq0 + r) * K2 + koff + (size_t)c * 8) * 2;
                cp16(nbase + C2_XH + off, (const char*)g_x2h + gsrc);
            }
            for (int i = tid; i < 512; i += 256) {
                int r = i >> 3, c = i & 7;
                uint32_t off = (uint32_t)r * C2_RSTR + (uint32_t)c * 16;
                size_t gsrc = ((size_t)(oc0 + r) * K2 + koff + (size_t)c * 8) * 2;
                cp16(nbase + C2_WH + off, (const char*)g_w2h + gsrc);
                cp16(nbase + C2_WL + off, (const char*)g_w2l + gsrc);
            }
            CP_COMMIT();
            CP_WAIT1();
        } else {
            CP_WAIT0();
        }
        __syncthreads();

#pragma unroll
        for (int k0 = 0; k0 < 64; k0 += 16) {
            uint32_t ah[2][4], bh[2][4], bl[2][4];
#pragma unroll
            for (int pf = 0; pf < 2; pf++) {
                uint32_t arow = (uint32_t)(pgrp*32 + pf*16 + a_sub);
                uint32_t aoff = arow * C2_RSTR + (uint32_t)(k0 + a_kh) * 2;
                ldm_x4(ah[pf], cbase + C2_XH + aoff);
            }
#pragma unroll
            for (int bn = 0; bn < 2; bn++) {
                uint32_t brow = (uint32_t)(wn*32 + bn*16 + b_sub);
                uint32_t boff = brow * C2_RSTR + (uint32_t)(k0 + b_kh) * 2;
                ldm_x4(bh[bn], cbase + C2_WH + boff);
                ldm_x4(bl[bn], cbase + C2_WL + boff);
            }
#pragma unroll
            for (int pf = 0; pf < 2; pf++)
#pragma unroll
                for (int bn = 0; bn < 2; bn++)
#pragma unroll
                    for (int j = 0; j < 2; j++) {
                        mma_f16(acc[pf][bn*2+j], ah[pf], bh[bn] + j*2);
                        mma_f16(acc[pf][bn*2+j], ah[pf], bl[bn] + j*2);
                    }
        }
        __syncthreads();
    }

    const int prow = lane >> 2;
#pragma unroll
    for (int pf = 0; pf < 2; pf++) {
        int p0 = pq0 + pgrp*32 + pf*16 + prow;
#pragma unroll
        for (int nf = 0; nf < 4; nf++) {
            int col = oc0 + wn*32 + nf*8 + (lane & 3)*2;
            float bias0 = __ldg(&b2[col]);
            float bias1 = __ldg(&b2[col + 1]);
            g_h2p[(size_t)p0*EMBD + col]       = acc[pf][nf][0] + bias0;
            g_h2p[(size_t)p0*EMBD + col + 1]   = acc[pf][nf][1] + bias1;
            g_h2p[(size_t)(p0+8)*EMBD + col]   = acc[pf][nf][2] + bias0;
            g_h2p[(size_t)(p0+8)*EMBD + col+1] = acc[pf][nf][3] + bias1;
        }
    }
}

// ---------------- h2 fp16 split ----------------
__global__ void k_h2split()
{
    size_t i = (size_t)blockIdx.x * 256 + threadIdx.x;
    float v = g_h2p[i];
    __half hi = __float2half(v);
    g_h2hx[i] = hi;
    g_h2lx[i] = __float2half(v - __half2float(hi));
}

// ------- attn GEMM (k_c2g clone, K=256 in 4 chunks, 3-pass): attn = h2 @ Wlin^T -
#define A2_XH   0
#define A2_XL   18432
#define A2_WH   36864
#define A2_WL   46080
#define A2_BUF  55296
#define A2_SMEM (2*A2_BUF)         // 110592

__global__ void __launch_bounds__(256) k_attn_g(const float* __restrict__ blin)
{
    extern __shared__ char smem[];
    const uint32_t sb = smem_u32(smem);
    const int tid  = threadIdx.x;
    const int lane = tid & 31;
    const int w    = tid >> 5;
    const int pgrp = w >> 1;
    const int wn   = w & 1;
    const int pq0  = blockIdx.x * 128;
    const int oc0  = blockIdx.y * 64;

    const int a_sub = (((lane >> 3) & 1) << 3) + (lane & 7);
    const int a_kh  = ((lane >> 4) & 1) << 3;
    const int b_sub = (((lane >> 4) & 1) << 3) + (lane & 7);
    const int b_kh  = ((lane >> 3) & 1) << 3;

    {
        const uint32_t base = sb;
        for (int i = tid; i < 1024; i += 256) {
            int r = i >> 3, c = i & 7;
            uint32_t off = (uint32_t)r * C2_RSTR + (uint32_t)c * 16;
            size_t gsrc = ((size_t)(pq0 + r) * EMBD + (size_t)c * 8) * 2;
            cp16(base + A2_XH + off, (const char*)g_h2hx + gsrc);
            cp16(base + A2_XL + off, (const char*)g_h2lx + gsrc);
        }
        for (int i = tid; i < 512; i += 256) {
            int r = i >> 3, c = i & 7;
            uint32_t off = (uint32_t)r * C2_RSTR + (uint32_t)c * 16;
            size_t gsrc = ((size_t)(oc0 + r) * EMBD + (size_t)c * 8) * 2;
            cp16(base + A2_WH + off, (const char*)g_wlh + gsrc);
            cp16(base + A2_WL + off, (const char*)g_wll + gsrc);
        }
        CP_COMMIT();
    }

    float acc[2][4][4];
#pragma unroll
    for (int pf = 0; pf < 2; pf++)
#pragma unroll
        for (int nf = 0; nf < 4; nf++)
#pragma unroll
            for (int q = 0; q < 4; q++) acc[pf][nf][q] = 0.f;

    for (int kc = 0; kc < 4; kc++) {
        const uint32_t cbase = sb + (kc & 1) * A2_BUF;

        if (kc < 3) {
            const uint32_t nbase = sb + ((kc + 1) & 1) * A2_BUF;
            int koff = (kc + 1) * 64;
            for (int i = tid; i < 1024; i += 256) {
                int r = i >> 3, c = i & 7;
                uint32_t off = (uint32_t)r * C2_RSTR + (uint32_t)c * 16;
                size_t gsrc = ((size_t)(pq0 + r) * EMBD + koff + (size_t)c * 8) * 2;
                cp16(nbase + A2_XH + off, (const char*)g_h2hx + gsrc);
                cp16(nbase + A2_XL + off, (const char*)g_h2lx + gsrc);
            }
            for (int i = tid; i < 512; i += 256) {
                int r = i >> 3, c = i & 7;
                uint32_t off = (uint32_t)r * C2_RSTR + (uint32_t)c * 16;
                size_t gsrc = ((size_t)(oc0 + r) * EMBD + koff + (size_t)c * 8) * 2;
                cp16(nbase + A2_WH + off, (const char*)g_wlh + gsrc);
                cp16(nbase + A2_WL + off, (const char*)g_wll + gsrc);
            }
            CP_COMMIT();
            CP_WAIT1();
        } else {
            CP_WAIT0();
        }
        __syncthreads();

#pragma unroll
        for (int k0 = 0; k0 < 64; k0 += 16) {
            uint32_t ah[2][4], al[2][4], bh[2][4], bl[2][4];
#pragma unroll
            for (int pf = 0; pf < 2; pf++) {
                uint32_t arow = (uint32_t)(pgrp*32 + pf*16 + a_sub);
                uint32_t aoff = arow * C2_RSTR + (uint32_t)(k0 + a_kh) * 2;
                ldm_x4(ah[pf], cbase + A2_XH + aoff);
                ldm_x4(al[pf], cbase + A2_XL + aoff);
            }
#pragma unroll
            for (int bn = 0; bn < 2; bn++) {
                uint32_t brow = (uint32_t)(wn*32 + bn*16 + b_sub);
                uint32_t boff = brow * C2_RSTR + (uint32_t)(k0 + b_kh) * 2;
                ldm_x4(bh[bn], cbase + A2_WH + boff);
                ldm_x4(bl[bn], cbase + A2_WL + boff);
            }
#pragma unroll
            for (int pf = 0; pf < 2; pf++)
#pragma unroll
                for (int bn = 0; bn < 2; bn++)
#pragma unroll
                    for (int j = 0; j < 2; j++) {
                        mma_f16(acc[pf][bn*2+j], ah[pf], bh[bn] + j*2);
                        mma_f16(acc[pf][bn*2+j], ah[pf], bl[bn] + j*2);
                        mma_f16(acc[pf][bn*2+j], al[pf], bh[bn] + j*2);
                    }
        }
        __syncthreads();
    }

    const int prow = lane >> 2;
#pragma unroll
    for (int pf = 0; pf < 2; pf++) {
        int p0 = pq0 + pgrp*32 + pf*16 + prow;
#pragma unroll
        for (int nf = 0; nf < 4; nf++) {
            int col = oc0 + wn*32 + nf*8 + (lane & 3)*2;
            float bias0 = __ldg(&blin[col]);
            float bias1 = __ldg(&blin[col + 1]);
            g_attn[(size_t)p0*EMBD + col]       = acc[pf][nf][0] + bias0;
            g_attn[(size_t)p0*EMBD + col + 1]   = acc[pf][nf][1] + bias1;
            g_attn[(size_t)(p0+8)*EMBD + col]   = acc[pf][nf][2] + bias0;
            g_attn[(size_t)(p0+8)*EMBD + col+1] = acc[pf][nf][3] + bias1;
        }
    }
}

// ------- sim3 GEMM (k_c2g clone, K=256 in 4 chunks, 3-pass): T = e @ W3^T -------
__global__ void __launch_bounds__(256) k_t_g()
{
    extern __shared__ char smem[];
    const uint32_t sb = smem_u32(smem);
    const int tid  = threadIdx.x;
    const int lane = tid & 31;
    const int w    = tid >> 5;
    const int pgrp = w >> 1;
    const int wn   = w & 1;
    const int pq0  = blockIdx.x * 128;       // rows of e (0 or 128)
    const int oc0  = blockIdx.y * 64;        // cols of T (0..10688)

    const int a_sub = (((lane >> 3) & 1) << 3) + (lane & 7);
    const int a_kh  = ((lane >> 4) & 1) << 3;
    const int b_sub = (((lane >> 4) & 1) << 3) + (lane & 7);
    const int b_kh  = ((lane >> 3) & 1) << 3;

    {
        const uint32_t base = sb;
        for (int i = tid; i < 1024; i += 256) {
            int r = i >> 3, c = i & 7;
            int gm = pq0 + r; if (gm > NROWS-1) gm = NROWS-1;
            uint32_t off = (uint32_t)r * C2_RSTR + (uint32_t)c * 16;
            size_t gsrc = ((size_t)gm * EMBD + (size_t)c * 8) * 2;
            cp16(base + A2_XH + off, (const char*)g_e_h + gsrc);
            cp16(base + A2_XL + off, (const char*)g_e_l + gsrc);
        }
        for (int i = tid; i < 512; i += 256) {
            int r = i >> 3, c = i & 7;
            uint32_t off = (uint32_t)r * C2_RSTR + (uint32_t)c * 16;
            size_t gsrc = ((size_t)(oc0 + r) * EMBD + (size_t)c * 8) * 2;
            cp16(base + A2_WH + off, (const char*)g_W3h + gsrc);
            cp16(base + A2_WL + off, (const char*)g_W3l + gsrc);
        }
        CP_COMMIT();
    }

    float acc[2][4][4];
#pragma unroll
    for (int pf = 0; pf < 2; pf++)
#pragma unroll
        for (int nf = 0; nf < 4; nf++)
#pragma unroll
            for (int q = 0; q < 4; q++) acc[pf][nf][q] = 0.f;

    for (int kc = 0; kc < 4; kc++) {
        const uint32_t cbase = sb + (kc & 1) * A2_BUF;

        if (kc < 3) {
            const uint32_t nbase = sb + ((kc + 1) & 1) * A2_BUF;
            int koff = (kc + 1) * 64;
            for (int i = tid; i < 1024; i += 256) {
                int r = i >> 3, c = i & 7;
                int gm = pq0 + r; if (gm > NROWS-1) gm = NROWS-1;
                uint32_t off = (uint32_t)r * C2_RSTR + (uint32_t)c * 16;
                size_t gsrc = ((size_t)gm * EMBD + koff + (size_t)c * 8) * 2;
                cp16(nbase + A2_XH + off, (const char*)g_e_h + gsrc);
                cp16(nbase + A2_XL + off, (const char*)g_e_l + gsrc);
            }
            for (int i = tid; i < 512; i += 256) {
                int r = i >> 3, c = i & 7;
                uint32_t off = (uint32_t)r * C2_RSTR + (uint32_t)c * 16;
                size_t gsrc = ((size_t)(oc0 + r) * EMBD + koff + (size_t)c * 8) * 2;
                cp16(nbase + A2_WH + off, (const char*)g_W3h + gsrc);
                cp16(nbase + A2_WL + off, (const char*)g_W3l + gsrc);
            }
            CP_COMMIT();
            CP_WAIT1();
        } else {
            CP_WAIT0();
        }
        __syncthreads();

#pragma unroll
        for (int k0 = 0; k0 < 64; k0 += 16) {
            uint32_t ah[2][4], al[2][4], bh[2][4], bl[2][4];
#pragma unroll
            for (int pf = 0; pf < 2; pf++) {
                uint32_t arow = (uint32_t)(pgrp*32 + pf*16 + a_sub);
                uint32_t aoff = arow * C2_RSTR + (uint32_t)(k0 + a_kh) * 2;
                ldm_x4(ah[pf], cbase + A2_XH + aoff);
                ldm_x4(al[pf], cbase + A2_XL + aoff);
            }
#pragma unroll
            for (int bn = 0; bn < 2; bn++) {
                uint32_t brow = (uint32_t)(wn*32 + bn*16 + b_sub);
                uint32_t boff = brow * C2_RSTR + (uint32_t)(k0 + b_kh) * 2;
                ldm_x4(bh[bn], cbase + A2_WH + boff);
                ldm_x4(bl[bn], cbase + A2_WL + boff);
            }
#pragma unroll
            for (int pf = 0; pf < 2; pf++)
#pragma unroll
                for (int bn = 0; bn < 2; bn++)
#pragma unroll
                    for (int j = 0; j < 2; j++) {
                        mma_f16(acc[pf][bn*2+j], ah[pf], bh[bn] + j*2);
                        mma_f16(acc[pf][bn*2+j], ah[pf], bl[bn] + j*2);
                        mma_f16(acc[pf][bn*2+j], al[pf], bh[bn] + j*2);
                    }
        }
        __syncthreads();
    }

    const int prow = lane >> 2;
#pragma unroll
    for (int pf = 0; pf < 2; pf++) {
        int p0 = pq0 + pgrp*32 + pf*16 + prow;
#pragma unroll
        for (int nf = 0; nf < 4; nf++) {
            int col = oc0 + wn*32 + nf*8 + (lane & 3)*2;
            if (p0 < NROWS) {
                g_T[(size_t)p0*NT + col]     = acc[pf][nf][0];
                g_T[(size_t)p0*NT + col + 1] = acc[pf][nf][1];
            }
            if (p0 + 8 < NROWS) {
                g_T[(size_t)(p0+8)*NT + col]     = acc[pf][nf][2];
                g_T[(size_t)(p0+8)*NT + col + 1] = acc[pf][nf][3];
            }
        }
    }
}

// ---------------- zs/zo: tanh + fp16 zs (padded to 7168 rows) ----------
__global__ void k_zszo()
{
    int pq = blockIdx.x;
    int c  = threadIdx.x;
    float zs = 0.f, zo = 0.f;
    if (pq < NPAIR) {
        int b   = pq / NPIX;
        int rem = pq - b*NPIX;
        int a1  = rem / NE;
        int a2  = rem - a1*NE;
        float a = g_attn[pq*EMBD + c];
        zs = tanhf(g_S[(b*NE + a1)*EMBD + c] + a);
        zo = tanhf(g_O[(b*NE + a2)*EMBD + c] + a);
    }
    g_zs_h[pq*EMBD + c] = __float2half(zs);
    g_zo [pq*EMBD + c] = zo;
}

// ---------------- zo transpose: g_zoT[m][pq] = fp16(g_zo[pq][m]) ----------------
__global__ void __launch_bounds__(256) k_zot()
{
    __shared__ float tile[32][33];
    int pq0 = blockIdx.x * 32;
    int m0  = blockIdx.y * 32;
    int tx = threadIdx.x & 31, ty = threadIdx.x >> 5;
    for (int r = ty; r < 32; r += 8)
        tile[r][tx] = g_zo[(size_t)(pq0 + r)*EMBD + m0 + tx];
    __syncthreads();
    for (int r = ty; r < 32; r += 8)
        g_zoT[(size_t)(m0 + r)*NPAIR_PAD + pq0 + tx] = __float2half(tile[tx][r]);
}

// ======================= final bilinear via mma.sync fp16 ======================
#define FB_ZS      0
#define FB_W       131072
#define FB_WBUF    32768
#define FB_ZO      196608
#define FB_SUMS    196608             // overlays zo (used only after final sync)
#define FB_SMEM    230400

__global__ void __launch_bounds__(256) k_final_mma(const float* __restrict__ bb,
                                                   float* __restrict__ out)
{
    extern __shared__ char smem[];
    const uint32_t sb = smem_u32(smem);
    const int tid  = threadIdx.x;
    const int lane = tid & 31;
    const int w    = tid >> 5;
    const int pgrp = w >> 1;             // 0..3  (64 p each)
    const int wm   = w & 1;              // 0..1  (32 m each within 64-m chunk)
    const int pq0  = blockIdx.x * FB_TILE;
    const int o    = blockIdx.y;

    for (int i = tid; i < 256*32; i += 256) {
        int row = i >> 5, c = i & 31;
        size_t gsrc = ((size_t)(pq0 + row) * 256 + (size_t)c * 8) * 2;
        cp16(sb + FB_ZS + SWZ(row, c), (const char*)g_zs_h + gsrc);
    }
    for (int i = tid; i < 64*32; i += 256) {
        int r = i >> 5, c = i & 31;
        size_t gsrc = ((size_t)o * 65536 + (size_t)r * 256 + (size_t)c * 8) * 2;
        cp16(sb + FB_W + SWZ(r, c), (const char*)g_Wt_h + gsrc);
    }
    CP_COMMIT();

    const int a_sub = (((lane >> 3) & 1) << 3) + (lane & 7);
    const int a_ku  = (lane >> 4) & 1;
    const int b_sub = (((lane >> 4) & 1) << 3) + (lane & 7);
    const int b_ku  = (lane >> 3) & 1;

    float psum[4][2];
#pragma unroll
    for (int pf = 0; pf < 4; pf++) { psum[pf][0] = 0.f; psum[pf][1] = 0.f; }
    const __half* zo_s = (const __half*)(smem + FB_ZO);

    for (int mc = 0; mc < 4; mc++) {
        const int cur = mc & 1, nxt = cur ^ 1;
        CP_WAIT0();
        __syncthreads();

        for (int i = tid; i < 64*32; i += 256) {
            int m = i >> 5, c = i & 31;
            uint32_t off = (uint32_t)m * 528 + (uint32_t)c * 16;
            size_t gsrc = ((size_t)(mc*64 + m) * NPAIR_PAD + pq0) * 2 + (size_t)c * 16;
            cp16(sb + FB_ZO + off, (const char*)g_zoT + gsrc);
        }
        CP_COMMIT();

        if (mc < 3) {
            for (int i = tid; i < 64*32; i += 256) {
                int r = i >> 5, c = i & 31;
                size_t gsrc = ((size_t)o * 65536 +
                               (size_t)((mc + 1) * 64 + r) * 256 + (size_t)c * 8) * 2;
                cp16(sb + FB_W + nxt*FB_WBUF + SWZ(r, c), (const char*)g_Wt_h + gsrc);
            }
            CP_COMMIT();
        }

        float acc[4][4][4];
#pragma unroll
        for (int pf = 0; pf < 4; pf++)
#pragma unroll
            for (int mf = 0; mf < 4; mf++)
#pragma unroll
                for (int q = 0; q < 4; q++) acc[pf][mf][q] = 0.f;

        const uint32_t wbase = sb + FB_W + cur*FB_WBUF;
#pragma unroll 4
        for (int k0 = 0; k0 < 256; k0 += 16) {
            uint32_t av[4][4], bv[2][4];
            const int ku = k0 >> 3;
#pragma unroll
            for (int pf = 0; pf < 4; pf++) {
                int arow = pgrp*64 + pf*16 + a_sub;
                ldm_x4(av[pf], sb + FB_ZS + SWZ(arow, ku + a_ku));
            }
#pragma unroll
            for (int bn = 0; bn < 2; bn++) {
                int brow = wm*32 + bn*16 + b_sub;
                ldm_x4(bv[bn], wbase + SWZ(brow, ku + b_ku));
            }
#pragma unroll
            for (int pf = 0; pf < 4; pf++)
#pragma unroll
                for (int bn = 0; bn < 2; bn++)
#pragma unroll
                    for (int j = 0; j < 2; j++)
                        mma_f16(acc[pf][bn*2+j], av[pf], bv[bn] + j*2);
        }

        if (mc < 3) { CP_WAIT1(); } else { CP_WAIT0(); }
        __syncthreads();

        const int mbase = wm*32 + (lane & 3)*2;
        const int prow  = (lane >> 2);
#pragma unroll
        for (int pf = 0; pf < 4; pf++) {
            int pl0 = pgrp*64 + pf*16 + prow;
#pragma unroll
            for (int mf = 0; mf < 4; mf++) {
                int ml = mbase + mf*8;
                float z0 = __half2float(zo_s[ml*264 + pl0]);
                float z1 = __half2float(zo_s[(ml+1)*264 + pl0]);
                float z2 = __half2float(zo_s[ml*264 + pl0 + 8]);
                float z3 = __half2float(zo_s[(ml+1)*264 + pl0 + 8]);
                psum[pf][0] += acc[pf][mf][0]*z0 + acc[pf][mf][1]*z1;
                psum[pf][1] += acc[pf][mf][2]*z2 + acc[pf][mf][3]*z3;
            }
        }
    }

    __syncthreads();
    float* sums = (float*)(smem + FB_SUMS);
#pragma unroll
    for (int pf = 0; pf < 4; pf++)
#pragma unroll
        for (int rh = 0; rh < 2; rh++) {
            float v = psum[pf][rh];
            v += __shfl_xor_sync(0xffffffffu, v, 1);
            v += __shfl_xor_sync(0xffffffffu, v, 2);
            if ((lane & 3) == 0) {
                int p = pgrp*64 + pf*16 + rh*8 + (lane >> 2);
                sums[p*2 + wm] = v;
            }
        }
    __syncthreads();

    {
        int pq = pq0 + tid;
        if (pq < NPAIR) {
            float tot = sums[tid*2] + sums[tid*2 + 1] + __ldg(&bb[o]);
            out[(size_t)pq*NREL + o] = tot;
        }
    }
}

// ---------------- launcher ----------------
extern "C" void kernel_launch(void* const* d_in, const int* in_sizes, int n_in,
                              void* d_out, int out_size)
{
    const float* entity  = (const float*)d_in[0];
    const float* w_red   = (const float*)d_in[1];
    const float* w_sim3  = (const float*)d_in[2];
    const float* c1w     = (const float*)d_in[3];
    const float* c1b     = (const float*)d_in[4];
    const float* c2w     = (const float*)d_in[5];
    const float* c2b     = (const float*)d_in[6];
    const float* w_lin   = (const float*)d_in[7];
    const float* b_lin   = (const float*)d_in[8];
    const float* w_s     = (const float*)d_in[9];
    const float* w_o     = (const float*)d_in[10];
    const float* w_bil   = (const float*)d_in[11];
    const float* b_bil   = (const float*)d_in[12];
    float* out = (float*)d_out;

    cudaFuncSetAttribute(k_final_mma, cudaFuncAttributeMaxDynamicSharedMemorySize,
                         FB_SMEM);
    cudaFuncSetAttribute(k_c2g, cudaFuncAttributeMaxDynamicSharedMemorySize,
                         C2_SMEM);
    cudaFuncSetAttribute(k_attn_g, cudaFuncAttributeMaxDynamicSharedMemorySize,
                         A2_SMEM);
    cudaFuncSetAttribute(k_t_g, cudaFuncAttributeMaxDynamicSharedMemorySize,
                         A2_SMEM);

    k_prep<<<(EMBD*K2 + 255)/256, 256>>>(c1w, c2w, w_lin);
    k_w3split<<<dim3(64, NE), 256>>>(w_sim3);
    k_wsplit<<<dim3(64, NREL), 256>>>(w_bil);

    // e = entity @ W_reduce^T, split-K 6 (partials combined in k_norms)
    k_gemm_E<<<dim3((EMBD+63)/64, (NROWS+63)/64, 6), 256>>>(entity, w_red);
    k_norms<<<NROWS, 256>>>();

    // sim3 GEMM: T[168, 10752] = e @ W3^T (fp16 3-pass, k_c2g-clone)
    k_t_g<<<dim3(2, NT/64), 256, A2_SMEM>>>();

    k_sims<<<dim3(BATCH, NE), 256>>>();
    k_sim3b<<<NROWS, 256>>>();

    k_conv1<<<dim3(BATCH, NE), 256>>>(c1b);
    k_im2col<<<dim3(BATCH, NE, 8), 256>>>();
    k_c2g<<<dim3(56, 4), 256, C2_SMEM>>>(c2b);
    k_h2split<<<NPAIR_PAD, 256>>>();

    // attn[7168, 256] = h2 @ W_lin^T + b_lin (fp16 3-pass, k_c2g-clone)
    k_attn_g<<<dim3(56, 4), 256, A2_SMEM>>>(b_lin);

    // S/O projections, split-K 4 each (z: 0-3 S, 4-7 O), then combine
    k_gemm_SO<<<dim3(EMBD/64, (NROWS+63)/64, 8), 256>>>(w_s, w_o);
    k_socomb<<<NROWS, 256>>>();

    k_zszo<<<NPAIR_PAD, 256>>>();
    k_zot<<<dim3(NPAIR_PAD/32, EMBD/32), 256>>>();

    k_final_mma<<<dim3(NPAIR_PAD/FB_TILE, NREL), 256, FB_SMEM>>>(b_bil, out);
}